// round 1
// baseline (speedup 1.0000x reference)
#include <cuda_runtime.h>
#include <math.h>

#define NPTS 120000
#define NBLK 1875   // NPTS / 64

// Scratch (device globals: allocation-free, harness-legal)
__device__ float g_A[NPTS * 128];   // branch a activations
__device__ float g_B[NPTS * 128];   // branch b activations
__device__ float g_T[NPTS * 64];    // post-W1 features
__device__ float g_T2[NPTS * 64];   // post-conv features

// ---------------------------------------------------------------------------
// t = relu(in[P,128] @ W[128,64])
// 64 threads, 64x64 tile, 8x8 micro, K chunked by 32
// ---------------------------------------------------------------------------
__global__ __launch_bounds__(64) void k_gemm_down(
    const float* __restrict__ in, const float* __restrict__ W,
    float* __restrict__ out)
{
    __shared__ float As[32][64];   // [k][p]
    __shared__ float Ws[32][64];   // [k][n]
    const int tid = threadIdx.x;
    const int p0  = blockIdx.x * 64;
    const int tx  = tid & 7;       // output-col group
    const int ty  = tid >> 3;      // point group

    float acc[8][8];
#pragma unroll
    for (int i = 0; i < 8; i++)
#pragma unroll
        for (int j = 0; j < 8; j++) acc[i][j] = 0.f;

    for (int kc = 0; kc < 128; kc += 32) {
        const float* arow = in + (size_t)(p0 + tid) * 128 + kc;
#pragma unroll
        for (int kk = 0; kk < 32; kk += 4) {
            float4 v = *(const float4*)(arow + kk);
            As[kk + 0][tid] = v.x; As[kk + 1][tid] = v.y;
            As[kk + 2][tid] = v.z; As[kk + 3][tid] = v.w;
        }
        const float4* wsrc = (const float4*)(W + kc * 64);
        float4* wdst = (float4*)&Ws[0][0];
#pragma unroll
        for (int q = 0; q < 8; q++) wdst[tid + q * 64] = wsrc[tid + q * 64];
        __syncthreads();
#pragma unroll 8
        for (int kk = 0; kk < 32; kk++) {
            float a[8], b[8];
            *(float4*)&a[0] = *(const float4*)&As[kk][ty * 8];
            *(float4*)&a[4] = *(const float4*)&As[kk][ty * 8 + 4];
            *(float4*)&b[0] = *(const float4*)&Ws[kk][tx * 8];
            *(float4*)&b[4] = *(const float4*)&Ws[kk][tx * 8 + 4];
#pragma unroll
            for (int i = 0; i < 8; i++)
#pragma unroll
                for (int j = 0; j < 8; j++)
                    acc[i][j] = fmaf(a[i], b[j], acc[i][j]);
        }
        __syncthreads();
    }
#pragma unroll
    for (int i = 0; i < 8; i++) {
        float* orow = out + (size_t)(p0 + ty * 8 + i) * 64 + tx * 8;
        float4 o;
        o.x = fmaxf(acc[i][0], 0.f); o.y = fmaxf(acc[i][1], 0.f);
        o.z = fmaxf(acc[i][2], 0.f); o.w = fmaxf(acc[i][3], 0.f);
        *(float4*)orow = o;
        o.x = fmaxf(acc[i][4], 0.f); o.y = fmaxf(acc[i][5], 0.f);
        o.z = fmaxf(acc[i][6], 0.f); o.w = fmaxf(acc[i][7], 0.f);
        *(float4*)(orow + 4) = o;
    }
}

// ---------------------------------------------------------------------------
// t2 = relu( sum_{k=0..26} gather_k(t) @ Wk[k] )   (64 -> 64 channels)
// 64 threads, 64 points per block, 8x8 micro; gather staged transposed [c][p]
// ---------------------------------------------------------------------------
__global__ __launch_bounds__(64) void k_conv(
    const float* __restrict__ t, const float* __restrict__ Wk,
    const int* __restrict__ nbr, float* __restrict__ out)
{
    __shared__ float Gs[64][64];   // [c][p]  gathered features
    __shared__ float Ws[64][64];   // [c][j]  weights for current tap
    const int tid = threadIdx.x;
    const int p0  = blockIdx.x * 64;
    const int tx  = tid & 7;
    const int ty  = tid >> 3;

    float acc[8][8];
#pragma unroll
    for (int i = 0; i < 8; i++)
#pragma unroll
        for (int j = 0; j < 8; j++) acc[i][j] = 0.f;

    for (int k = 0; k < 27; k++) {
        // gather: each thread owns one point's neighbor row
        int row = nbr[(size_t)(p0 + tid) * 27 + k];
        if (row >= 0) {
            const float4* src = (const float4*)(t + (size_t)row * 64);
#pragma unroll
            for (int c = 0; c < 64; c += 4) {
                float4 v = src[c >> 2];
                Gs[c + 0][tid] = v.x; Gs[c + 1][tid] = v.y;
                Gs[c + 2][tid] = v.z; Gs[c + 3][tid] = v.w;
            }
        } else {
#pragma unroll
            for (int c = 0; c < 64; c++) Gs[c][tid] = 0.f;
        }
        // stage weights Wk[k]: 64x64 floats
        const float4* wsrc = (const float4*)(Wk + (size_t)k * 4096);
        float4* wdst = (float4*)&Ws[0][0];
#pragma unroll
        for (int q = 0; q < 16; q++) wdst[tid + q * 64] = wsrc[tid + q * 64];
        __syncthreads();
#pragma unroll 8
        for (int kk = 0; kk < 64; kk++) {
            float a[8], b[8];
            *(float4*)&a[0] = *(const float4*)&Gs[kk][ty * 8];
            *(float4*)&a[4] = *(const float4*)&Gs[kk][ty * 8 + 4];
            *(float4*)&b[0] = *(const float4*)&Ws[kk][tx * 8];
            *(float4*)&b[4] = *(const float4*)&Ws[kk][tx * 8 + 4];
#pragma unroll
            for (int i = 0; i < 8; i++)
#pragma unroll
                for (int j = 0; j < 8; j++)
                    acc[i][j] = fmaf(a[i], b[j], acc[i][j]);
        }
        __syncthreads();
    }
#pragma unroll
    for (int i = 0; i < 8; i++) {
        float* orow = out + (size_t)(p0 + ty * 8 + i) * 64 + tx * 8;
        float4 o;
        o.x = fmaxf(acc[i][0], 0.f); o.y = fmaxf(acc[i][1], 0.f);
        o.z = fmaxf(acc[i][2], 0.f); o.w = fmaxf(acc[i][3], 0.f);
        *(float4*)orow = o;
        o.x = fmaxf(acc[i][4], 0.f); o.y = fmaxf(acc[i][5], 0.f);
        o.z = fmaxf(acc[i][6], 0.f); o.w = fmaxf(acc[i][7], 0.f);
        *(float4*)(orow + 4) = o;
    }
}

// ---------------------------------------------------------------------------
// h = relu( t2[P,64] @ W[64,128] + hprev )
// 128 threads, 64x128 tile, 8x8 micro, whole K=64 staged once
// ---------------------------------------------------------------------------
__global__ __launch_bounds__(128) void k_gemm_up(
    const float* __restrict__ t2, const float* __restrict__ W,
    const float* __restrict__ hprev, float* __restrict__ hout)
{
    __shared__ float As[64][64];    // [k][p]
    __shared__ float Ws[64][128];   // [k][n]
    const int tid = threadIdx.x;
    const int p0  = blockIdx.x * 64;
    const int tx  = tid & 15;      // 16 col groups
    const int ty  = tid >> 4;      // 8 point groups

    float acc[8][8];
#pragma unroll
    for (int i = 0; i < 8; i++)
#pragma unroll
        for (int j = 0; j < 8; j++) acc[i][j] = 0.f;

    {
        int p = tid & 63, kh = tid >> 6;   // two threads per point, 32 k each
        const float* arow = t2 + (size_t)(p0 + p) * 64 + kh * 32;
#pragma unroll
        for (int kk = 0; kk < 32; kk += 4) {
            float4 v = *(const float4*)(arow + kk);
            As[kh * 32 + kk + 0][p] = v.x; As[kh * 32 + kk + 1][p] = v.y;
            As[kh * 32 + kk + 2][p] = v.z; As[kh * 32 + kk + 3][p] = v.w;
        }
        const float4* wsrc = (const float4*)W;
        float4* wdst = (float4*)&Ws[0][0];
#pragma unroll
        for (int q = 0; q < 16; q++) wdst[tid + q * 128] = wsrc[tid + q * 128];
    }
    __syncthreads();
#pragma unroll 8
    for (int kk = 0; kk < 64; kk++) {
        float a[8], b[8];
        *(float4*)&a[0] = *(const float4*)&As[kk][ty * 8];
        *(float4*)&a[4] = *(const float4*)&As[kk][ty * 8 + 4];
        *(float4*)&b[0] = *(const float4*)&Ws[kk][tx * 8];
        *(float4*)&b[4] = *(const float4*)&Ws[kk][tx * 8 + 4];
#pragma unroll
        for (int i = 0; i < 8; i++)
#pragma unroll
            for (int j = 0; j < 8; j++)
                acc[i][j] = fmaf(a[i], b[j], acc[i][j]);
    }
#pragma unroll
    for (int i = 0; i < 8; i++) {
        size_t base = (size_t)(p0 + ty * 8 + i) * 128 + tx * 8;
        float4 h0 = *(const float4*)(hprev + base);
        float4 h1 = *(const float4*)(hprev + base + 4);
        float4 o;
        o.x = fmaxf(acc[i][0] + h0.x, 0.f); o.y = fmaxf(acc[i][1] + h0.y, 0.f);
        o.z = fmaxf(acc[i][2] + h0.z, 0.f); o.w = fmaxf(acc[i][3] + h0.w, 0.f);
        *(float4*)(hout + base) = o;
        o.x = fmaxf(acc[i][4] + h1.x, 0.f); o.y = fmaxf(acc[i][5] + h1.y, 0.f);
        o.z = fmaxf(acc[i][6] + h1.z, 0.f); o.w = fmaxf(acc[i][7] + h1.w, 0.f);
        *(float4*)(hout + base + 4) = o;
    }
}

// ---------------------------------------------------------------------------
// out = a * sigmoid( b[P,128] @ Wf[128,128] ) + x
// 128 threads, 64x128 tile, 8x8 micro, K chunked by 64
// ---------------------------------------------------------------------------
__global__ __launch_bounds__(128) void k_final(
    const float* __restrict__ bin, const float* __restrict__ Wf,
    const float* __restrict__ a, const float* __restrict__ x,
    float* __restrict__ out)
{
    __shared__ float As[64][64];
    __shared__ float Ws[64][128];
    const int tid = threadIdx.x;
    const int p0  = blockIdx.x * 64;
    const int tx  = tid & 15;
    const int ty  = tid >> 4;

    float acc[8][8];
#pragma unroll
    for (int i = 0; i < 8; i++)
#pragma unroll
        for (int j = 0; j < 8; j++) acc[i][j] = 0.f;

    for (int kc = 0; kc < 128; kc += 64) {
        int p = tid & 63, kh = tid >> 6;
        const float* arow = bin + (size_t)(p0 + p) * 128 + kc + kh * 32;
#pragma unroll
        for (int kk = 0; kk < 32; kk += 4) {
            float4 v = *(const float4*)(arow + kk);
            As[kh * 32 + kk + 0][p] = v.x; As[kh * 32 + kk + 1][p] = v.y;
            As[kh * 32 + kk + 2][p] = v.z; As[kh * 32 + kk + 3][p] = v.w;
        }
        const float4* wsrc = (const float4*)(Wf + kc * 128);
        float4* wdst = (float4*)&Ws[0][0];
#pragma unroll
        for (int q = 0; q < 16; q++) wdst[tid + q * 128] = wsrc[tid + q * 128];
        __syncthreads();
#pragma unroll 8
        for (int kk = 0; kk < 64; kk++) {
            float av[8], bv[8];
            *(float4*)&av[0] = *(const float4*)&As[kk][ty * 8];
            *(float4*)&av[4] = *(const float4*)&As[kk][ty * 8 + 4];
            *(float4*)&bv[0] = *(const float4*)&Ws[kk][tx * 8];
            *(float4*)&bv[4] = *(const float4*)&Ws[kk][tx * 8 + 4];
#pragma unroll
            for (int i = 0; i < 8; i++)
#pragma unroll
                for (int j = 0; j < 8; j++)
                    acc[i][j] = fmaf(av[i], bv[j], acc[i][j]);
        }
        __syncthreads();
    }
#pragma unroll
    for (int i = 0; i < 8; i++) {
        size_t base = (size_t)(p0 + ty * 8 + i) * 128 + tx * 8;
        float4 a0 = *(const float4*)(a + base);
        float4 a1 = *(const float4*)(a + base + 4);
        float4 x0 = *(const float4*)(x + base);
        float4 x1 = *(const float4*)(x + base + 4);
        float4 o;
        o.x = a0.x / (1.f + __expf(-acc[i][0])) + x0.x;
        o.y = a0.y / (1.f + __expf(-acc[i][1])) + x0.y;
        o.z = a0.z / (1.f + __expf(-acc[i][2])) + x0.z;
        o.w = a0.w / (1.f + __expf(-acc[i][3])) + x0.w;
        *(float4*)(out + base) = o;
        o.x = a1.x / (1.f + __expf(-acc[i][4])) + x1.x;
        o.y = a1.y / (1.f + __expf(-acc[i][5])) + x1.y;
        o.z = a1.z / (1.f + __expf(-acc[i][6])) + x1.z;
        o.w = a1.w / (1.f + __expf(-acc[i][7])) + x1.w;
        *(float4*)(out + base + 4) = o;
    }
}

// ---------------------------------------------------------------------------
extern "C" void kernel_launch(void* const* d_in, const int* in_sizes, int n_in,
                              void* d_out, int out_size)
{
    const float* x   = (const float*)d_in[0];
    const float* W1s = (const float*)d_in[1];
    const float* Wks = (const float*)d_in[2];
    const float* W2s = (const float*)d_in[3];
    const float* Wf  = (const float*)d_in[4];
    const int*   nbr = (const int*)d_in[5];
    float* out = (float*)d_out;

    float *A, *B, *T, *T2;
    cudaGetSymbolAddress((void**)&A,  g_A);
    cudaGetSymbolAddress((void**)&B,  g_B);
    cudaGetSymbolAddress((void**)&T,  g_T);
    cudaGetSymbolAddress((void**)&T2, g_T2);

    // branch a: units 0..2
    for (int i = 0; i < 3; i++) {
        const float* hin = (i == 0) ? x : A;
        k_gemm_down<<<NBLK, 64>>>(hin, W1s + (size_t)i * 128 * 64, T);
        k_conv<<<NBLK, 64>>>(T, Wks + (size_t)i * 27 * 64 * 64, nbr, T2);
        k_gemm_up<<<NBLK, 128>>>(T2, W2s + (size_t)i * 64 * 128, hin, A);
    }
    // branch b: units 3..5
    for (int i = 3; i < 6; i++) {
        const float* hin = (i == 3) ? x : B;
        k_gemm_down<<<NBLK, 64>>>(hin, W1s + (size_t)i * 128 * 64, T);
        k_conv<<<NBLK, 64>>>(T, Wks + (size_t)i * 27 * 64 * 64, nbr, T2);
        k_gemm_up<<<NBLK, 128>>>(T2, W2s + (size_t)i * 64 * 128, hin, B);
    }
    k_final<<<NBLK, 128>>>(B, Wf, A, x, out);
}

// round 3
// speedup vs baseline: 1.7367x; 1.7367x over previous
#include <cuda_runtime.h>
#include <cuda_bf16.h>
#include <cstdint>

#define NPTS 120000
#define NBLK64 1875
#define NBLK128 938   // ceil(120000/128)

// ---------------- scratch (device globals: allocation-free) ----------------
__device__ float g_A[NPTS * 128];
__device__ float g_B[NPTS * 128];
__device__ float g_T2[NPTS * 64];
__device__ __nv_bfloat16 g_Thi[NPTS * 64];
__device__ __nv_bfloat16 g_Tlo[NPTS * 64];
__device__ __nv_bfloat16 g_WtH[6 * 27 * 64 * 64];   // [u][k][j][c]
__device__ __nv_bfloat16 g_WtL[6 * 27 * 64 * 64];

// ---------------- helpers ---------------------------------------------------
__device__ __forceinline__ uint32_t smem_u32(const void* p) {
    uint32_t a;
    asm("{ .reg .u64 t; cvta.to.shared.u64 t, %1; cvt.u32.u64 %0, t; }"
        : "=r"(a) : "l"(p));
    return a;
}

__device__ __forceinline__ void ldsm_x4(uint32_t (&r)[4], uint32_t addr) {
    asm volatile("ldmatrix.sync.aligned.m8n8.x4.shared.b16 {%0,%1,%2,%3}, [%4];"
                 : "=r"(r[0]), "=r"(r[1]), "=r"(r[2]), "=r"(r[3]) : "r"(addr));
}
__device__ __forceinline__ void ldsm_x2(uint32_t (&r)[2], uint32_t addr) {
    asm volatile("ldmatrix.sync.aligned.m8n8.x2.shared.b16 {%0,%1}, [%2];"
                 : "=r"(r[0]), "=r"(r[1]) : "r"(addr));
}
__device__ __forceinline__ void mma16816(float* c, const uint32_t* a,
                                         const uint32_t* b) {
    asm volatile(
        "mma.sync.aligned.m16n8k16.row.col.f32.bf16.bf16.f32 "
        "{%0,%1,%2,%3}, {%4,%5,%6,%7}, {%8,%9}, {%0,%1,%2,%3};"
        : "+f"(c[0]), "+f"(c[1]), "+f"(c[2]), "+f"(c[3])
        : "r"(a[0]), "r"(a[1]), "r"(a[2]), "r"(a[3]), "r"(b[0]), "r"(b[1]));
}

__device__ __forceinline__ unsigned pack_bf2(__nv_bfloat16 a, __nv_bfloat16 b) {
    __nv_bfloat162 t; t.x = a; t.y = b;
    return *reinterpret_cast<unsigned*>(&t);
}

// ---------------------------------------------------------------------------
// weight split+transpose: Wt[u][k][j][c] = Wk[u][k][c][j] as bf16 hi/lo
// ---------------------------------------------------------------------------
__global__ void k_wsplit(const float* __restrict__ Wks,
                         __nv_bfloat16* __restrict__ WtH,
                         __nv_bfloat16* __restrict__ WtL) {
    int k = blockIdx.x, u = blockIdx.y;
    const float* src = Wks + ((size_t)u * 27 + k) * 4096;
    __nv_bfloat16* dh = WtH + ((size_t)u * 27 + k) * 4096;
    __nv_bfloat16* dl = WtL + ((size_t)u * 27 + k) * 4096;
    for (int e = threadIdx.x; e < 4096; e += blockDim.x) {
        int c = e >> 6, j = e & 63;
        float v = src[c * 64 + j];
        __nv_bfloat16 h = __float2bfloat16(v);
        float r = v - __bfloat162float(h);
        dh[j * 64 + c] = h;
        dl[j * 64 + c] = __float2bfloat16(r);
    }
}

// ---------------------------------------------------------------------------
// t = relu(in[P,128] @ W[128,64])  -> bf16 hi/lo planar outputs
// ---------------------------------------------------------------------------
__global__ __launch_bounds__(64) void k_gemm_down(
    const float* __restrict__ in, const float* __restrict__ W,
    __nv_bfloat16* __restrict__ Thi, __nv_bfloat16* __restrict__ Tlo)
{
    __shared__ float As[32][64];
    __shared__ float Ws[32][64];
    const int tid = threadIdx.x;
    const int p0  = blockIdx.x * 64;
    const int tx  = tid & 7;
    const int ty  = tid >> 3;

    float acc[8][8];
#pragma unroll
    for (int i = 0; i < 8; i++)
#pragma unroll
        for (int j = 0; j < 8; j++) acc[i][j] = 0.f;

    for (int kc = 0; kc < 128; kc += 32) {
        const float* arow = in + (size_t)(p0 + tid) * 128 + kc;
#pragma unroll
        for (int kk = 0; kk < 32; kk += 4) {
            float4 v = *(const float4*)(arow + kk);
            As[kk + 0][tid] = v.x; As[kk + 1][tid] = v.y;
            As[kk + 2][tid] = v.z; As[kk + 3][tid] = v.w;
        }
        const float4* wsrc = (const float4*)(W + kc * 64);
        float4* wdst = (float4*)&Ws[0][0];
#pragma unroll
        for (int q = 0; q < 8; q++) wdst[tid + q * 64] = wsrc[tid + q * 64];
        __syncthreads();
#pragma unroll 8
        for (int kk = 0; kk < 32; kk++) {
            float a[8], b[8];
            *(float4*)&a[0] = *(const float4*)&As[kk][ty * 8];
            *(float4*)&a[4] = *(const float4*)&As[kk][ty * 8 + 4];
            *(float4*)&b[0] = *(const float4*)&Ws[kk][tx * 8];
            *(float4*)&b[4] = *(const float4*)&Ws[kk][tx * 8 + 4];
#pragma unroll
            for (int i = 0; i < 8; i++)
#pragma unroll
                for (int j = 0; j < 8; j++)
                    acc[i][j] = fmaf(a[i], b[j], acc[i][j]);
        }
        __syncthreads();
    }
#pragma unroll
    for (int i = 0; i < 8; i++) {
        size_t base = (size_t)(p0 + ty * 8 + i) * 64 + tx * 8;
        unsigned hh[4], ll[4];
#pragma unroll
        for (int jj = 0; jj < 4; jj++) {
            float v0 = fmaxf(acc[i][jj * 2 + 0], 0.f);
            float v1 = fmaxf(acc[i][jj * 2 + 1], 0.f);
            __nv_bfloat16 h0 = __float2bfloat16(v0);
            __nv_bfloat16 h1 = __float2bfloat16(v1);
            float r0 = v0 - __bfloat162float(h0);
            float r1 = v1 - __bfloat162float(h1);
            hh[jj] = pack_bf2(h0, h1);
            ll[jj] = pack_bf2(__float2bfloat16(r0), __float2bfloat16(r1));
        }
        *(uint4*)(Thi + base) = make_uint4(hh[0], hh[1], hh[2], hh[3]);
        *(uint4*)(Tlo + base) = make_uint4(ll[0], ll[1], ll[2], ll[3]);
    }
}

// ---------------------------------------------------------------------------
// HMMA conv: out[p,j] = relu( sum_k sum_c gather_k(T)[p,c] * Wk[k][c][j] )
// CTA: 128 pts x 64 out-ch, 8 warps (4 M-bands x 2 N-bands, 32x32 warp tile)
// bf16 hi/lo split: acc += Ah*Bh + Ah*Bl + Al*Bh  (fp32 accumulators)
// smem (dynamic), row stride 144B (72 bf16) for conflict-free ldmatrix:
//   Ahi @ 0      (128*144 = 18432)
//   Alo @ 18432
//   Bhi @ 36864  (64*144 = 9216)
//   Blo @ 46080
//   idx @ 55296  (27*128*4 = 13824)   total 69120
// ---------------------------------------------------------------------------
#define CONV_SMEM 69120
#define ASTRIDE 144
#define A_LO 18432
#define B_HI 36864
#define B_LO 46080
#define IDX_OFF 55296

__global__ __launch_bounds__(256, 2) void k_conv_mma(
    const __nv_bfloat16* __restrict__ Thi, const __nv_bfloat16* __restrict__ Tlo,
    const __nv_bfloat16* __restrict__ WtH, const __nv_bfloat16* __restrict__ WtL,
    const int* __restrict__ nbr, float* __restrict__ out)
{
    extern __shared__ char sm[];
    const int tid  = threadIdx.x;
    const int lane = tid & 31;
    const int w    = tid >> 5;
    const int wm   = w & 3;        // M band: rows wm*32..+31
    const int wn   = w >> 2;       // N band: cols wn*32..+31
    const int p0   = blockIdx.x * 128;

    const uint32_t su = smem_u32(sm);
    int* idxs = (int*)(sm + IDX_OFF);

    // preload neighbor indices
    for (int i = tid; i < 27 * 128; i += 256) {
        int p = i / 27;
        int k = i - p * 27;
        int gp = p0 + p;
        idxs[k * 128 + p] = (gp < NPTS) ? nbr[(size_t)gp * 27 + k] : -1;
    }

    float acc[2][4][4];
#pragma unroll
    for (int mt = 0; mt < 2; mt++)
#pragma unroll
        for (int nt = 0; nt < 4; nt++)
#pragma unroll
            for (int e = 0; e < 4; e++) acc[mt][nt][e] = 0.f;

    // per-thread staging offsets
    const int pr   = tid >> 1;          // A row 0..127
    const int ahalf = tid & 1;          // 32-bf16 half
    const uint32_t a_dst = (uint32_t)pr * ASTRIDE + (uint32_t)ahalf * 64;
    const int bplane = tid >> 7;        // 0=hi, 1=lo
    const int brow   = (tid & 127) >> 1;
    const uint32_t b_dst = (uint32_t)(B_HI + bplane * 9216)
                         + (uint32_t)brow * ASTRIDE + (uint32_t)ahalf * 64;

    // ldmatrix lane addresses (byte offsets within smem)
    const uint32_t a_ld = su + (uint32_t)(wm * 32 + (lane & 15)) * ASTRIDE
                        + (uint32_t)(lane >> 4) * 16;
    const uint32_t b_ld = su + B_HI + (uint32_t)(wn * 32 + (lane & 7)) * ASTRIDE
                        + (uint32_t)((lane & 15) >> 3) * 16;

    for (int k = 0; k < 27; k++) {
        __syncthreads();   // protect previous tap's tiles until mma done
        // ---- A gather (hi+lo) ----
        {
            int row = idxs[k * 128 + pr];
            char* Ah = sm + a_dst;
            char* Al = sm + A_LO + a_dst;
            if (row >= 0) {
                const uint4* sh = (const uint4*)(Thi + (size_t)row * 64 + ahalf * 32);
                const uint4* sl = (const uint4*)(Tlo + (size_t)row * 64 + ahalf * 32);
#pragma unroll
                for (int i = 0; i < 4; i++) {
                    *(uint4*)(Ah + i * 16) = sh[i];
                    *(uint4*)(Al + i * 16) = sl[i];
                }
            } else {
                uint4 z = make_uint4(0, 0, 0, 0);
#pragma unroll
                for (int i = 0; i < 4; i++) {
                    *(uint4*)(Ah + i * 16) = z;
                    *(uint4*)(Al + i * 16) = z;
                }
            }
        }
        // ---- B stage (this tap's 64x64 hi/lo weights) ----
        {
            const uint4* ws = (const uint4*)((bplane ? WtL : WtH)
                              + ((size_t)k * 64 + brow) * 64 + ahalf * 32);
            char* Bd = sm + b_dst;
#pragma unroll
            for (int i = 0; i < 4; i++) *(uint4*)(Bd + i * 16) = ws[i];
        }
        __syncthreads();

        // ---- MMA over K=64 (4 ksteps of 16) ----
#pragma unroll
        for (int ks = 0; ks < 4; ks++) {
            uint32_t ah[2][4], al[2][4];
#pragma unroll
            for (int mt = 0; mt < 2; mt++) {
                ldsm_x4(ah[mt], a_ld + (uint32_t)mt * (16 * ASTRIDE) + ks * 32);
                ldsm_x4(al[mt], a_ld + A_LO + (uint32_t)mt * (16 * ASTRIDE) + ks * 32);
            }
#pragma unroll
            for (int nt = 0; nt < 4; nt++) {
                uint32_t bh[2], bl[2];
                ldsm_x2(bh, b_ld + (uint32_t)nt * (8 * ASTRIDE) + ks * 32);
                ldsm_x2(bl, b_ld + 9216 + (uint32_t)nt * (8 * ASTRIDE) + ks * 32);
#pragma unroll
                for (int mt = 0; mt < 2; mt++) {
                    mma16816(acc[mt][nt], ah[mt], bh);
                    mma16816(acc[mt][nt], ah[mt], bl);
                    mma16816(acc[mt][nt], al[mt], bh);
                }
            }
        }
    }

    // ---- epilogue: relu + fp32 store ----
    const int g = lane >> 2, tg = lane & 3;
#pragma unroll
    for (int mt = 0; mt < 2; mt++) {
        int row0 = p0 + wm * 32 + mt * 16 + g;
#pragma unroll
        for (int nt = 0; nt < 4; nt++) {
            int col = wn * 32 + nt * 8 + tg * 2;
            if (row0 < NPTS) {
                float2 o;
                o.x = fmaxf(acc[mt][nt][0], 0.f);
                o.y = fmaxf(acc[mt][nt][1], 0.f);
                *(float2*)(out + (size_t)row0 * 64 + col) = o;
            }
            if (row0 + 8 < NPTS) {
                float2 o;
                o.x = fmaxf(acc[mt][nt][2], 0.f);
                o.y = fmaxf(acc[mt][nt][3], 0.f);
                *(float2*)(out + (size_t)(row0 + 8) * 64 + col) = o;
            }
        }
    }
}

// ---------------------------------------------------------------------------
// h = relu( t2[P,64] @ W[64,128] + hprev )
// ---------------------------------------------------------------------------
__global__ __launch_bounds__(128) void k_gemm_up(
    const float* __restrict__ t2, const float* __restrict__ W,
    const float* __restrict__ hprev, float* __restrict__ hout)
{
    __shared__ float As[64][64];
    __shared__ float Ws[64][128];
    const int tid = threadIdx.x;
    const int p0  = blockIdx.x * 64;
    const int tx  = tid & 15;
    const int ty  = tid >> 4;

    float acc[8][8];
#pragma unroll
    for (int i = 0; i < 8; i++)
#pragma unroll
        for (int j = 0; j < 8; j++) acc[i][j] = 0.f;

    {
        int p = tid & 63, kh = tid >> 6;
        const float* arow = t2 + (size_t)(p0 + p) * 64 + kh * 32;
#pragma unroll
        for (int kk = 0; kk < 32; kk += 4) {
            float4 v = *(const float4*)(arow + kk);
            As[kh * 32 + kk + 0][p] = v.x; As[kh * 32 + kk + 1][p] = v.y;
            As[kh * 32 + kk + 2][p] = v.z; As[kh * 32 + kk + 3][p] = v.w;
        }
        const float4* wsrc = (const float4*)W;
        float4* wdst = (float4*)&Ws[0][0];
#pragma unroll
        for (int q = 0; q < 16; q++) wdst[tid + q * 128] = wsrc[tid + q * 128];
    }
    __syncthreads();
#pragma unroll 8
    for (int kk = 0; kk < 64; kk++) {
        float a[8], b[8];
        *(float4*)&a[0] = *(const float4*)&As[kk][ty * 8];
        *(float4*)&a[4] = *(const float4*)&As[kk][ty * 8 + 4];
        *(float4*)&b[0] = *(const float4*)&Ws[kk][tx * 8];
        *(float4*)&b[4] = *(const float4*)&Ws[kk][tx * 8 + 4];
#pragma unroll
        for (int i = 0; i < 8; i++)
#pragma unroll
            for (int j = 0; j < 8; j++)
                acc[i][j] = fmaf(a[i], b[j], acc[i][j]);
    }
#pragma unroll
    for (int i = 0; i < 8; i++) {
        size_t base = (size_t)(p0 + ty * 8 + i) * 128 + tx * 8;
        float4 h0 = *(const float4*)(hprev + base);
        float4 h1 = *(const float4*)(hprev + base + 4);
        float4 o;
        o.x = fmaxf(acc[i][0] + h0.x, 0.f); o.y = fmaxf(acc[i][1] + h0.y, 0.f);
        o.z = fmaxf(acc[i][2] + h0.z, 0.f); o.w = fmaxf(acc[i][3] + h0.w, 0.f);
        *(float4*)(hout + base) = o;
        o.x = fmaxf(acc[i][4] + h1.x, 0.f); o.y = fmaxf(acc[i][5] + h1.y, 0.f);
        o.z = fmaxf(acc[i][6] + h1.z, 0.f); o.w = fmaxf(acc[i][7] + h1.w, 0.f);
        *(float4*)(hout + base + 4) = o;
    }
}

// ---------------------------------------------------------------------------
// out = a * sigmoid( b[P,128] @ Wf[128,128] ) + x
// ---------------------------------------------------------------------------
__global__ __launch_bounds__(128) void k_final(
    const float* __restrict__ bin, const float* __restrict__ Wf,
    const float* __restrict__ a, const float* __restrict__ x,
    float* __restrict__ out)
{
    __shared__ float As[64][64];
    __shared__ float Ws[64][128];
    const int tid = threadIdx.x;
    const int p0  = blockIdx.x * 64;
    const int tx  = tid & 15;
    const int ty  = tid >> 4;

    float acc[8][8];
#pragma unroll
    for (int i = 0; i < 8; i++)
#pragma unroll
        for (int j = 0; j < 8; j++) acc[i][j] = 0.f;

    for (int kc = 0; kc < 128; kc += 64) {
        int p = tid & 63, kh = tid >> 6;
        const float* arow = bin + (size_t)(p0 + p) * 128 + kc + kh * 32;
#pragma unroll
        for (int kk = 0; kk < 32; kk += 4) {
            float4 v = *(const float4*)(arow + kk);
            As[kh * 32 + kk + 0][p] = v.x; As[kh * 32 + kk + 1][p] = v.y;
            As[kh * 32 + kk + 2][p] = v.z; As[kh * 32 + kk + 3][p] = v.w;
        }
        const float4* wsrc = (const float4*)(Wf + kc * 128);
        float4* wdst = (float4*)&Ws[0][0];
#pragma unroll
        for (int q = 0; q < 16; q++) wdst[tid + q * 128] = wsrc[tid + q * 128];
        __syncthreads();
#pragma unroll 8
        for (int kk = 0; kk < 64; kk++) {
            float av[8], bv[8];
            *(float4*)&av[0] = *(const float4*)&As[kk][ty * 8];
            *(float4*)&av[4] = *(const float4*)&As[kk][ty * 8 + 4];
            *(float4*)&bv[0] = *(const float4*)&Ws[kk][tx * 8];
            *(float4*)&bv[4] = *(const float4*)&Ws[kk][tx * 8 + 4];
#pragma unroll
            for (int i = 0; i < 8; i++)
#pragma unroll
                for (int j = 0; j < 8; j++)
                    acc[i][j] = fmaf(av[i], bv[j], acc[i][j]);
        }
        __syncthreads();
    }
#pragma unroll
    for (int i = 0; i < 8; i++) {
        size_t base = (size_t)(p0 + ty * 8 + i) * 128 + tx * 8;
        float4 a0 = *(const float4*)(a + base);
        float4 a1 = *(const float4*)(a + base + 4);
        float4 x0 = *(const float4*)(x + base);
        float4 x1 = *(const float4*)(x + base + 4);
        float4 o;
        o.x = a0.x / (1.f + __expf(-acc[i][0])) + x0.x;
        o.y = a0.y / (1.f + __expf(-acc[i][1])) + x0.y;
        o.z = a0.z / (1.f + __expf(-acc[i][2])) + x0.z;
        o.w = a0.w / (1.f + __expf(-acc[i][3])) + x0.w;
        *(float4*)(out + base) = o;
        o.x = a1.x / (1.f + __expf(-acc[i][4])) + x1.x;
        o.y = a1.y / (1.f + __expf(-acc[i][5])) + x1.y;
        o.z = a1.z / (1.f + __expf(-acc[i][6])) + x1.z;
        o.w = a1.w / (1.f + __expf(-acc[i][7])) + x1.w;
        *(float4*)(out + base + 4) = o;
    }
}

// ---------------------------------------------------------------------------
extern "C" void kernel_launch(void* const* d_in, const int* in_sizes, int n_in,
                              void* d_out, int out_size)
{
    const float* x   = (const float*)d_in[0];
    const float* W1s = (const float*)d_in[1];
    const float* Wks = (const float*)d_in[2];
    const float* W2s = (const float*)d_in[3];
    const float* Wf  = (const float*)d_in[4];
    const int*   nbr = (const int*)d_in[5];
    float* out = (float*)d_out;

    float *A, *B, *T2;
    __nv_bfloat16 *Thi, *Tlo, *WtH, *WtL;
    cudaGetSymbolAddress((void**)&A,   g_A);
    cudaGetSymbolAddress((void**)&B,   g_B);
    cudaGetSymbolAddress((void**)&T2,  g_T2);
    cudaGetSymbolAddress((void**)&Thi, g_Thi);
    cudaGetSymbolAddress((void**)&Tlo, g_Tlo);
    cudaGetSymbolAddress((void**)&WtH, g_WtH);
    cudaGetSymbolAddress((void**)&WtL, g_WtL);

    cudaFuncSetAttribute(k_conv_mma, cudaFuncAttributeMaxDynamicSharedMemorySize,
                         CONV_SMEM);

    // split+transpose all 6 units' conv weights to bf16 hi/lo
    k_wsplit<<<dim3(27, 6), 256>>>(Wks, WtH, WtL);

    // branch a: units 0..2
    for (int i = 0; i < 3; i++) {
        const float* hin = (i == 0) ? x : A;
        k_gemm_down<<<NBLK64, 64>>>(hin, W1s + (size_t)i * 128 * 64, Thi, Tlo);
        k_conv_mma<<<NBLK128, 256, CONV_SMEM>>>(
            Thi, Tlo, WtH + (size_t)i * 27 * 4096, WtL + (size_t)i * 27 * 4096,
            nbr, T2);
        k_gemm_up<<<NBLK64, 128>>>(T2, W2s + (size_t)i * 64 * 128, hin, A);
    }
    // branch b: units 3..5
    for (int i = 3; i < 6; i++) {
        const float* hin = (i == 3) ? x : B;
        k_gemm_down<<<NBLK64, 64>>>(hin, W1s + (size_t)i * 128 * 64, Thi, Tlo);
        k_conv_mma<<<NBLK128, 256, CONV_SMEM>>>(
            Thi, Tlo, WtH + (size_t)i * 27 * 4096, WtL + (size_t)i * 27 * 4096,
            nbr, T2);
        k_gemm_up<<<NBLK64, 128>>>(T2, W2s + (size_t)i * 64 * 128, hin, B);
    }
    k_final<<<NBLK64, 128>>>(B, Wf, A, x, out);
}

// round 4
// speedup vs baseline: 1.9579x; 1.1274x over previous
#include <cuda_runtime.h>
#include <cuda_bf16.h>
#include <cstdint>

#define NPTS 120000
#define NBLK128 938   // ceil(120000/128)

// ---------------- scratch (device globals: allocation-free) ----------------
__device__ float g_A[NPTS * 128];
__device__ float g_B[NPTS * 128];
__device__ float g_T2[NPTS * 64];
__device__ __nv_bfloat16 g_Thi[NPTS * 64];
__device__ __nv_bfloat16 g_Tlo[NPTS * 64];
__device__ __nv_bfloat16 g_WtH[6 * 27 * 64 * 64];   // conv weights [u][k][j][c]
__device__ __nv_bfloat16 g_WtL[6 * 27 * 64 * 64];
__device__ __nv_bfloat16 g_W1H[6 * 64 * 128];       // down weights [u][n][k]
__device__ __nv_bfloat16 g_W1L[6 * 64 * 128];
__device__ __nv_bfloat16 g_W2H[6 * 128 * 64];       // up weights [u][n][k]
__device__ __nv_bfloat16 g_W2L[6 * 128 * 64];
__device__ __nv_bfloat16 g_WfH[128 * 128];          // final weights [n][k]
__device__ __nv_bfloat16 g_WfL[128 * 128];

// ---------------- helpers ---------------------------------------------------
__device__ __forceinline__ uint32_t smem_u32(const void* p) {
    uint32_t a;
    asm("{ .reg .u64 t; cvta.to.shared.u64 t, %1; cvt.u32.u64 %0, t; }"
        : "=r"(a) : "l"(p));
    return a;
}
__device__ __forceinline__ void ldsm_x4(uint32_t (&r)[4], uint32_t addr) {
    asm volatile("ldmatrix.sync.aligned.m8n8.x4.shared.b16 {%0,%1,%2,%3}, [%4];"
                 : "=r"(r[0]), "=r"(r[1]), "=r"(r[2]), "=r"(r[3]) : "r"(addr));
}
__device__ __forceinline__ void ldsm_x2(uint32_t (&r)[2], uint32_t addr) {
    asm volatile("ldmatrix.sync.aligned.m8n8.x2.shared.b16 {%0,%1}, [%2];"
                 : "=r"(r[0]), "=r"(r[1]) : "r"(addr));
}
__device__ __forceinline__ void mma16816(float* c, const uint32_t* a,
                                         const uint32_t* b) {
    asm volatile(
        "mma.sync.aligned.m16n8k16.row.col.f32.bf16.bf16.f32 "
        "{%0,%1,%2,%3}, {%4,%5,%6,%7}, {%8,%9}, {%0,%1,%2,%3};"
        : "+f"(c[0]), "+f"(c[1]), "+f"(c[2]), "+f"(c[3])
        : "r"(a[0]), "r"(a[1]), "r"(a[2]), "r"(a[3]), "r"(b[0]), "r"(b[1]));
}
__device__ __forceinline__ unsigned pack_bf2(__nv_bfloat16 a, __nv_bfloat16 b) {
    __nv_bfloat162 t; t.x = a; t.y = b;
    return *reinterpret_cast<unsigned*>(&t);
}
// split one fp32 pair into hi/lo bf16x2 words
__device__ __forceinline__ void split2(float x, float y, unsigned& h, unsigned& l) {
    __nv_bfloat16 hx = __float2bfloat16(x);
    __nv_bfloat16 hy = __float2bfloat16(y);
    float rx = x - __bfloat162float(hx);
    float ry = y - __bfloat162float(hy);
    h = pack_bf2(hx, hy);
    l = pack_bf2(__float2bfloat16(rx), __float2bfloat16(ry));
}

// ---------------------------------------------------------------------------
// conv weight split+transpose: Wt[u][k][j][c] = Wk[u][k][c][j] as bf16 hi/lo
// ---------------------------------------------------------------------------
__global__ void k_wsplit(const float* __restrict__ Wks,
                         __nv_bfloat16* __restrict__ WtH,
                         __nv_bfloat16* __restrict__ WtL) {
    int k = blockIdx.x, u = blockIdx.y;
    const float* src = Wks + ((size_t)u * 27 + k) * 4096;
    __nv_bfloat16* dh = WtH + ((size_t)u * 27 + k) * 4096;
    __nv_bfloat16* dl = WtL + ((size_t)u * 27 + k) * 4096;
    for (int e = threadIdx.x; e < 4096; e += blockDim.x) {
        int c = e >> 6, j = e & 63;
        float v = src[c * 64 + j];
        __nv_bfloat16 h = __float2bfloat16(v);
        float r = v - __bfloat162float(h);
        dh[j * 64 + c] = h;
        dl[j * 64 + c] = __float2bfloat16(r);
    }
}

// ---------------------------------------------------------------------------
// linear weight split+transpose: [k][n] fp32 -> [n][k] bf16 hi/lo
// blocks: 0-5 = W1s units, 6-11 = W2s units, 12 = Wf
// ---------------------------------------------------------------------------
__global__ void k_wsplit_lin(const float* __restrict__ W1s,
                             const float* __restrict__ W2s,
                             const float* __restrict__ Wf,
                             __nv_bfloat16* __restrict__ W1H, __nv_bfloat16* __restrict__ W1L,
                             __nv_bfloat16* __restrict__ W2H, __nv_bfloat16* __restrict__ W2L,
                             __nv_bfloat16* __restrict__ WfH, __nv_bfloat16* __restrict__ WfL) {
    int b = blockIdx.x;
    if (b < 6) {   // W1s[b]: [128][64] -> [64][128]
        const float* s = W1s + (size_t)b * 8192;
        __nv_bfloat16* dh = W1H + (size_t)b * 8192;
        __nv_bfloat16* dl = W1L + (size_t)b * 8192;
        for (int e = threadIdx.x; e < 8192; e += blockDim.x) {
            int k = e >> 6, n = e & 63;
            float v = s[e];
            __nv_bfloat16 h = __float2bfloat16(v);
            dh[n * 128 + k] = h;
            dl[n * 128 + k] = __float2bfloat16(v - __bfloat162float(h));
        }
    } else if (b < 12) {  // W2s[b-6]: [64][128] -> [128][64]
        const float* s = W2s + (size_t)(b - 6) * 8192;
        __nv_bfloat16* dh = W2H + (size_t)(b - 6) * 8192;
        __nv_bfloat16* dl = W2L + (size_t)(b - 6) * 8192;
        for (int e = threadIdx.x; e < 8192; e += blockDim.x) {
            int k = e >> 7, n = e & 127;
            float v = s[e];
            __nv_bfloat16 h = __float2bfloat16(v);
            dh[n * 64 + k] = h;
            dl[n * 64 + k] = __float2bfloat16(v - __bfloat162float(h));
        }
    } else {              // Wf: [128][128] -> [128][128]
        for (int e = threadIdx.x; e < 16384; e += blockDim.x) {
            int k = e >> 7, n = e & 127;
            float v = Wf[e];
            __nv_bfloat16 h = __float2bfloat16(v);
            WfH[n * 128 + k] = h;
            WfL[n * 128 + k] = __float2bfloat16(v - __bfloat162float(h));
        }
    }
}

// ---------------------------------------------------------------------------
// generic HMMA 1x1 layer: C[128pts, N] = act( in[128pts, K] @ W[N,K]^T ... )
// EPI 0: down   -> relu, bf16 hi/lo planar outputs (outH/outL, stride 64)
// EPI 1: up     -> relu(acc + res), fp32 out (stride 128)
// EPI 2: final  -> res * sigmoid(acc) + xres, fp32 out (stride 128)
// 256 threads = 8 warps; warp grid WMxWN; A/W split into bf16 hi/lo in smem.
// ---------------------------------------------------------------------------
template <int K, int N, int EPI>
__global__ __launch_bounds__(256) void k_lin(
    const float* __restrict__ in,
    const __nv_bfloat16* __restrict__ BH, const __nv_bfloat16* __restrict__ BL,
    const float* __restrict__ res, const float* __restrict__ xres,
    float* __restrict__ fout,
    __nv_bfloat16* __restrict__ outH, __nv_bfloat16* __restrict__ outL)
{
    constexpr int SB   = K * 2 + 16;          // smem row stride bytes
    constexpr int ASZ  = 128 * SB;            // one A plane
    constexpr int BOFF = 2 * ASZ;             // B hi plane
    constexpr int WN   = (N == 64) ? 2 : 4;
    constexpr int WM   = 8 / WN;
    constexpr int MT   = (128 / WM) / 16;     // m16 tiles per warp
    constexpr int KS   = K / 16;

    extern __shared__ char sm[];
    const uint32_t su = smem_u32(sm);
    const int tid  = threadIdx.x;
    const int lane = tid & 31;
    const int w    = tid >> 5;
    const int wm   = w % WM;
    const int wn   = w / WM;
    const int mbase = wm * (128 / WM);
    const int p0   = blockIdx.x * 128;

    // ---- stage A (fp32 -> hi/lo bf16) ----
    {
        int row = tid >> 1, half = tid & 1;
        int gp = p0 + row;
        bool v = gp < NPTS;
        const float* src = in + (size_t)gp * K + half * (K / 2);
        char* ah = sm + row * SB + half * K;          // bytes
        char* al = sm + ASZ + row * SB + half * K;
#pragma unroll
        for (int c = 0; c < K / 2; c += 8) {
            float4 f0 = v ? *(const float4*)(src + c)     : make_float4(0, 0, 0, 0);
            float4 f1 = v ? *(const float4*)(src + c + 4) : make_float4(0, 0, 0, 0);
            unsigned h0, h1, h2, h3, l0, l1, l2, l3;
            split2(f0.x, f0.y, h0, l0);
            split2(f0.z, f0.w, h1, l1);
            split2(f1.x, f1.y, h2, l2);
            split2(f1.z, f1.w, h3, l3);
            *(uint4*)(ah + c * 2) = make_uint4(h0, h1, h2, h3);
            *(uint4*)(al + c * 2) = make_uint4(l0, l1, l2, l3);
        }
    }
    // ---- stage B (pre-split bf16, copy with pad) ----
    {
        constexpr int ITER = N * K / 1024;     // uint4 per thread per plane
        int plane = tid >> 7, t = tid & 127;
        const __nv_bfloat16* bs = plane ? BL : BH;
        char* bd = sm + BOFF + plane * (N * SB);
#pragma unroll
        for (int i = 0; i < ITER; i++) {
            int j = t + i * 128;
            int e = j * 8;
            int r = e / K, c = e % K;
            *(uint4*)(bd + r * SB + c * 2) = *(const uint4*)(bs + e);
        }
    }
    __syncthreads();

    float acc[MT][4][4];
#pragma unroll
    for (int mt = 0; mt < MT; mt++)
#pragma unroll
        for (int nt = 0; nt < 4; nt++)
#pragma unroll
            for (int e = 0; e < 4; e++) acc[mt][nt][e] = 0.f;

    const uint32_t a_ld = su + (uint32_t)(mbase + (lane & 15)) * SB
                        + (uint32_t)(lane >> 4) * 16;
    const uint32_t b_ld = su + BOFF + (uint32_t)(wn * 32 + (lane & 7)) * SB
                        + (uint32_t)((lane >> 3) & 1) * 16;

#pragma unroll
    for (int ks = 0; ks < KS; ks++) {
        uint32_t ah[MT][4], al[MT][4];
#pragma unroll
        for (int mt = 0; mt < MT; mt++) {
            ldsm_x4(ah[mt], a_ld + (uint32_t)mt * (16 * SB) + ks * 32);
            ldsm_x4(al[mt], a_ld + ASZ + (uint32_t)mt * (16 * SB) + ks * 32);
        }
#pragma unroll
        for (int nt = 0; nt < 4; nt++) {
            uint32_t bh[2], bl[2];
            ldsm_x2(bh, b_ld + (uint32_t)nt * (8 * SB) + ks * 32);
            ldsm_x2(bl, b_ld + (uint32_t)(N * SB) + (uint32_t)nt * (8 * SB) + ks * 32);
#pragma unroll
            for (int mt = 0; mt < MT; mt++) {
                mma16816(acc[mt][nt], ah[mt], bh);
                mma16816(acc[mt][nt], ah[mt], bl);
                mma16816(acc[mt][nt], al[mt], bh);
            }
        }
    }

    // ---- epilogue ----
    const int g = lane >> 2, tg = lane & 3;
#pragma unroll
    for (int mt = 0; mt < MT; mt++) {
        int r0 = p0 + mbase + mt * 16 + g;
#pragma unroll
        for (int nt = 0; nt < 4; nt++) {
            int col = wn * 32 + nt * 8 + tg * 2;
            float c0 = acc[mt][nt][0], c1 = acc[mt][nt][1];
            float c2 = acc[mt][nt][2], c3 = acc[mt][nt][3];
            if (EPI == 0) {
                if (r0 < NPTS) {
                    unsigned h, l;
                    split2(fmaxf(c0, 0.f), fmaxf(c1, 0.f), h, l);
                    *(unsigned*)(outH + (size_t)r0 * 64 + col) = h;
                    *(unsigned*)(outL + (size_t)r0 * 64 + col) = l;
                }
                if (r0 + 8 < NPTS) {
                    unsigned h, l;
                    split2(fmaxf(c2, 0.f), fmaxf(c3, 0.f), h, l);
                    *(unsigned*)(outH + (size_t)(r0 + 8) * 64 + col) = h;
                    *(unsigned*)(outL + (size_t)(r0 + 8) * 64 + col) = l;
                }
            } else if (EPI == 1) {
                if (r0 < NPTS) {
                    float2 rr = *(const float2*)(res + (size_t)r0 * 128 + col);
                    float2 o;
                    o.x = fmaxf(c0 + rr.x, 0.f);
                    o.y = fmaxf(c1 + rr.y, 0.f);
                    *(float2*)(fout + (size_t)r0 * 128 + col) = o;
                }
                if (r0 + 8 < NPTS) {
                    float2 rr = *(const float2*)(res + (size_t)(r0 + 8) * 128 + col);
                    float2 o;
                    o.x = fmaxf(c2 + rr.x, 0.f);
                    o.y = fmaxf(c3 + rr.y, 0.f);
                    *(float2*)(fout + (size_t)(r0 + 8) * 128 + col) = o;
                }
            } else {
                if (r0 < NPTS) {
                    float2 aa = *(const float2*)(res  + (size_t)r0 * 128 + col);
                    float2 xx = *(const float2*)(xres + (size_t)r0 * 128 + col);
                    float2 o;
                    o.x = aa.x / (1.f + __expf(-c0)) + xx.x;
                    o.y = aa.y / (1.f + __expf(-c1)) + xx.y;
                    *(float2*)(fout + (size_t)r0 * 128 + col) = o;
                }
                if (r0 + 8 < NPTS) {
                    float2 aa = *(const float2*)(res  + (size_t)(r0 + 8) * 128 + col);
                    float2 xx = *(const float2*)(xres + (size_t)(r0 + 8) * 128 + col);
                    float2 o;
                    o.x = aa.x / (1.f + __expf(-c2)) + xx.x;
                    o.y = aa.y / (1.f + __expf(-c3)) + xx.y;
                    *(float2*)(fout + (size_t)(r0 + 8) * 128 + col) = o;
                }
            }
        }
    }
}

// ---------------------------------------------------------------------------
// HMMA conv with register-prefetch pipelining.
// CTA: 128 pts x 64 out-ch, 8 warps (4Mx2N), bf16 hi/lo split, fp32 acc.
// smem: Ahi@0 (128*144), Alo@18432, Bhi@36864 (64*144), Blo@46080,
//       idx@55296 (27*128*4)  total 69120 -> 2 CTAs/SM
// ---------------------------------------------------------------------------
#define CONV_SMEM 69120
#define ASTRIDE 144
#define A_LO 18432
#define B_HI 36864
#define IDX_OFF 55296

__global__ __launch_bounds__(256, 2) void k_conv_mma(
    const __nv_bfloat16* __restrict__ Thi, const __nv_bfloat16* __restrict__ Tlo,
    const __nv_bfloat16* __restrict__ WtH, const __nv_bfloat16* __restrict__ WtL,
    const int* __restrict__ nbr, float* __restrict__ out)
{
    extern __shared__ char sm[];
    const int tid  = threadIdx.x;
    const int lane = tid & 31;
    const int w    = tid >> 5;
    const int wm   = w & 3;
    const int wn   = w >> 2;
    const int p0   = blockIdx.x * 128;

    const uint32_t su = smem_u32(sm);
    int* idxs = (int*)(sm + IDX_OFF);

    for (int i = tid; i < 27 * 128; i += 256) {
        int p = i / 27;
        int k = i - p * 27;
        int gp = p0 + p;
        idxs[k * 128 + p] = (gp < NPTS) ? nbr[(size_t)gp * 27 + k] : -1;
    }

    float acc[2][4][4];
#pragma unroll
    for (int mt = 0; mt < 2; mt++)
#pragma unroll
        for (int nt = 0; nt < 4; nt++)
#pragma unroll
            for (int e = 0; e < 4; e++) acc[mt][nt][e] = 0.f;

    const int pr    = tid >> 1;
    const int ahalf = tid & 1;
    const uint32_t a_dst = (uint32_t)pr * ASTRIDE + (uint32_t)ahalf * 64;
    const int bplane = tid >> 7;
    const int brow   = (tid & 127) >> 1;
    const uint32_t b_dst = (uint32_t)(B_HI + bplane * 9216)
                         + (uint32_t)brow * ASTRIDE + (uint32_t)ahalf * 64;

    const uint32_t a_ld = su + (uint32_t)(wm * 32 + (lane & 15)) * ASTRIDE
                        + (uint32_t)(lane >> 4) * 16;
    const uint32_t b_ld = su + B_HI + (uint32_t)(wn * 32 + (lane & 7)) * ASTRIDE
                        + (uint32_t)((lane >> 3) & 1) * 16;

    __syncthreads();   // idxs visible

    uint4 sh[4], sl[4], wsv[4];
    // prefetch tap 0
    {
        int row = idxs[pr];   // k=0
        if (row >= 0) {
            const uint4* s1 = (const uint4*)(Thi + (size_t)row * 64 + ahalf * 32);
            const uint4* s2 = (const uint4*)(Tlo + (size_t)row * 64 + ahalf * 32);
#pragma unroll
            for (int i = 0; i < 4; i++) { sh[i] = s1[i]; sl[i] = s2[i]; }
        } else {
            uint4 z = make_uint4(0, 0, 0, 0);
#pragma unroll
            for (int i = 0; i < 4; i++) { sh[i] = z; sl[i] = z; }
        }
        const uint4* ws = (const uint4*)((bplane ? WtL : WtH)
                          + (size_t)brow * 64 + ahalf * 32);
#pragma unroll
        for (int i = 0; i < 4; i++) wsv[i] = ws[i];
    }

    for (int k = 0; k < 27; k++) {
        __syncthreads();   // previous tap's ldmatrix reads complete
        {
            char* Ah = sm + a_dst;
            char* Al = sm + A_LO + a_dst;
            char* Bd = sm + b_dst;
#pragma unroll
            for (int i = 0; i < 4; i++) {
                *(uint4*)(Ah + i * 16) = sh[i];
                *(uint4*)(Al + i * 16) = sl[i];
                *(uint4*)(Bd + i * 16) = wsv[i];
            }
        }
        __syncthreads();   // stores visible

        // prefetch tap k+1 (LDG latency hides behind MMA below)
        if (k < 26) {
            int row = idxs[(k + 1) * 128 + pr];
            if (row >= 0) {
                const uint4* s1 = (const uint4*)(Thi + (size_t)row * 64 + ahalf * 32);
                const uint4* s2 = (const uint4*)(Tlo + (size_t)row * 64 + ahalf * 32);
#pragma unroll
                for (int i = 0; i < 4; i++) { sh[i] = s1[i]; sl[i] = s2[i]; }
            } else {
                uint4 z = make_uint4(0, 0, 0, 0);
#pragma unroll
                for (int i = 0; i < 4; i++) { sh[i] = z; sl[i] = z; }
            }
            const uint4* ws = (const uint4*)((bplane ? WtL : WtH)
                              + ((size_t)(k + 1) * 64 + brow) * 64 + ahalf * 32);
#pragma unroll
            for (int i = 0; i < 4; i++) wsv[i] = ws[i];
        }

        // MMA over K=64 (4 ksteps of 16)
#pragma unroll
        for (int ks = 0; ks < 4; ks++) {
            uint32_t ah[2][4], al[2][4];
#pragma unroll
            for (int mt = 0; mt < 2; mt++) {
                ldsm_x4(ah[mt], a_ld + (uint32_t)mt * (16 * ASTRIDE) + ks * 32);
                ldsm_x4(al[mt], a_ld + A_LO + (uint32_t)mt * (16 * ASTRIDE) + ks * 32);
            }
#pragma unroll
            for (int nt = 0; nt < 4; nt++) {
                uint32_t bh[2], bl[2];
                ldsm_x2(bh, b_ld + (uint32_t)nt * (8 * ASTRIDE) + ks * 32);
                ldsm_x2(bl, b_ld + 9216 + (uint32_t)nt * (8 * ASTRIDE) + ks * 32);
#pragma unroll
                for (int mt = 0; mt < 2; mt++) {
                    mma16816(acc[mt][nt], ah[mt], bh);
                    mma16816(acc[mt][nt], ah[mt], bl);
                    mma16816(acc[mt][nt], al[mt], bh);
                }
            }
        }
    }

    // epilogue: relu + fp32 store
    const int g = lane >> 2, tg = lane & 3;
#pragma unroll
    for (int mt = 0; mt < 2; mt++) {
        int row0 = p0 + wm * 32 + mt * 16 + g;
#pragma unroll
        for (int nt = 0; nt < 4; nt++) {
            int col = wn * 32 + nt * 8 + tg * 2;
            if (row0 < NPTS) {
                float2 o;
                o.x = fmaxf(acc[mt][nt][0], 0.f);
                o.y = fmaxf(acc[mt][nt][1], 0.f);
                *(float2*)(out + (size_t)row0 * 64 + col) = o;
            }
            if (row0 + 8 < NPTS) {
                float2 o;
                o.x = fmaxf(acc[mt][nt][2], 0.f);
                o.y = fmaxf(acc[mt][nt][3], 0.f);
                *(float2*)(out + (size_t)(row0 + 8) * 64 + col) = o;
            }
        }
    }
}

// ---------------------------------------------------------------------------
extern "C" void kernel_launch(void* const* d_in, const int* in_sizes, int n_in,
                              void* d_out, int out_size)
{
    const float* x   = (const float*)d_in[0];
    const float* W1s = (const float*)d_in[1];
    const float* Wks = (const float*)d_in[2];
    const float* W2s = (const float*)d_in[3];
    const float* Wf  = (const float*)d_in[4];
    const int*   nbr = (const int*)d_in[5];
    float* out = (float*)d_out;

    float *A, *B, *T2;
    __nv_bfloat16 *Thi, *Tlo, *WtH, *WtL, *W1H, *W1L, *W2H, *W2L, *WfH, *WfL;
    cudaGetSymbolAddress((void**)&A,   g_A);
    cudaGetSymbolAddress((void**)&B,   g_B);
    cudaGetSymbolAddress((void**)&T2,  g_T2);
    cudaGetSymbolAddress((void**)&Thi, g_Thi);
    cudaGetSymbolAddress((void**)&Tlo, g_Tlo);
    cudaGetSymbolAddress((void**)&WtH, g_WtH);
    cudaGetSymbolAddress((void**)&WtL, g_WtL);
    cudaGetSymbolAddress((void**)&W1H, g_W1H);
    cudaGetSymbolAddress((void**)&W1L, g_W1L);
    cudaGetSymbolAddress((void**)&W2H, g_W2H);
    cudaGetSymbolAddress((void**)&W2L, g_W2L);
    cudaGetSymbolAddress((void**)&WfH, g_WfH);
    cudaGetSymbolAddress((void**)&WfL, g_WfL);

    constexpr int SM_DOWN  = (128 * 2 + 16) * (256 + 2 * 64);   // 104448
    constexpr int SM_UP    = (64 * 2 + 16) * (256 + 2 * 128);   // 73728
    constexpr int SM_FINAL = (128 * 2 + 16) * (256 + 2 * 128);  // 139264

    cudaFuncSetAttribute(k_conv_mma, cudaFuncAttributeMaxDynamicSharedMemorySize,
                         CONV_SMEM);
    cudaFuncSetAttribute((const void*)k_lin<128, 64, 0>,
                         cudaFuncAttributeMaxDynamicSharedMemorySize, SM_DOWN);
    cudaFuncSetAttribute((const void*)k_lin<64, 128, 1>,
                         cudaFuncAttributeMaxDynamicSharedMemorySize, SM_UP);
    cudaFuncSetAttribute((const void*)k_lin<128, 128, 2>,
                         cudaFuncAttributeMaxDynamicSharedMemorySize, SM_FINAL);

    // one-time weight splitting (cheap; kept in the graph each launch)
    k_wsplit<<<dim3(27, 6), 256>>>(Wks, WtH, WtL);
    k_wsplit_lin<<<13, 256>>>(W1s, W2s, Wf, W1H, W1L, W2H, W2L, WfH, WfL);

    for (int i = 0; i < 6; i++) {
        const float* hin = (i == 0) ? x : ((i == 3) ? x : ((i < 3) ? A : B));
        float* hout = (i < 3) ? A : B;
        k_lin<128, 64, 0><<<NBLK128, 256, SM_DOWN>>>(
            hin, W1H + (size_t)i * 8192, W1L + (size_t)i * 8192,
            nullptr, nullptr, nullptr, Thi, Tlo);
        k_conv_mma<<<NBLK128, 256, CONV_SMEM>>>(
            Thi, Tlo, WtH + (size_t)i * 27 * 4096, WtL + (size_t)i * 27 * 4096,
            nbr, T2);
        k_lin<64, 128, 1><<<NBLK128, 256, SM_UP>>>(
            T2, W2H + (size_t)i * 8192, W2L + (size_t)i * 8192,
            hin, nullptr, hout, nullptr, nullptr);
    }
    k_lin<128, 128, 2><<<NBLK128, 256, SM_FINAL>>>(
        B, WfH, WfL, A, x, out, nullptr, nullptr);
}

// round 5
// speedup vs baseline: 2.4119x; 1.2319x over previous
#include <cuda_runtime.h>
#include <cuda_bf16.h>
#include <cuda_fp16.h>
#include <cstdint>

#define NPTS 120000
#define NBLK128 938   // ceil(120000/128)

// ---------------- scratch (device globals: allocation-free) ----------------
__device__ float g_A[NPTS * 128];
__device__ float g_B[NPTS * 128];
__device__ float g_T2[NPTS * 64];
__device__ __half g_T16[NPTS * 64];                 // conv input activations (fp16)
__device__ __half g_WtH[6 * 27 * 64 * 64];          // conv weights [u][k][j][c] fp16 hi
__device__ __half g_WtL[6 * 27 * 64 * 64];          // fp16 lo residual
__device__ __nv_bfloat16 g_W1H[6 * 64 * 128];       // down weights [u][n][k]
__device__ __nv_bfloat16 g_W1L[6 * 64 * 128];
__device__ __nv_bfloat16 g_W2H[6 * 128 * 64];       // up weights [u][n][k]
__device__ __nv_bfloat16 g_W2L[6 * 128 * 64];
__device__ __nv_bfloat16 g_WfH[128 * 128];          // final weights [n][k]
__device__ __nv_bfloat16 g_WfL[128 * 128];

// ---------------- helpers ---------------------------------------------------
__device__ __forceinline__ uint32_t smem_u32(const void* p) {
    uint32_t a;
    asm("{ .reg .u64 t; cvta.to.shared.u64 t, %1; cvt.u32.u64 %0, t; }"
        : "=r"(a) : "l"(p));
    return a;
}
__device__ __forceinline__ void ldsm_x4(uint32_t (&r)[4], uint32_t addr) {
    asm volatile("ldmatrix.sync.aligned.m8n8.x4.shared.b16 {%0,%1,%2,%3}, [%4];"
                 : "=r"(r[0]), "=r"(r[1]), "=r"(r[2]), "=r"(r[3]) : "r"(addr));
}
__device__ __forceinline__ void ldsm_x2(uint32_t (&r)[2], uint32_t addr) {
    asm volatile("ldmatrix.sync.aligned.m8n8.x2.shared.b16 {%0,%1}, [%2];"
                 : "=r"(r[0]), "=r"(r[1]) : "r"(addr));
}
// bf16 HMMA
__device__ __forceinline__ void mma_bf16(float* c, const uint32_t* a,
                                         const uint32_t* b) {
    asm volatile(
        "mma.sync.aligned.m16n8k16.row.col.f32.bf16.bf16.f32 "
        "{%0,%1,%2,%3}, {%4,%5,%6,%7}, {%8,%9}, {%0,%1,%2,%3};"
        : "+f"(c[0]), "+f"(c[1]), "+f"(c[2]), "+f"(c[3])
        : "r"(a[0]), "r"(a[1]), "r"(a[2]), "r"(a[3]), "r"(b[0]), "r"(b[1]));
}
// fp16 HMMA
__device__ __forceinline__ void mma_f16(float* c, const uint32_t* a,
                                        uint32_t b0, uint32_t b1) {
    asm volatile(
        "mma.sync.aligned.m16n8k16.row.col.f32.f16.f16.f32 "
        "{%0,%1,%2,%3}, {%4,%5,%6,%7}, {%8,%9}, {%0,%1,%2,%3};"
        : "+f"(c[0]), "+f"(c[1]), "+f"(c[2]), "+f"(c[3])
        : "r"(a[0]), "r"(a[1]), "r"(a[2]), "r"(a[3]), "r"(b0), "r"(b1));
}
__device__ __forceinline__ unsigned pack_bf2(__nv_bfloat16 a, __nv_bfloat16 b) {
    __nv_bfloat162 t; t.x = a; t.y = b;
    return *reinterpret_cast<unsigned*>(&t);
}
__device__ __forceinline__ void split2(float x, float y, unsigned& h, unsigned& l) {
    __nv_bfloat16 hx = __float2bfloat16(x);
    __nv_bfloat16 hy = __float2bfloat16(y);
    float rx = x - __bfloat162float(hx);
    float ry = y - __bfloat162float(hy);
    h = pack_bf2(hx, hy);
    l = pack_bf2(__float2bfloat16(rx), __float2bfloat16(ry));
}

// ---------------------------------------------------------------------------
// conv weight split+transpose: Wt[u][k][j][c] = Wk[u][k][c][j] as fp16 hi/lo
// ---------------------------------------------------------------------------
__global__ void k_wsplit(const float* __restrict__ Wks,
                         __half* __restrict__ WtH,
                         __half* __restrict__ WtL) {
    int k = blockIdx.x, u = blockIdx.y;
    const float* src = Wks + ((size_t)u * 27 + k) * 4096;
    __half* dh = WtH + ((size_t)u * 27 + k) * 4096;
    __half* dl = WtL + ((size_t)u * 27 + k) * 4096;
    for (int e = threadIdx.x; e < 4096; e += blockDim.x) {
        int c = e >> 6, j = e & 63;
        float v = src[c * 64 + j];
        __half h = __float2half(v);
        float r = v - __half2float(h);
        dh[j * 64 + c] = h;
        dl[j * 64 + c] = __float2half(r);
    }
}

// ---------------------------------------------------------------------------
// linear weight split+transpose: [k][n] fp32 -> [n][k] bf16 hi/lo
// blocks: 0-5 = W1s units, 6-11 = W2s units, 12 = Wf
// ---------------------------------------------------------------------------
__global__ void k_wsplit_lin(const float* __restrict__ W1s,
                             const float* __restrict__ W2s,
                             const float* __restrict__ Wf,
                             __nv_bfloat16* __restrict__ W1H, __nv_bfloat16* __restrict__ W1L,
                             __nv_bfloat16* __restrict__ W2H, __nv_bfloat16* __restrict__ W2L,
                             __nv_bfloat16* __restrict__ WfH, __nv_bfloat16* __restrict__ WfL) {
    int b = blockIdx.x;
    if (b < 6) {
        const float* s = W1s + (size_t)b * 8192;
        __nv_bfloat16* dh = W1H + (size_t)b * 8192;
        __nv_bfloat16* dl = W1L + (size_t)b * 8192;
        for (int e = threadIdx.x; e < 8192; e += blockDim.x) {
            int k = e >> 6, n = e & 63;
            float v = s[e];
            __nv_bfloat16 h = __float2bfloat16(v);
            dh[n * 128 + k] = h;
            dl[n * 128 + k] = __float2bfloat16(v - __bfloat162float(h));
        }
    } else if (b < 12) {
        const float* s = W2s + (size_t)(b - 6) * 8192;
        __nv_bfloat16* dh = W2H + (size_t)(b - 6) * 8192;
        __nv_bfloat16* dl = W2L + (size_t)(b - 6) * 8192;
        for (int e = threadIdx.x; e < 8192; e += blockDim.x) {
            int k = e >> 7, n = e & 127;
            float v = s[e];
            __nv_bfloat16 h = __float2bfloat16(v);
            dh[n * 64 + k] = h;
            dl[n * 64 + k] = __float2bfloat16(v - __bfloat162float(h));
        }
    } else {
        for (int e = threadIdx.x; e < 16384; e += blockDim.x) {
            int k = e >> 7, n = e & 127;
            float v = Wf[e];
            __nv_bfloat16 h = __float2bfloat16(v);
            WfH[n * 128 + k] = h;
            WfL[n * 128 + k] = __float2bfloat16(v - __bfloat162float(h));
        }
    }
}

// ---------------------------------------------------------------------------
// generic HMMA 1x1 layer (bf16 3-product): C = act( in[128,K] @ W[N,K]^T ...)
// EPI 0: relu -> single fp16 plane (out16, stride 64)
// EPI 1: relu(acc + res) -> fp32 (stride 128)
// EPI 2: res * sigmoid(acc) + xres -> fp32 (stride 128)
// ---------------------------------------------------------------------------
template <int K, int N, int EPI>
__global__ __launch_bounds__(256) void k_lin(
    const float* __restrict__ in,
    const __nv_bfloat16* __restrict__ BH, const __nv_bfloat16* __restrict__ BL,
    const float* __restrict__ res, const float* __restrict__ xres,
    float* __restrict__ fout, __half* __restrict__ out16)
{
    constexpr int SB   = K * 2 + 16;
    constexpr int ASZ  = 128 * SB;
    constexpr int BOFF = 2 * ASZ;
    constexpr int WN   = (N == 64) ? 2 : 4;
    constexpr int WM   = 8 / WN;
    constexpr int MT   = (128 / WM) / 16;
    constexpr int KS   = K / 16;

    extern __shared__ char sm[];
    const uint32_t su = smem_u32(sm);
    const int tid  = threadIdx.x;
    const int lane = tid & 31;
    const int w    = tid >> 5;
    const int wm   = w % WM;
    const int wn   = w / WM;
    const int mbase = wm * (128 / WM);
    const int p0   = blockIdx.x * 128;

    // stage A (fp32 -> hi/lo bf16)
    {
        int row = tid >> 1, half = tid & 1;
        int gp = p0 + row;
        bool v = gp < NPTS;
        const float* src = in + (size_t)gp * K + half * (K / 2);
        char* ah = sm + row * SB + half * K;
        char* al = sm + ASZ + row * SB + half * K;
#pragma unroll
        for (int c = 0; c < K / 2; c += 8) {
            float4 f0 = v ? *(const float4*)(src + c)     : make_float4(0, 0, 0, 0);
            float4 f1 = v ? *(const float4*)(src + c + 4) : make_float4(0, 0, 0, 0);
            unsigned h0, h1, h2, h3, l0, l1, l2, l3;
            split2(f0.x, f0.y, h0, l0);
            split2(f0.z, f0.w, h1, l1);
            split2(f1.x, f1.y, h2, l2);
            split2(f1.z, f1.w, h3, l3);
            *(uint4*)(ah + c * 2) = make_uint4(h0, h1, h2, h3);
            *(uint4*)(al + c * 2) = make_uint4(l0, l1, l2, l3);
        }
    }
    // stage B (pre-split bf16)
    {
        constexpr int ITER = N * K / 1024;
        int plane = tid >> 7, t = tid & 127;
        const __nv_bfloat16* bs = plane ? BL : BH;
        char* bd = sm + BOFF + plane * (N * SB);
#pragma unroll
        for (int i = 0; i < ITER; i++) {
            int j = t + i * 128;
            int e = j * 8;
            int r = e / K, c = e % K;
            *(uint4*)(bd + r * SB + c * 2) = *(const uint4*)(bs + e);
        }
    }
    __syncthreads();

    float acc[MT][4][4];
#pragma unroll
    for (int mt = 0; mt < MT; mt++)
#pragma unroll
        for (int nt = 0; nt < 4; nt++)
#pragma unroll
            for (int e = 0; e < 4; e++) acc[mt][nt][e] = 0.f;

    const uint32_t a_ld = su + (uint32_t)(mbase + (lane & 15)) * SB
                        + (uint32_t)(lane >> 4) * 16;
    const uint32_t b_ld = su + BOFF + (uint32_t)(wn * 32 + (lane & 7)) * SB
                        + (uint32_t)((lane >> 3) & 1) * 16;

#pragma unroll
    for (int ks = 0; ks < KS; ks++) {
        uint32_t ah[MT][4], al[MT][4];
#pragma unroll
        for (int mt = 0; mt < MT; mt++) {
            ldsm_x4(ah[mt], a_ld + (uint32_t)mt * (16 * SB) + ks * 32);
            ldsm_x4(al[mt], a_ld + ASZ + (uint32_t)mt * (16 * SB) + ks * 32);
        }
#pragma unroll
        for (int nt = 0; nt < 4; nt++) {
            uint32_t bh[2], bl[2];
            ldsm_x2(bh, b_ld + (uint32_t)nt * (8 * SB) + ks * 32);
            ldsm_x2(bl, b_ld + (uint32_t)(N * SB) + (uint32_t)nt * (8 * SB) + ks * 32);
#pragma unroll
            for (int mt = 0; mt < MT; mt++) {
                mma_bf16(acc[mt][nt], ah[mt], bh);
                mma_bf16(acc[mt][nt], ah[mt], bl);
                mma_bf16(acc[mt][nt], al[mt], bh);
            }
        }
    }

    const int g = lane >> 2, tg = lane & 3;
#pragma unroll
    for (int mt = 0; mt < MT; mt++) {
        int r0 = p0 + mbase + mt * 16 + g;
#pragma unroll
        for (int nt = 0; nt < 4; nt++) {
            int col = wn * 32 + nt * 8 + tg * 2;
            float c0 = acc[mt][nt][0], c1 = acc[mt][nt][1];
            float c2 = acc[mt][nt][2], c3 = acc[mt][nt][3];
            if (EPI == 0) {
                if (r0 < NPTS) {
                    __half2 o = __floats2half2_rn(fmaxf(c0, 0.f), fmaxf(c1, 0.f));
                    *(__half2*)(out16 + (size_t)r0 * 64 + col) = o;
                }
                if (r0 + 8 < NPTS) {
                    __half2 o = __floats2half2_rn(fmaxf(c2, 0.f), fmaxf(c3, 0.f));
                    *(__half2*)(out16 + (size_t)(r0 + 8) * 64 + col) = o;
                }
            } else if (EPI == 1) {
                if (r0 < NPTS) {
                    float2 rr = *(const float2*)(res + (size_t)r0 * 128 + col);
                    float2 o;
                    o.x = fmaxf(c0 + rr.x, 0.f);
                    o.y = fmaxf(c1 + rr.y, 0.f);
                    *(float2*)(fout + (size_t)r0 * 128 + col) = o;
                }
                if (r0 + 8 < NPTS) {
                    float2 rr = *(const float2*)(res + (size_t)(r0 + 8) * 128 + col);
                    float2 o;
                    o.x = fmaxf(c2 + rr.x, 0.f);
                    o.y = fmaxf(c3 + rr.y, 0.f);
                    *(float2*)(fout + (size_t)(r0 + 8) * 128 + col) = o;
                }
            } else {
                if (r0 < NPTS) {
                    float2 aa = *(const float2*)(res  + (size_t)r0 * 128 + col);
                    float2 xx = *(const float2*)(xres + (size_t)r0 * 128 + col);
                    float2 o;
                    o.x = aa.x / (1.f + __expf(-c0)) + xx.x;
                    o.y = aa.y / (1.f + __expf(-c1)) + xx.y;
                    *(float2*)(fout + (size_t)r0 * 128 + col) = o;
                }
                if (r0 + 8 < NPTS) {
                    float2 aa = *(const float2*)(res  + (size_t)(r0 + 8) * 128 + col);
                    float2 xx = *(const float2*)(xres + (size_t)(r0 + 8) * 128 + col);
                    float2 o;
                    o.x = aa.x / (1.f + __expf(-c2)) + xx.x;
                    o.y = aa.y / (1.f + __expf(-c3)) + xx.y;
                    *(float2*)(fout + (size_t)(r0 + 8) * 128 + col) = o;
                }
            }
        }
    }
}

// ---------------------------------------------------------------------------
// fp16 HMMA conv, 2-product split (A single fp16, W = Wh + Wl fp16):
//   acc += A*Wh + A*Wl
// CTA: 128 pts x 64 out-ch, 8 warps (4Mx2N), fp32 acc, register-prefetch pipe.
// smem: A @0 (128*144=18432), Bhi @18432 (64*144=9216), Blo @27648 (9216),
//       idx @36864 (27*128*4=13824)  -> total 50688, 2 CTAs/SM
// ---------------------------------------------------------------------------
#define CONV_SMEM 50688
#define ASTRIDE 144
#define B_HI 18432
#define B_LO 27648
#define IDX_OFF 36864

__global__ __launch_bounds__(256, 2) void k_conv_mma(
    const __half* __restrict__ T16,
    const __half* __restrict__ WtH, const __half* __restrict__ WtL,
    const int* __restrict__ nbr, float* __restrict__ out)
{
    extern __shared__ char sm[];
    const int tid  = threadIdx.x;
    const int lane = tid & 31;
    const int w    = tid >> 5;
    const int wm   = w & 3;
    const int wn   = w >> 2;
    const int p0   = blockIdx.x * 128;

    const uint32_t su = smem_u32(sm);
    int* idxs = (int*)(sm + IDX_OFF);

    for (int i = tid; i < 27 * 128; i += 256) {
        int p = i / 27;
        int k = i - p * 27;
        int gp = p0 + p;
        idxs[k * 128 + p] = (gp < NPTS) ? nbr[(size_t)gp * 27 + k] : -1;
    }

    float acc[2][4][4];
#pragma unroll
    for (int mt = 0; mt < 2; mt++)
#pragma unroll
        for (int nt = 0; nt < 4; nt++)
#pragma unroll
            for (int e = 0; e < 4; e++) acc[mt][nt][e] = 0.f;

    // staging: A rows (128 x 128B) -> 2 threads/row, 64B each
    const int pr    = tid >> 1;
    const int ahalf = tid & 1;
    const uint32_t a_dst = (uint32_t)pr * ASTRIDE + (uint32_t)ahalf * 64;
    // B rows: 128 total (hi 64 + lo 64), 2 threads/row
    const int bplane = tid >> 7;
    const int brow   = (tid & 127) >> 1;
    const uint32_t b_dst = (uint32_t)(B_HI + bplane * 9216)
                         + (uint32_t)brow * ASTRIDE + (uint32_t)ahalf * 64;

    // ldmatrix addresses
    const uint32_t a_ld = su + (uint32_t)(wm * 32 + (lane & 15)) * ASTRIDE
                        + (uint32_t)(lane >> 4) * 16;
    const uint32_t b_ld = su + B_HI + (uint32_t)(wn * 32 + (lane & 15)) * ASTRIDE
                        + (uint32_t)(lane >> 4) * 16;

    __syncthreads();   // idxs visible

    uint4 av[4], wv[4];
    // prefetch tap 0
    {
        int row = idxs[pr];
        if (row >= 0) {
            const uint4* s1 = (const uint4*)(T16 + (size_t)row * 64 + ahalf * 32);
#pragma unroll
            for (int i = 0; i < 4; i++) av[i] = s1[i];
        } else {
            uint4 z = make_uint4(0, 0, 0, 0);
#pragma unroll
            for (int i = 0; i < 4; i++) av[i] = z;
        }
        const uint4* ws = (const uint4*)((bplane ? WtL : WtH)
                          + (size_t)brow * 64 + ahalf * 32);
#pragma unroll
        for (int i = 0; i < 4; i++) wv[i] = ws[i];
    }

    for (int k = 0; k < 27; k++) {
        __syncthreads();   // previous tap's ldmatrix reads complete
        {
            char* Ad = sm + a_dst;
            char* Bd = sm + b_dst;
#pragma unroll
            for (int i = 0; i < 4; i++) {
                *(uint4*)(Ad + i * 16) = av[i];
                *(uint4*)(Bd + i * 16) = wv[i];
            }
        }
        __syncthreads();   // stores visible

        // prefetch tap k+1 (LDG latency hides behind MMA below)
        if (k < 26) {
            int row = idxs[(k + 1) * 128 + pr];
            if (row >= 0) {
                const uint4* s1 = (const uint4*)(T16 + (size_t)row * 64 + ahalf * 32);
#pragma unroll
                for (int i = 0; i < 4; i++) av[i] = s1[i];
            } else {
                uint4 z = make_uint4(0, 0, 0, 0);
#pragma unroll
                for (int i = 0; i < 4; i++) av[i] = z;
            }
            const uint4* ws = (const uint4*)((bplane ? WtL : WtH)
                              + ((size_t)(k + 1) * 64 + brow) * 64 + ahalf * 32);
#pragma unroll
            for (int i = 0; i < 4; i++) wv[i] = ws[i];
        }

        // MMA over K=64 (4 ksteps of 16); B loaded as 16x16 blocks via ldsm_x4
#pragma unroll
        for (int ks = 0; ks < 4; ks++) {
            uint32_t a0[4], a1[4];
            ldsm_x4(a0, a_ld + ks * 32);
            ldsm_x4(a1, a_ld + 16 * ASTRIDE + ks * 32);
#pragma unroll
            for (int nt2 = 0; nt2 < 2; nt2++) {
                uint32_t bh[4], bl[4];
                ldsm_x4(bh, b_ld + (uint32_t)nt2 * (16 * ASTRIDE) + ks * 32);
                ldsm_x4(bl, b_ld + 9216 + (uint32_t)nt2 * (16 * ASTRIDE) + ks * 32);
                // nt even uses rows 0-7 ({m0,m2}); nt odd rows 8-15 ({m1,m3})
                mma_f16(acc[0][nt2 * 2 + 0], a0, bh[0], bh[2]);
                mma_f16(acc[0][nt2 * 2 + 0], a0, bl[0], bl[2]);
                mma_f16(acc[0][nt2 * 2 + 1], a0, bh[1], bh[3]);
                mma_f16(acc[0][nt2 * 2 + 1], a0, bl[1], bl[3]);
                mma_f16(acc[1][nt2 * 2 + 0], a1, bh[0], bh[2]);
                mma_f16(acc[1][nt2 * 2 + 0], a1, bl[0], bl[2]);
                mma_f16(acc[1][nt2 * 2 + 1], a1, bh[1], bh[3]);
                mma_f16(acc[1][nt2 * 2 + 1], a1, bl[1], bl[3]);
            }
        }
    }

    // epilogue: relu + fp32 store
    const int g = lane >> 2, tg = lane & 3;
#pragma unroll
    for (int mt = 0; mt < 2; mt++) {
        int row0 = p0 + wm * 32 + mt * 16 + g;
#pragma unroll
        for (int nt = 0; nt < 4; nt++) {
            int col = wn * 32 + nt * 8 + tg * 2;
            if (row0 < NPTS) {
                float2 o;
                o.x = fmaxf(acc[mt][nt][0], 0.f);
                o.y = fmaxf(acc[mt][nt][1], 0.f);
                *(float2*)(out + (size_t)row0 * 64 + col) = o;
            }
            if (row0 + 8 < NPTS) {
                float2 o;
                o.x = fmaxf(acc[mt][nt][2], 0.f);
                o.y = fmaxf(acc[mt][nt][3], 0.f);
                *(float2*)(out + (size_t)(row0 + 8) * 64 + col) = o;
            }
        }
    }
}

// ---------------------------------------------------------------------------
extern "C" void kernel_launch(void* const* d_in, const int* in_sizes, int n_in,
                              void* d_out, int out_size)
{
    const float* x   = (const float*)d_in[0];
    const float* W1s = (const float*)d_in[1];
    const float* Wks = (const float*)d_in[2];
    const float* W2s = (const float*)d_in[3];
    const float* Wf  = (const float*)d_in[4];
    const int*   nbr = (const int*)d_in[5];
    float* out = (float*)d_out;

    float *A, *B, *T2;
    __half *T16, *WtH, *WtL;
    __nv_bfloat16 *W1H, *W1L, *W2H, *W2L, *WfH, *WfL;
    cudaGetSymbolAddress((void**)&A,   g_A);
    cudaGetSymbolAddress((void**)&B,   g_B);
    cudaGetSymbolAddress((void**)&T2,  g_T2);
    cudaGetSymbolAddress((void**)&T16, g_T16);
    cudaGetSymbolAddress((void**)&WtH, g_WtH);
    cudaGetSymbolAddress((void**)&WtL, g_WtL);
    cudaGetSymbolAddress((void**)&W1H, g_W1H);
    cudaGetSymbolAddress((void**)&W1L, g_W1L);
    cudaGetSymbolAddress((void**)&W2H, g_W2H);
    cudaGetSymbolAddress((void**)&W2L, g_W2L);
    cudaGetSymbolAddress((void**)&WfH, g_WfH);
    cudaGetSymbolAddress((void**)&WfL, g_WfL);

    constexpr int SM_DOWN  = (128 * 2 + 16) * (256 + 2 * 64);   // 104448
    constexpr int SM_UP    = (64 * 2 + 16) * (256 + 2 * 128);   // 73728
    constexpr int SM_FINAL = (128 * 2 + 16) * (256 + 2 * 128);  // 139264

    cudaFuncSetAttribute(k_conv_mma, cudaFuncAttributeMaxDynamicSharedMemorySize,
                         CONV_SMEM);
    cudaFuncSetAttribute((const void*)k_lin<128, 64, 0>,
                         cudaFuncAttributeMaxDynamicSharedMemorySize, SM_DOWN);
    cudaFuncSetAttribute((const void*)k_lin<64, 128, 1>,
                         cudaFuncAttributeMaxDynamicSharedMemorySize, SM_UP);
    cudaFuncSetAttribute((const void*)k_lin<128, 128, 2>,
                         cudaFuncAttributeMaxDynamicSharedMemorySize, SM_FINAL);

    k_wsplit<<<dim3(27, 6), 256>>>(Wks, WtH, WtL);
    k_wsplit_lin<<<13, 256>>>(W1s, W2s, Wf, W1H, W1L, W2H, W2L, WfH, WfL);

    for (int i = 0; i < 6; i++) {
        const float* hin = (i == 0 || i == 3) ? x : ((i < 3) ? A : B);
        float* hout = (i < 3) ? A : B;
        k_lin<128, 64, 0><<<NBLK128, 256, SM_DOWN>>>(
            hin, W1H + (size_t)i * 8192, W1L + (size_t)i * 8192,
            nullptr, nullptr, nullptr, T16);
        k_conv_mma<<<NBLK128, 256, CONV_SMEM>>>(
            T16, WtH + (size_t)i * 27 * 4096, WtL + (size_t)i * 27 * 4096,
            nbr, T2);
        k_lin<64, 128, 1><<<NBLK128, 256, SM_UP>>>(
            T2, W2H + (size_t)i * 8192, W2L + (size_t)i * 8192,
            hin, nullptr, hout, nullptr);
    }
    k_lin<128, 128, 2><<<NBLK128, 256, SM_FINAL>>>(
        B, WfH, WfL, A, x, out, nullptr);
}

// round 6
// speedup vs baseline: 2.6213x; 1.0868x over previous
#include <cuda_runtime.h>
#include <cuda_bf16.h>
#include <cuda_fp16.h>
#include <cstdint>

#define NPTS 120000
#define NBLK64 1875
#define NBLK128 938   // ceil(120000/128)

// ---------------- scratch (device globals: allocation-free) ----------------
__device__ float g_A[NPTS * 128];
__device__ float g_B[NPTS * 128];
__device__ float g_T2[NPTS * 64];
__device__ __half g_T16[NPTS * 64];                 // conv input activations (fp16)
__device__ __half g_WtH[6 * 27 * 64 * 64];          // conv weights [u][k][j][c] fp16 hi
__device__ __half g_WtL[6 * 27 * 64 * 64];          // fp16 lo residual
__device__ __nv_bfloat16 g_W1H[6 * 64 * 128];       // down weights [u][n][k]
__device__ __nv_bfloat16 g_W1L[6 * 64 * 128];
__device__ __nv_bfloat16 g_W2H[6 * 128 * 64];       // up weights [u][n][k]
__device__ __nv_bfloat16 g_W2L[6 * 128 * 64];
__device__ __nv_bfloat16 g_WfH[128 * 128];          // final weights [n][k]
__device__ __nv_bfloat16 g_WfL[128 * 128];

// ---------------- helpers ---------------------------------------------------
__device__ __forceinline__ uint32_t smem_u32(const void* p) {
    uint32_t a;
    asm("{ .reg .u64 t; cvta.to.shared.u64 t, %1; cvt.u32.u64 %0, t; }"
        : "=r"(a) : "l"(p));
    return a;
}
__device__ __forceinline__ void ldsm_x4(uint32_t (&r)[4], uint32_t addr) {
    asm volatile("ldmatrix.sync.aligned.m8n8.x4.shared.b16 {%0,%1,%2,%3}, [%4];"
                 : "=r"(r[0]), "=r"(r[1]), "=r"(r[2]), "=r"(r[3]) : "r"(addr));
}
__device__ __forceinline__ void ldsm_x2(uint32_t (&r)[2], uint32_t addr) {
    asm volatile("ldmatrix.sync.aligned.m8n8.x2.shared.b16 {%0,%1}, [%2];"
                 : "=r"(r[0]), "=r"(r[1]) : "r"(addr));
}
__device__ __forceinline__ void mma_bf16(float* c, const uint32_t* a,
                                         const uint32_t* b) {
    asm volatile(
        "mma.sync.aligned.m16n8k16.row.col.f32.bf16.bf16.f32 "
        "{%0,%1,%2,%3}, {%4,%5,%6,%7}, {%8,%9}, {%0,%1,%2,%3};"
        : "+f"(c[0]), "+f"(c[1]), "+f"(c[2]), "+f"(c[3])
        : "r"(a[0]), "r"(a[1]), "r"(a[2]), "r"(a[3]), "r"(b[0]), "r"(b[1]));
}
__device__ __forceinline__ void mma_f16(float* c, const uint32_t* a,
                                        uint32_t b0, uint32_t b1) {
    asm volatile(
        "mma.sync.aligned.m16n8k16.row.col.f32.f16.f16.f32 "
        "{%0,%1,%2,%3}, {%4,%5,%6,%7}, {%8,%9}, {%0,%1,%2,%3};"
        : "+f"(c[0]), "+f"(c[1]), "+f"(c[2]), "+f"(c[3])
        : "r"(a[0]), "r"(a[1]), "r"(a[2]), "r"(a[3]), "r"(b0), "r"(b1));
}
__device__ __forceinline__ unsigned pack_bf2(__nv_bfloat16 a, __nv_bfloat16 b) {
    __nv_bfloat162 t; t.x = a; t.y = b;
    return *reinterpret_cast<unsigned*>(&t);
}
__device__ __forceinline__ void split2(float x, float y, unsigned& h, unsigned& l) {
    __nv_bfloat16 hx = __float2bfloat16(x);
    __nv_bfloat16 hy = __float2bfloat16(y);
    float rx = x - __bfloat162float(hx);
    float ry = y - __bfloat162float(hy);
    h = pack_bf2(hx, hy);
    l = pack_bf2(__float2bfloat16(rx), __float2bfloat16(ry));
}

// ---------------------------------------------------------------------------
// conv weight split+transpose: Wt[u][k][j][c] = Wk[u][k][c][j] as fp16 hi/lo
// ---------------------------------------------------------------------------
__global__ void k_wsplit(const float* __restrict__ Wks,
                         __half* __restrict__ WtH,
                         __half* __restrict__ WtL) {
    int k = blockIdx.x, u = blockIdx.y;
    const float* src = Wks + ((size_t)u * 27 + k) * 4096;
    __half* dh = WtH + ((size_t)u * 27 + k) * 4096;
    __half* dl = WtL + ((size_t)u * 27 + k) * 4096;
    for (int e = threadIdx.x; e < 4096; e += blockDim.x) {
        int c = e >> 6, j = e & 63;
        float v = src[c * 64 + j];
        __half h = __float2half(v);
        float r = v - __half2float(h);
        dh[j * 64 + c] = h;
        dl[j * 64 + c] = __float2half(r);
    }
}

// ---------------------------------------------------------------------------
// linear weight split+transpose: [k][n] fp32 -> [n][k] bf16 hi/lo
// ---------------------------------------------------------------------------
__global__ void k_wsplit_lin(const float* __restrict__ W1s,
                             const float* __restrict__ W2s,
                             const float* __restrict__ Wf,
                             __nv_bfloat16* __restrict__ W1H, __nv_bfloat16* __restrict__ W1L,
                             __nv_bfloat16* __restrict__ W2H, __nv_bfloat16* __restrict__ W2L,
                             __nv_bfloat16* __restrict__ WfH, __nv_bfloat16* __restrict__ WfL) {
    int b = blockIdx.x;
    if (b < 6) {
        const float* s = W1s + (size_t)b * 8192;
        __nv_bfloat16* dh = W1H + (size_t)b * 8192;
        __nv_bfloat16* dl = W1L + (size_t)b * 8192;
        for (int e = threadIdx.x; e < 8192; e += blockDim.x) {
            int k = e >> 6, n = e & 63;
            float v = s[e];
            __nv_bfloat16 h = __float2bfloat16(v);
            dh[n * 128 + k] = h;
            dl[n * 128 + k] = __float2bfloat16(v - __bfloat162float(h));
        }
    } else if (b < 12) {
        const float* s = W2s + (size_t)(b - 6) * 8192;
        __nv_bfloat16* dh = W2H + (size_t)(b - 6) * 8192;
        __nv_bfloat16* dl = W2L + (size_t)(b - 6) * 8192;
        for (int e = threadIdx.x; e < 8192; e += blockDim.x) {
            int k = e >> 7, n = e & 127;
            float v = s[e];
            __nv_bfloat16 h = __float2bfloat16(v);
            dh[n * 64 + k] = h;
            dl[n * 64 + k] = __float2bfloat16(v - __bfloat162float(h));
        }
    } else {
        for (int e = threadIdx.x; e < 16384; e += blockDim.x) {
            int k = e >> 7, n = e & 127;
            float v = Wf[e];
            __nv_bfloat16 h = __float2bfloat16(v);
            WfH[n * 128 + k] = h;
            WfL[n * 128 + k] = __float2bfloat16(v - __bfloat162float(h));
        }
    }
}

// ---------------------------------------------------------------------------
// HMMA 1x1 layer, M=64 tiles (no bounds checks; NPTS % 64 == 0), 2 CTAs/SM.
// C[64, N] = act( in[64, K] @ W[N,K]^T ... ), bf16 3-product split.
// 8 warps: wm in {0,1} (32 rows), wn in {0..3} (N/4 cols).
// EPI 0: relu -> fp16 plane (out16, stride 64)
// EPI 1: relu(acc + res) -> fp32 (stride 128)
// EPI 2: res * sigmoid(acc) + xres -> fp32 (stride 128)
// ---------------------------------------------------------------------------
template <int K, int N, int EPI>
__global__ __launch_bounds__(256, 2) void k_lin(
    const float* __restrict__ in,
    const __nv_bfloat16* __restrict__ BH, const __nv_bfloat16* __restrict__ BL,
    const float* __restrict__ res, const float* __restrict__ xres,
    float* __restrict__ fout, __half* __restrict__ out16)
{
    constexpr int SB   = K * 2 + 16;          // smem row stride bytes
    constexpr int ASZ  = 64 * SB;             // one A plane
    constexpr int BOFF = 2 * ASZ;
    constexpr int NTW  = N / 4;               // cols per warp
    constexpr int NT   = NTW / 8;             // n8 tiles per warp
    constexpr int KS   = K / 16;

    extern __shared__ char sm[];
    const uint32_t su = smem_u32(sm);
    const int tid  = threadIdx.x;
    const int lane = tid & 31;
    const int w    = tid >> 5;
    const int wm   = w & 1;
    const int wn   = w >> 1;
    const int mbase = wm * 32;
    const int p0   = blockIdx.x * 64;

    // stage A (fp32 -> hi/lo bf16): 4 threads per row, K/4 floats each
    {
        int row = tid >> 2, q = tid & 3;
        const float* src = in + (size_t)(p0 + row) * K + q * (K / 4);
        char* ah = sm + row * SB + q * (K / 2);
        char* al = sm + ASZ + row * SB + q * (K / 2);
#pragma unroll
        for (int c = 0; c < K / 4; c += 8) {
            float4 f0 = *(const float4*)(src + c);
            float4 f1 = *(const float4*)(src + c + 4);
            unsigned h0, h1, h2, h3, l0, l1, l2, l3;
            split2(f0.x, f0.y, h0, l0);
            split2(f0.z, f0.w, h1, l1);
            split2(f1.x, f1.y, h2, l2);
            split2(f1.z, f1.w, h3, l3);
            *(uint4*)(ah + c * 2) = make_uint4(h0, h1, h2, h3);
            *(uint4*)(al + c * 2) = make_uint4(l0, l1, l2, l3);
        }
    }
    // stage B (pre-split bf16)
    {
        constexpr int ITER = N * K / 1024;
        int plane = tid >> 7, t = tid & 127;
        const __nv_bfloat16* bs = plane ? BL : BH;
        char* bd = sm + BOFF + plane * (N * SB);
#pragma unroll
        for (int i = 0; i < ITER; i++) {
            int j = t + i * 128;
            int e = j * 8;
            int r = e / K, c = e % K;
            *(uint4*)(bd + r * SB + c * 2) = *(const uint4*)(bs + e);
        }
    }
    __syncthreads();

    float acc[2][NT][4];
#pragma unroll
    for (int mt = 0; mt < 2; mt++)
#pragma unroll
        for (int nt = 0; nt < NT; nt++)
#pragma unroll
            for (int e = 0; e < 4; e++) acc[mt][nt][e] = 0.f;

    const uint32_t a_ld = su + (uint32_t)(mbase + (lane & 15)) * SB
                        + (uint32_t)(lane >> 4) * 16;
    const uint32_t b_ld = su + BOFF + (uint32_t)(wn * NTW + (lane & 7)) * SB
                        + (uint32_t)((lane >> 3) & 1) * 16;

#pragma unroll
    for (int ks = 0; ks < KS; ks++) {
        uint32_t ah[2][4], al[2][4];
#pragma unroll
        for (int mt = 0; mt < 2; mt++) {
            ldsm_x4(ah[mt], a_ld + (uint32_t)mt * (16 * SB) + ks * 32);
            ldsm_x4(al[mt], a_ld + ASZ + (uint32_t)mt * (16 * SB) + ks * 32);
        }
#pragma unroll
        for (int nt = 0; nt < NT; nt++) {
            uint32_t bh[2], bl[2];
            ldsm_x2(bh, b_ld + (uint32_t)nt * (8 * SB) + ks * 32);
            ldsm_x2(bl, b_ld + (uint32_t)(N * SB) + (uint32_t)nt * (8 * SB) + ks * 32);
#pragma unroll
            for (int mt = 0; mt < 2; mt++) {
                mma_bf16(acc[mt][nt], ah[mt], bh);
                mma_bf16(acc[mt][nt], ah[mt], bl);
                mma_bf16(acc[mt][nt], al[mt], bh);
            }
        }
    }

    const int g = lane >> 2, tg = lane & 3;
#pragma unroll
    for (int mt = 0; mt < 2; mt++) {
        int r0 = p0 + mbase + mt * 16 + g;
#pragma unroll
        for (int nt = 0; nt < NT; nt++) {
            int col = wn * NTW + nt * 8 + tg * 2;
            float c0 = acc[mt][nt][0], c1 = acc[mt][nt][1];
            float c2 = acc[mt][nt][2], c3 = acc[mt][nt][3];
            if (EPI == 0) {
                __half2 o0 = __floats2half2_rn(fmaxf(c0, 0.f), fmaxf(c1, 0.f));
                __half2 o1 = __floats2half2_rn(fmaxf(c2, 0.f), fmaxf(c3, 0.f));
                *(__half2*)(out16 + (size_t)r0 * 64 + col) = o0;
                *(__half2*)(out16 + (size_t)(r0 + 8) * 64 + col) = o1;
            } else if (EPI == 1) {
                float2 ra = *(const float2*)(res + (size_t)r0 * 128 + col);
                float2 rb = *(const float2*)(res + (size_t)(r0 + 8) * 128 + col);
                float2 o0, o1;
                o0.x = fmaxf(c0 + ra.x, 0.f); o0.y = fmaxf(c1 + ra.y, 0.f);
                o1.x = fmaxf(c2 + rb.x, 0.f); o1.y = fmaxf(c3 + rb.y, 0.f);
                *(float2*)(fout + (size_t)r0 * 128 + col) = o0;
                *(float2*)(fout + (size_t)(r0 + 8) * 128 + col) = o1;
            } else {
                float2 aa = *(const float2*)(res  + (size_t)r0 * 128 + col);
                float2 xa = *(const float2*)(xres + (size_t)r0 * 128 + col);
                float2 ab = *(const float2*)(res  + (size_t)(r0 + 8) * 128 + col);
                float2 xb = *(const float2*)(xres + (size_t)(r0 + 8) * 128 + col);
                float2 o0, o1;
                o0.x = aa.x / (1.f + __expf(-c0)) + xa.x;
                o0.y = aa.y / (1.f + __expf(-c1)) + xa.y;
                o1.x = ab.x / (1.f + __expf(-c2)) + xb.x;
                o1.y = ab.y / (1.f + __expf(-c3)) + xb.y;
                *(float2*)(fout + (size_t)r0 * 128 + col) = o0;
                *(float2*)(fout + (size_t)(r0 + 8) * 128 + col) = o1;
            }
        }
    }
}

// ---------------------------------------------------------------------------
// fp16 HMMA conv, 2-product split, DOUBLE-BUFFERED stages (1 sync per tap).
// CTA: 128 pts x 64 out-ch, 8 warps (4Mx2N), fp32 acc.
// Per stage (36864B): A @+0 (128*144), Bhi @+18432, Blo @+27648.
// Stage 0 @0, stage 1 @36864, idx @73728 (13824) -> 87552 total, 2 CTAs/SM.
// ---------------------------------------------------------------------------
#define STAGE_SZ 36864
#define ASTRIDE 144
#define B_HI 18432
#define B_LO 27648
#define IDX_OFF 73728
#define CONV_SMEM (IDX_OFF + 13824)

__global__ __launch_bounds__(256, 2) void k_conv_mma(
    const __half* __restrict__ T16,
    const __half* __restrict__ WtH, const __half* __restrict__ WtL,
    const int* __restrict__ nbr, float* __restrict__ out)
{
    extern __shared__ char sm[];
    const int tid  = threadIdx.x;
    const int lane = tid & 31;
    const int w    = tid >> 5;
    const int wm   = w & 3;
    const int wn   = w >> 2;
    const int p0   = blockIdx.x * 128;

    const uint32_t su = smem_u32(sm);
    int* idxs = (int*)(sm + IDX_OFF);

    for (int i = tid; i < 27 * 128; i += 256) {
        int p = i / 27;
        int k = i - p * 27;
        int gp = p0 + p;
        idxs[k * 128 + p] = (gp < NPTS) ? nbr[(size_t)gp * 27 + k] : -1;
    }

    float acc[2][4][4];
#pragma unroll
    for (int mt = 0; mt < 2; mt++)
#pragma unroll
        for (int nt = 0; nt < 4; nt++)
#pragma unroll
            for (int e = 0; e < 4; e++) acc[mt][nt][e] = 0.f;

    const int pr    = tid >> 1;
    const int ahalf = tid & 1;
    const uint32_t a_dst = (uint32_t)pr * ASTRIDE + (uint32_t)ahalf * 64;
    const int bplane = tid >> 7;
    const int brow   = (tid & 127) >> 1;
    const uint32_t b_dst = (uint32_t)(B_HI + bplane * 9216)
                         + (uint32_t)brow * ASTRIDE + (uint32_t)ahalf * 64;

    const uint32_t a_ld0 = su + (uint32_t)(wm * 32 + (lane & 15)) * ASTRIDE
                         + (uint32_t)(lane >> 4) * 16;
    const uint32_t b_ld0 = su + B_HI + (uint32_t)(wn * 32 + (lane & 15)) * ASTRIDE
                         + (uint32_t)(lane >> 4) * 16;

    __syncthreads();   // idxs visible

    uint4 av[4], wv[4];
    // prefetch + stage tap 0 into buffer 0
    {
        int row = idxs[pr];
        if (row >= 0) {
            const uint4* s1 = (const uint4*)(T16 + (size_t)row * 64 + ahalf * 32);
#pragma unroll
            for (int i = 0; i < 4; i++) av[i] = s1[i];
        } else {
            uint4 z = make_uint4(0, 0, 0, 0);
#pragma unroll
            for (int i = 0; i < 4; i++) av[i] = z;
        }
        const uint4* ws = (const uint4*)((bplane ? WtL : WtH)
                          + (size_t)brow * 64 + ahalf * 32);
#pragma unroll
        for (int i = 0; i < 4; i++) wv[i] = ws[i];
        char* Ad = sm + a_dst;
        char* Bd = sm + b_dst;
#pragma unroll
        for (int i = 0; i < 4; i++) {
            *(uint4*)(Ad + i * 16) = av[i];
            *(uint4*)(Bd + i * 16) = wv[i];
        }
    }
    __syncthreads();

    for (int k = 0; k < 27; k++) {
        const uint32_t sb = (uint32_t)(k & 1) * STAGE_SZ;

        // issue LDG prefetch for tap k+1 (hides behind MMA below)
        if (k < 26) {
            int row = idxs[(k + 1) * 128 + pr];
            if (row >= 0) {
                const uint4* s1 = (const uint4*)(T16 + (size_t)row * 64 + ahalf * 32);
#pragma unroll
                for (int i = 0; i < 4; i++) av[i] = s1[i];
            } else {
                uint4 z = make_uint4(0, 0, 0, 0);
#pragma unroll
                for (int i = 0; i < 4; i++) av[i] = z;
            }
            const uint4* ws = (const uint4*)((bplane ? WtL : WtH)
                              + ((size_t)(k + 1) * 64 + brow) * 64 + ahalf * 32);
#pragma unroll
            for (int i = 0; i < 4; i++) wv[i] = ws[i];
        }

        // MMA over K=64 from buffer k&1
        const uint32_t a_ld = a_ld0 + sb;
        const uint32_t b_ld = b_ld0 + sb;
#pragma unroll
        for (int ks = 0; ks < 4; ks++) {
            uint32_t a0[4], a1[4];
            ldsm_x4(a0, a_ld + ks * 32);
            ldsm_x4(a1, a_ld + 16 * ASTRIDE + ks * 32);
#pragma unroll
            for (int nt2 = 0; nt2 < 2; nt2++) {
                uint32_t bh[4], bl[4];
                ldsm_x4(bh, b_ld + (uint32_t)nt2 * (16 * ASTRIDE) + ks * 32);
                ldsm_x4(bl, b_ld + 9216 + (uint32_t)nt2 * (16 * ASTRIDE) + ks * 32);
                mma_f16(acc[0][nt2 * 2 + 0], a0, bh[0], bh[2]);
                mma_f16(acc[0][nt2 * 2 + 0], a0, bl[0], bl[2]);
                mma_f16(acc[0][nt2 * 2 + 1], a0, bh[1], bh[3]);
                mma_f16(acc[0][nt2 * 2 + 1], a0, bl[1], bl[3]);
                mma_f16(acc[1][nt2 * 2 + 0], a1, bh[0], bh[2]);
                mma_f16(acc[1][nt2 * 2 + 0], a1, bl[0], bl[2]);
                mma_f16(acc[1][nt2 * 2 + 1], a1, bh[1], bh[3]);
                mma_f16(acc[1][nt2 * 2 + 1], a1, bl[1], bl[3]);
            }
        }

        // store tap k+1 into the other buffer; 1 sync per tap
        if (k < 26) {
            const uint32_t sb1 = (uint32_t)((k + 1) & 1) * STAGE_SZ;
            char* Ad = sm + sb1 + a_dst;
            char* Bd = sm + sb1 + b_dst;
#pragma unroll
            for (int i = 0; i < 4; i++) {
                *(uint4*)(Ad + i * 16) = av[i];
                *(uint4*)(Bd + i * 16) = wv[i];
            }
            __syncthreads();
        }
    }

    // epilogue: relu + fp32 store
    const int g = lane >> 2, tg = lane & 3;
#pragma unroll
    for (int mt = 0; mt < 2; mt++) {
        int row0 = p0 + wm * 32 + mt * 16 + g;
#pragma unroll
        for (int nt = 0; nt < 4; nt++) {
            int col = wn * 32 + nt * 8 + tg * 2;
            if (row0 < NPTS) {
                float2 o;
                o.x = fmaxf(acc[mt][nt][0], 0.f);
                o.y = fmaxf(acc[mt][nt][1], 0.f);
                *(float2*)(out + (size_t)row0 * 64 + col) = o;
            }
            if (row0 + 8 < NPTS) {
                float2 o;
                o.x = fmaxf(acc[mt][nt][2], 0.f);
                o.y = fmaxf(acc[mt][nt][3], 0.f);
                *(float2*)(out + (size_t)(row0 + 8) * 64 + col) = o;
            }
        }
    }
}

// ---------------------------------------------------------------------------
extern "C" void kernel_launch(void* const* d_in, const int* in_sizes, int n_in,
                              void* d_out, int out_size)
{
    const float* x   = (const float*)d_in[0];
    const float* W1s = (const float*)d_in[1];
    const float* Wks = (const float*)d_in[2];
    const float* W2s = (const float*)d_in[3];
    const float* Wf  = (const float*)d_in[4];
    const int*   nbr = (const int*)d_in[5];
    float* out = (float*)d_out;

    float *A, *B, *T2;
    __half *T16, *WtH, *WtL;
    __nv_bfloat16 *W1H, *W1L, *W2H, *W2L, *WfH, *WfL;
    cudaGetSymbolAddress((void**)&A,   g_A);
    cudaGetSymbolAddress((void**)&B,   g_B);
    cudaGetSymbolAddress((void**)&T2,  g_T2);
    cudaGetSymbolAddress((void**)&T16, g_T16);
    cudaGetSymbolAddress((void**)&WtH, g_WtH);
    cudaGetSymbolAddress((void**)&WtL, g_WtL);
    cudaGetSymbolAddress((void**)&W1H, g_W1H);
    cudaGetSymbolAddress((void**)&W1L, g_W1L);
    cudaGetSymbolAddress((void**)&W2H, g_W2H);
    cudaGetSymbolAddress((void**)&W2L, g_W2L);
    cudaGetSymbolAddress((void**)&WfH, g_WfH);
    cudaGetSymbolAddress((void**)&WfL, g_WfL);

    constexpr int SM_DOWN  = (128 * 2 + 16) * (128 + 2 * 64);   // 69632
    constexpr int SM_UP    = (64 * 2 + 16) * (128 + 2 * 128);   // 55296
    constexpr int SM_FINAL = (128 * 2 + 16) * (128 + 2 * 128);  // 104448

    cudaFuncSetAttribute(k_conv_mma, cudaFuncAttributeMaxDynamicSharedMemorySize,
                         CONV_SMEM);
    cudaFuncSetAttribute((const void*)k_lin<128, 64, 0>,
                         cudaFuncAttributeMaxDynamicSharedMemorySize, SM_DOWN);
    cudaFuncSetAttribute((const void*)k_lin<64, 128, 1>,
                         cudaFuncAttributeMaxDynamicSharedMemorySize, SM_UP);
    cudaFuncSetAttribute((const void*)k_lin<128, 128, 2>,
                         cudaFuncAttributeMaxDynamicSharedMemorySize, SM_FINAL);

    k_wsplit<<<dim3(27, 6), 256>>>(Wks, WtH, WtL);
    k_wsplit_lin<<<13, 256>>>(W1s, W2s, Wf, W1H, W1L, W2H, W2L, WfH, WfL);

    for (int i = 0; i < 6; i++) {
        const float* hin = (i == 0 || i == 3) ? x : ((i < 3) ? A : B);
        float* hout = (i < 3) ? A : B;
        k_lin<128, 64, 0><<<NBLK64, 256, SM_DOWN>>>(
            hin, W1H + (size_t)i * 8192, W1L + (size_t)i * 8192,
            nullptr, nullptr, nullptr, T16);
        k_conv_mma<<<NBLK128, 256, CONV_SMEM>>>(
            T16, WtH + (size_t)i * 27 * 4096, WtL + (size_t)i * 27 * 4096,
            nbr, T2);
        k_lin<64, 128, 1><<<NBLK64, 256, SM_UP>>>(
            T2, W2H + (size_t)i * 8192, W2L + (size_t)i * 8192,
            hin, nullptr, hout, nullptr);
    }
    k_lin<128, 128, 2><<<NBLK64, 256, SM_FINAL>>>(
        B, WfH, WfL, A, x, out, nullptr);
}

// round 7
// speedup vs baseline: 2.7913x; 1.0649x over previous
#include <cuda_runtime.h>
#include <cuda_bf16.h>
#include <cuda_fp16.h>
#include <cstdint>

#define NPTS 120000
#define NBLK64 1875
#define NBLK256 469   // ceil(120000/256)

// ---------------- scratch (device globals: allocation-free) ----------------
__device__ float g_A[NPTS * 128];
__device__ float g_B[NPTS * 128];
__device__ float g_T2[NPTS * 64];
__device__ __half g_T16[NPTS * 64];                 // conv input activations (fp16)
__device__ __half g_WtH[6 * 27 * 64 * 64];          // conv weights [u][k][j][c] fp16 hi
__device__ __half g_WtL[6 * 27 * 64 * 64];          // fp16 lo residual
__device__ __nv_bfloat16 g_W1H[6 * 64 * 128];       // down weights [u][n][k]
__device__ __nv_bfloat16 g_W1L[6 * 64 * 128];
__device__ __nv_bfloat16 g_W2H[6 * 128 * 64];       // up weights [u][n][k]
__device__ __nv_bfloat16 g_W2L[6 * 128 * 64];
__device__ __nv_bfloat16 g_WfH[128 * 128];          // final weights [n][k]
__device__ __nv_bfloat16 g_WfL[128 * 128];

// ---------------- helpers ---------------------------------------------------
__device__ __forceinline__ uint32_t smem_u32(const void* p) {
    uint32_t a;
    asm("{ .reg .u64 t; cvta.to.shared.u64 t, %1; cvt.u32.u64 %0, t; }"
        : "=r"(a) : "l"(p));
    return a;
}
__device__ __forceinline__ void ldsm_x4(uint32_t (&r)[4], uint32_t addr) {
    asm volatile("ldmatrix.sync.aligned.m8n8.x4.shared.b16 {%0,%1,%2,%3}, [%4];"
                 : "=r"(r[0]), "=r"(r[1]), "=r"(r[2]), "=r"(r[3]) : "r"(addr));
}
__device__ __forceinline__ void ldsm_x2(uint32_t (&r)[2], uint32_t addr) {
    asm volatile("ldmatrix.sync.aligned.m8n8.x2.shared.b16 {%0,%1}, [%2];"
                 : "=r"(r[0]), "=r"(r[1]) : "r"(addr));
}
__device__ __forceinline__ void mma_bf16(float* c, const uint32_t* a,
                                         const uint32_t* b) {
    asm volatile(
        "mma.sync.aligned.m16n8k16.row.col.f32.bf16.bf16.f32 "
        "{%0,%1,%2,%3}, {%4,%5,%6,%7}, {%8,%9}, {%0,%1,%2,%3};"
        : "+f"(c[0]), "+f"(c[1]), "+f"(c[2]), "+f"(c[3])
        : "r"(a[0]), "r"(a[1]), "r"(a[2]), "r"(a[3]), "r"(b[0]), "r"(b[1]));
}
__device__ __forceinline__ void mma_f16(float* c, const uint32_t* a,
                                        uint32_t b0, uint32_t b1) {
    asm volatile(
        "mma.sync.aligned.m16n8k16.row.col.f32.f16.f16.f32 "
        "{%0,%1,%2,%3}, {%4,%5,%6,%7}, {%8,%9}, {%0,%1,%2,%3};"
        : "+f"(c[0]), "+f"(c[1]), "+f"(c[2]), "+f"(c[3])
        : "r"(a[0]), "r"(a[1]), "r"(a[2]), "r"(a[3]), "r"(b0), "r"(b1));
}
__device__ __forceinline__ void cp_async16(uint32_t dst, const void* src,
                                           uint32_t src_size) {
    asm volatile("cp.async.ca.shared.global [%0], [%1], 16, %2;"
                 :: "r"(dst), "l"(src), "r"(src_size) : "memory");
}
__device__ __forceinline__ void cp_commit() {
    asm volatile("cp.async.commit_group;" ::: "memory");
}
__device__ __forceinline__ void cp_wait0() {
    asm volatile("cp.async.wait_group 0;" ::: "memory");
}
__device__ __forceinline__ unsigned pack_bf2(__nv_bfloat16 a, __nv_bfloat16 b) {
    __nv_bfloat162 t; t.x = a; t.y = b;
    return *reinterpret_cast<unsigned*>(&t);
}
__device__ __forceinline__ void split2(float x, float y, unsigned& h, unsigned& l) {
    __nv_bfloat16 hx = __float2bfloat16(x);
    __nv_bfloat16 hy = __float2bfloat16(y);
    float rx = x - __bfloat162float(hx);
    float ry = y - __bfloat162float(hy);
    h = pack_bf2(hx, hy);
    l = pack_bf2(__float2bfloat16(rx), __float2bfloat16(ry));
}

// ---------------------------------------------------------------------------
// conv weight split+transpose: Wt[u][k][j][c] = Wk[u][k][c][j] as fp16 hi/lo
// ---------------------------------------------------------------------------
__global__ void k_wsplit(const float* __restrict__ Wks,
                         __half* __restrict__ WtH,
                         __half* __restrict__ WtL) {
    int k = blockIdx.x, u = blockIdx.y;
    const float* src = Wks + ((size_t)u * 27 + k) * 4096;
    __half* dh = WtH + ((size_t)u * 27 + k) * 4096;
    __half* dl = WtL + ((size_t)u * 27 + k) * 4096;
    for (int e = threadIdx.x; e < 4096; e += blockDim.x) {
        int c = e >> 6, j = e & 63;
        float v = src[c * 64 + j];
        __half h = __float2half(v);
        float r = v - __half2float(h);
        dh[j * 64 + c] = h;
        dl[j * 64 + c] = __float2half(r);
    }
}

// ---------------------------------------------------------------------------
// linear weight split+transpose: [k][n] fp32 -> [n][k] bf16 hi/lo
// ---------------------------------------------------------------------------
__global__ void k_wsplit_lin(const float* __restrict__ W1s,
                             const float* __restrict__ W2s,
                             const float* __restrict__ Wf,
                             __nv_bfloat16* __restrict__ W1H, __nv_bfloat16* __restrict__ W1L,
                             __nv_bfloat16* __restrict__ W2H, __nv_bfloat16* __restrict__ W2L,
                             __nv_bfloat16* __restrict__ WfH, __nv_bfloat16* __restrict__ WfL) {
    int b = blockIdx.x;
    if (b < 6) {
        const float* s = W1s + (size_t)b * 8192;
        __nv_bfloat16* dh = W1H + (size_t)b * 8192;
        __nv_bfloat16* dl = W1L + (size_t)b * 8192;
        for (int e = threadIdx.x; e < 8192; e += blockDim.x) {
            int k = e >> 6, n = e & 63;
            float v = s[e];
            __nv_bfloat16 h = __float2bfloat16(v);
            dh[n * 128 + k] = h;
            dl[n * 128 + k] = __float2bfloat16(v - __bfloat162float(h));
        }
    } else if (b < 12) {
        const float* s = W2s + (size_t)(b - 6) * 8192;
        __nv_bfloat16* dh = W2H + (size_t)(b - 6) * 8192;
        __nv_bfloat16* dl = W2L + (size_t)(b - 6) * 8192;
        for (int e = threadIdx.x; e < 8192; e += blockDim.x) {
            int k = e >> 7, n = e & 127;
            float v = s[e];
            __nv_bfloat16 h = __float2bfloat16(v);
            dh[n * 64 + k] = h;
            dl[n * 64 + k] = __float2bfloat16(v - __bfloat162float(h));
        }
    } else {
        for (int e = threadIdx.x; e < 16384; e += blockDim.x) {
            int k = e >> 7, n = e & 127;
            float v = Wf[e];
            __nv_bfloat16 h = __float2bfloat16(v);
            WfH[n * 128 + k] = h;
            WfL[n * 128 + k] = __float2bfloat16(v - __bfloat162float(h));
        }
    }
}

// ---------------------------------------------------------------------------
// HMMA 1x1 layer, M=64 tiles, 2 CTAs/SM  (unchanged from round 6 — proven)
// ---------------------------------------------------------------------------
template <int K, int N, int EPI>
__global__ __launch_bounds__(256, 2) void k_lin(
    const float* __restrict__ in,
    const __nv_bfloat16* __restrict__ BH, const __nv_bfloat16* __restrict__ BL,
    const float* __restrict__ res, const float* __restrict__ xres,
    float* __restrict__ fout, __half* __restrict__ out16)
{
    constexpr int SB   = K * 2 + 16;
    constexpr int ASZ  = 64 * SB;
    constexpr int BOFF = 2 * ASZ;
    constexpr int NTW  = N / 4;
    constexpr int NT   = NTW / 8;
    constexpr int KS   = K / 16;

    extern __shared__ char sm[];
    const uint32_t su = smem_u32(sm);
    const int tid  = threadIdx.x;
    const int lane = tid & 31;
    const int w    = tid >> 5;
    const int wm   = w & 1;
    const int wn   = w >> 1;
    const int mbase = wm * 32;
    const int p0   = blockIdx.x * 64;

    {
        int row = tid >> 2, q = tid & 3;
        const float* src = in + (size_t)(p0 + row) * K + q * (K / 4);
        char* ah = sm + row * SB + q * (K / 2);
        char* al = sm + ASZ + row * SB + q * (K / 2);
#pragma unroll
        for (int c = 0; c < K / 4; c += 8) {
            float4 f0 = *(const float4*)(src + c);
            float4 f1 = *(const float4*)(src + c + 4);
            unsigned h0, h1, h2, h3, l0, l1, l2, l3;
            split2(f0.x, f0.y, h0, l0);
            split2(f0.z, f0.w, h1, l1);
            split2(f1.x, f1.y, h2, l2);
            split2(f1.z, f1.w, h3, l3);
            *(uint4*)(ah + c * 2) = make_uint4(h0, h1, h2, h3);
            *(uint4*)(al + c * 2) = make_uint4(l0, l1, l2, l3);
        }
    }
    {
        constexpr int ITER = N * K / 1024;
        int plane = tid >> 7, t = tid & 127;
        const __nv_bfloat16* bs = plane ? BL : BH;
        char* bd = sm + BOFF + plane * (N * SB);
#pragma unroll
        for (int i = 0; i < ITER; i++) {
            int j = t + i * 128;
            int e = j * 8;
            int r = e / K, c = e % K;
            *(uint4*)(bd + r * SB + c * 2) = *(const uint4*)(bs + e);
        }
    }
    __syncthreads();

    float acc[2][NT][4];
#pragma unroll
    for (int mt = 0; mt < 2; mt++)
#pragma unroll
        for (int nt = 0; nt < NT; nt++)
#pragma unroll
            for (int e = 0; e < 4; e++) acc[mt][nt][e] = 0.f;

    const uint32_t a_ld = su + (uint32_t)(mbase + (lane & 15)) * SB
                        + (uint32_t)(lane >> 4) * 16;
    const uint32_t b_ld = su + BOFF + (uint32_t)(wn * NTW + (lane & 7)) * SB
                        + (uint32_t)((lane >> 3) & 1) * 16;

#pragma unroll
    for (int ks = 0; ks < KS; ks++) {
        uint32_t ah[2][4], al[2][4];
#pragma unroll
        for (int mt = 0; mt < 2; mt++) {
            ldsm_x4(ah[mt], a_ld + (uint32_t)mt * (16 * SB) + ks * 32);
            ldsm_x4(al[mt], a_ld + ASZ + (uint32_t)mt * (16 * SB) + ks * 32);
        }
#pragma unroll
        for (int nt = 0; nt < NT; nt++) {
            uint32_t bh[2], bl[2];
            ldsm_x2(bh, b_ld + (uint32_t)nt * (8 * SB) + ks * 32);
            ldsm_x2(bl, b_ld + (uint32_t)(N * SB) + (uint32_t)nt * (8 * SB) + ks * 32);
#pragma unroll
            for (int mt = 0; mt < 2; mt++) {
                mma_bf16(acc[mt][nt], ah[mt], bh);
                mma_bf16(acc[mt][nt], ah[mt], bl);
                mma_bf16(acc[mt][nt], al[mt], bh);
            }
        }
    }

    const int g = lane >> 2, tg = lane & 3;
#pragma unroll
    for (int mt = 0; mt < 2; mt++) {
        int r0 = p0 + mbase + mt * 16 + g;
#pragma unroll
        for (int nt = 0; nt < NT; nt++) {
            int col = wn * NTW + nt * 8 + tg * 2;
            float c0 = acc[mt][nt][0], c1 = acc[mt][nt][1];
            float c2 = acc[mt][nt][2], c3 = acc[mt][nt][3];
            if (EPI == 0) {
                __half2 o0 = __floats2half2_rn(fmaxf(c0, 0.f), fmaxf(c1, 0.f));
                __half2 o1 = __floats2half2_rn(fmaxf(c2, 0.f), fmaxf(c3, 0.f));
                *(__half2*)(out16 + (size_t)r0 * 64 + col) = o0;
                *(__half2*)(out16 + (size_t)(r0 + 8) * 64 + col) = o1;
            } else if (EPI == 1) {
                float2 ra = *(const float2*)(res + (size_t)r0 * 128 + col);
                float2 rb = *(const float2*)(res + (size_t)(r0 + 8) * 128 + col);
                float2 o0, o1;
                o0.x = fmaxf(c0 + ra.x, 0.f); o0.y = fmaxf(c1 + ra.y, 0.f);
                o1.x = fmaxf(c2 + rb.x, 0.f); o1.y = fmaxf(c3 + rb.y, 0.f);
                *(float2*)(fout + (size_t)r0 * 128 + col) = o0;
                *(float2*)(fout + (size_t)(r0 + 8) * 128 + col) = o1;
            } else {
                float2 aa = *(const float2*)(res  + (size_t)r0 * 128 + col);
                float2 xa = *(const float2*)(xres + (size_t)r0 * 128 + col);
                float2 ab = *(const float2*)(res  + (size_t)(r0 + 8) * 128 + col);
                float2 xb = *(const float2*)(xres + (size_t)(r0 + 8) * 128 + col);
                float2 o0, o1;
                o0.x = aa.x / (1.f + __expf(-c0)) + xa.x;
                o0.y = aa.y / (1.f + __expf(-c1)) + xa.y;
                o1.x = ab.x / (1.f + __expf(-c2)) + xb.x;
                o1.y = ab.y / (1.f + __expf(-c3)) + xb.y;
                *(float2*)(fout + (size_t)r0 * 128 + col) = o0;
                *(float2*)(fout + (size_t)(r0 + 8) * 128 + col) = o1;
            }
        }
    }
}

// ---------------------------------------------------------------------------
// fp16 HMMA conv v3: M=256 pts/CTA, 8 warps (4Mx2N, warp tile 64x32),
// cp.async G->S staging (no reg staging, no STS), single buffer, 2 CTAs/SM.
// smem: A @0 (256*144=36864), Bhi @36864 (9216), Blo @46080 (9216),
//       idx @55296 (27*256*4=27648)  -> 82944 total.
// ---------------------------------------------------------------------------
#define ASTRIDE 144
#define B_HI 36864
#define B_LO 46080
#define IDX_OFF 55296
#define CONV_SMEM (IDX_OFF + 27648)

__global__ __launch_bounds__(256, 2) void k_conv_mma(
    const __half* __restrict__ T16,
    const __half* __restrict__ WtH, const __half* __restrict__ WtL,
    const int* __restrict__ nbr, float* __restrict__ out)
{
    extern __shared__ char sm[];
    const int tid  = threadIdx.x;
    const int lane = tid & 31;
    const int w    = tid >> 5;
    const int wm   = w & 3;        // M band: 64 rows each
    const int wn   = w >> 2;       // N band: 32 cols each
    const int p0   = blockIdx.x * 256;

    const uint32_t su = smem_u32(sm);
    int* idxs = (int*)(sm + IDX_OFF);

    for (int i = tid; i < 27 * 256; i += 256) {
        int p = i / 27;
        int k = i - p * 27;
        int gp = p0 + p;
        idxs[k * 256 + p] = (gp < NPTS) ? nbr[(size_t)gp * 27 + k] : -1;
    }

    float acc[4][4][4];
#pragma unroll
    for (int mt = 0; mt < 4; mt++)
#pragma unroll
        for (int nt = 0; nt < 4; nt++)
#pragma unroll
            for (int e = 0; e < 4; e++) acc[mt][nt][e] = 0.f;

    const uint32_t a_ld = su + (uint32_t)(wm * 64 + (lane & 15)) * ASTRIDE
                        + (uint32_t)(lane >> 4) * 16;
    const uint32_t b_ld = su + B_HI + (uint32_t)(wn * 32 + (lane & 15)) * ASTRIDE
                        + (uint32_t)(lane >> 4) * 16;

    // per-thread cp.async assignments
    // A: 2048 chunks of 16B (256 rows x 8); thread does j = tid + i*256
    // B: 1024 chunks (128 rows x 8: hi rows 0-63, lo rows 64-127)
    __syncthreads();   // idxs visible

    for (int k = 0; k < 27; k++) {
        __syncthreads();   // previous tap's ldmatrix reads complete

        // ---- A gather via cp.async ----
#pragma unroll
        for (int i = 0; i < 8; i++) {
            int j = tid + i * 256;
            int row = j >> 3, ch = j & 7;
            int gr = idxs[k * 256 + row];
            uint32_t dst = su + (uint32_t)row * ASTRIDE + (uint32_t)ch * 16;
            const void* src = T16 + ((size_t)(gr < 0 ? 0 : gr) * 64 + ch * 8);
            cp_async16(dst, src, gr < 0 ? 0u : 16u);
        }
        // ---- B stage via cp.async ----
#pragma unroll
        for (int i = 0; i < 4; i++) {
            int j = tid + i * 256;
            int row = j >> 3, ch = j & 7;       // row 0-127
            int plane = row >> 6, brow = row & 63;
            uint32_t dst = su + (uint32_t)(B_HI + plane * 9216)
                         + (uint32_t)brow * ASTRIDE + (uint32_t)ch * 16;
            const __half* src = (plane ? WtL : WtH)
                              + ((size_t)k * 64 + brow) * 64 + ch * 8;
            cp_async16(dst, src, 16u);
        }
        cp_commit();
        cp_wait0();
        __syncthreads();

        // ---- MMA over K=64 (4 ksteps of 16) ----
#pragma unroll
        for (int ks = 0; ks < 4; ks++) {
            uint32_t a[4][4];
#pragma unroll
            for (int mt = 0; mt < 4; mt++)
                ldsm_x4(a[mt], a_ld + (uint32_t)mt * (16 * ASTRIDE) + ks * 32);
#pragma unroll
            for (int nt2 = 0; nt2 < 2; nt2++) {
                uint32_t bh[4], bl[4];
                ldsm_x4(bh, b_ld + (uint32_t)nt2 * (16 * ASTRIDE) + ks * 32);
                ldsm_x4(bl, b_ld + 9216 + (uint32_t)nt2 * (16 * ASTRIDE) + ks * 32);
#pragma unroll
                for (int mt = 0; mt < 4; mt++) {
                    mma_f16(acc[mt][nt2 * 2 + 0], a[mt], bh[0], bh[2]);
                    mma_f16(acc[mt][nt2 * 2 + 0], a[mt], bl[0], bl[2]);
                    mma_f16(acc[mt][nt2 * 2 + 1], a[mt], bh[1], bh[3]);
                    mma_f16(acc[mt][nt2 * 2 + 1], a[mt], bl[1], bl[3]);
                }
            }
        }
    }

    // epilogue: relu + fp32 store
    const int g = lane >> 2, tg = lane & 3;
#pragma unroll
    for (int mt = 0; mt < 4; mt++) {
        int row0 = p0 + wm * 64 + mt * 16 + g;
#pragma unroll
        for (int nt = 0; nt < 4; nt++) {
            int col = wn * 32 + nt * 8 + tg * 2;
            if (row0 < NPTS) {
                float2 o;
                o.x = fmaxf(acc[mt][nt][0], 0.f);
                o.y = fmaxf(acc[mt][nt][1], 0.f);
                *(float2*)(out + (size_t)row0 * 64 + col) = o;
            }
            if (row0 + 8 < NPTS) {
                float2 o;
                o.x = fmaxf(acc[mt][nt][2], 0.f);
                o.y = fmaxf(acc[mt][nt][3], 0.f);
                *(float2*)(out + (size_t)(row0 + 8) * 64 + col) = o;
            }
        }
    }
}

// ---------------------------------------------------------------------------
extern "C" void kernel_launch(void* const* d_in, const int* in_sizes, int n_in,
                              void* d_out, int out_size)
{
    const float* x   = (const float*)d_in[0];
    const float* W1s = (const float*)d_in[1];
    const float* Wks = (const float*)d_in[2];
    const float* W2s = (const float*)d_in[3];
    const float* Wf  = (const float*)d_in[4];
    const int*   nbr = (const int*)d_in[5];
    float* out = (float*)d_out;

    float *A, *B, *T2;
    __half *T16, *WtH, *WtL;
    __nv_bfloat16 *W1H, *W1L, *W2H, *W2L, *WfH, *WfL;
    cudaGetSymbolAddress((void**)&A,   g_A);
    cudaGetSymbolAddress((void**)&B,   g_B);
    cudaGetSymbolAddress((void**)&T2,  g_T2);
    cudaGetSymbolAddress((void**)&T16, g_T16);
    cudaGetSymbolAddress((void**)&WtH, g_WtH);
    cudaGetSymbolAddress((void**)&WtL, g_WtL);
    cudaGetSymbolAddress((void**)&W1H, g_W1H);
    cudaGetSymbolAddress((void**)&W1L, g_W1L);
    cudaGetSymbolAddress((void**)&W2H, g_W2H);
    cudaGetSymbolAddress((void**)&W2L, g_W2L);
    cudaGetSymbolAddress((void**)&WfH, g_WfH);
    cudaGetSymbolAddress((void**)&WfL, g_WfL);

    constexpr int SM_DOWN  = (128 * 2 + 16) * (128 + 2 * 64);   // 69632
    constexpr int SM_UP    = (64 * 2 + 16) * (128 + 2 * 128);   // 55296
    constexpr int SM_FINAL = (128 * 2 + 16) * (128 + 2 * 128);  // 104448

    cudaFuncSetAttribute(k_conv_mma, cudaFuncAttributeMaxDynamicSharedMemorySize,
                         CONV_SMEM);
    cudaFuncSetAttribute((const void*)k_lin<128, 64, 0>,
                         cudaFuncAttributeMaxDynamicSharedMemorySize, SM_DOWN);
    cudaFuncSetAttribute((const void*)k_lin<64, 128, 1>,
                         cudaFuncAttributeMaxDynamicSharedMemorySize, SM_UP);
    cudaFuncSetAttribute((const void*)k_lin<128, 128, 2>,
                         cudaFuncAttributeMaxDynamicSharedMemorySize, SM_FINAL);

    k_wsplit<<<dim3(27, 6), 256>>>(Wks, WtH, WtL);
    k_wsplit_lin<<<13, 256>>>(W1s, W2s, Wf, W1H, W1L, W2H, W2L, WfH, WfL);

    for (int i = 0; i < 6; i++) {
        const float* hin = (i == 0 || i == 3) ? x : ((i < 3) ? A : B);
        float* hout = (i < 3) ? A : B;
        k_lin<128, 64, 0><<<NBLK64, 256, SM_DOWN>>>(
            hin, W1H + (size_t)i * 8192, W1L + (size_t)i * 8192,
            nullptr, nullptr, nullptr, T16);
        k_conv_mma<<<NBLK256, 256, CONV_SMEM>>>(
            T16, WtH + (size_t)i * 27 * 4096, WtL + (size_t)i * 27 * 4096,
            nbr, T2);
        k_lin<64, 128, 1><<<NBLK64, 256, SM_UP>>>(
            T2, W2H + (size_t)i * 8192, W2L + (size_t)i * 8192,
            hin, nullptr, hout, nullptr);
    }
    k_lin<128, 128, 2><<<NBLK64, 256, SM_FINAL>>>(
        B, WfH, WfL, A, x, out, nullptr);
}

// round 8
// speedup vs baseline: 3.0209x; 1.0823x over previous
#include <cuda_runtime.h>
#include <cuda_bf16.h>
#include <cuda_fp16.h>
#include <cstdint>

#define NPTS 120000
#define NBLK64 1875
#define NBLK192 625   // 120000 / 192 exactly

// ---------------- scratch (device globals: allocation-free) ----------------
__device__ float g_A[NPTS * 128];
__device__ float g_B[NPTS * 128];
__device__ float g_T2[NPTS * 64];
__device__ __half g_T16[NPTS * 64];                 // conv input activations (fp16)
__device__ __half g_WtH[6 * 27 * 64 * 64];          // conv weights [u][k][j][c] fp16 hi
__device__ __half g_WtL[6 * 27 * 64 * 64];          // fp16 lo residual
__device__ __nv_bfloat16 g_W1H[6 * 64 * 128];       // down weights [u][n][k]
__device__ __nv_bfloat16 g_W1L[6 * 64 * 128];
__device__ __nv_bfloat16 g_W2H[6 * 128 * 64];       // up weights [u][n][k]
__device__ __nv_bfloat16 g_W2L[6 * 128 * 64];
__device__ __nv_bfloat16 g_WfH[128 * 128];          // final weights [n][k]
__device__ __nv_bfloat16 g_WfL[128 * 128];

// ---------------- helpers ---------------------------------------------------
__device__ __forceinline__ uint32_t smem_u32(const void* p) {
    uint32_t a;
    asm("{ .reg .u64 t; cvta.to.shared.u64 t, %1; cvt.u32.u64 %0, t; }"
        : "=r"(a) : "l"(p));
    return a;
}
__device__ __forceinline__ void ldsm_x4(uint32_t (&r)[4], uint32_t addr) {
    asm volatile("ldmatrix.sync.aligned.m8n8.x4.shared.b16 {%0,%1,%2,%3}, [%4];"
                 : "=r"(r[0]), "=r"(r[1]), "=r"(r[2]), "=r"(r[3]) : "r"(addr));
}
__device__ __forceinline__ void ldsm_x2(uint32_t (&r)[2], uint32_t addr) {
    asm volatile("ldmatrix.sync.aligned.m8n8.x2.shared.b16 {%0,%1}, [%2];"
                 : "=r"(r[0]), "=r"(r[1]) : "r"(addr));
}
__device__ __forceinline__ void mma_bf16(float* c, const uint32_t* a,
                                         const uint32_t* b) {
    asm volatile(
        "mma.sync.aligned.m16n8k16.row.col.f32.bf16.bf16.f32 "
        "{%0,%1,%2,%3}, {%4,%5,%6,%7}, {%8,%9}, {%0,%1,%2,%3};"
        : "+f"(c[0]), "+f"(c[1]), "+f"(c[2]), "+f"(c[3])
        : "r"(a[0]), "r"(a[1]), "r"(a[2]), "r"(a[3]), "r"(b[0]), "r"(b[1]));
}
__device__ __forceinline__ void mma_f16(float* c, const uint32_t* a,
                                        uint32_t b0, uint32_t b1) {
    asm volatile(
        "mma.sync.aligned.m16n8k16.row.col.f32.f16.f16.f32 "
        "{%0,%1,%2,%3}, {%4,%5,%6,%7}, {%8,%9}, {%0,%1,%2,%3};"
        : "+f"(c[0]), "+f"(c[1]), "+f"(c[2]), "+f"(c[3])
        : "r"(a[0]), "r"(a[1]), "r"(a[2]), "r"(a[3]), "r"(b0), "r"(b1));
}
__device__ __forceinline__ void cp_async16(uint32_t dst, const void* src,
                                           uint32_t src_size) {
    asm volatile("cp.async.ca.shared.global [%0], [%1], 16, %2;"
                 :: "r"(dst), "l"(src), "r"(src_size) : "memory");
}
__device__ __forceinline__ void cp_commit() {
    asm volatile("cp.async.commit_group;" ::: "memory");
}
template <int N>
__device__ __forceinline__ void cp_wait() {
    asm volatile("cp.async.wait_group %0;" :: "n"(N) : "memory");
}
__device__ __forceinline__ unsigned pack_bf2(__nv_bfloat16 a, __nv_bfloat16 b) {
    __nv_bfloat162 t; t.x = a; t.y = b;
    return *reinterpret_cast<unsigned*>(&t);
}
__device__ __forceinline__ void split2(float x, float y, unsigned& h, unsigned& l) {
    __nv_bfloat16 hx = __float2bfloat16(x);
    __nv_bfloat16 hy = __float2bfloat16(y);
    float rx = x - __bfloat162float(hx);
    float ry = y - __bfloat162float(hy);
    h = pack_bf2(hx, hy);
    l = pack_bf2(__float2bfloat16(rx), __float2bfloat16(ry));
}

// ---------------------------------------------------------------------------
// conv weight split+transpose: Wt[u][k][j][c] = Wk[u][k][c][j] as fp16 hi/lo
// ---------------------------------------------------------------------------
__global__ void k_wsplit(const float* __restrict__ Wks,
                         __half* __restrict__ WtH,
                         __half* __restrict__ WtL) {
    int k = blockIdx.x, u = blockIdx.y;
    const float* src = Wks + ((size_t)u * 27 + k) * 4096;
    __half* dh = WtH + ((size_t)u * 27 + k) * 4096;
    __half* dl = WtL + ((size_t)u * 27 + k) * 4096;
    for (int e = threadIdx.x; e < 4096; e += blockDim.x) {
        int c = e >> 6, j = e & 63;
        float v = src[c * 64 + j];
        __half h = __float2half(v);
        float r = v - __half2float(h);
        dh[j * 64 + c] = h;
        dl[j * 64 + c] = __float2half(r);
    }
}

// ---------------------------------------------------------------------------
// linear weight split+transpose: [k][n] fp32 -> [n][k] bf16 hi/lo
// ---------------------------------------------------------------------------
__global__ void k_wsplit_lin(const float* __restrict__ W1s,
                             const float* __restrict__ W2s,
                             const float* __restrict__ Wf,
                             __nv_bfloat16* __restrict__ W1H, __nv_bfloat16* __restrict__ W1L,
                             __nv_bfloat16* __restrict__ W2H, __nv_bfloat16* __restrict__ W2L,
                             __nv_bfloat16* __restrict__ WfH, __nv_bfloat16* __restrict__ WfL) {
    int b = blockIdx.x;
    if (b < 6) {
        const float* s = W1s + (size_t)b * 8192;
        __nv_bfloat16* dh = W1H + (size_t)b * 8192;
        __nv_bfloat16* dl = W1L + (size_t)b * 8192;
        for (int e = threadIdx.x; e < 8192; e += blockDim.x) {
            int k = e >> 6, n = e & 63;
            float v = s[e];
            __nv_bfloat16 h = __float2bfloat16(v);
            dh[n * 128 + k] = h;
            dl[n * 128 + k] = __float2bfloat16(v - __bfloat162float(h));
        }
    } else if (b < 12) {
        const float* s = W2s + (size_t)(b - 6) * 8192;
        __nv_bfloat16* dh = W2H + (size_t)(b - 6) * 8192;
        __nv_bfloat16* dl = W2L + (size_t)(b - 6) * 8192;
        for (int e = threadIdx.x; e < 8192; e += blockDim.x) {
            int k = e >> 7, n = e & 127;
            float v = s[e];
            __nv_bfloat16 h = __float2bfloat16(v);
            dh[n * 64 + k] = h;
            dl[n * 64 + k] = __float2bfloat16(v - __bfloat162float(h));
        }
    } else {
        for (int e = threadIdx.x; e < 16384; e += blockDim.x) {
            int k = e >> 7, n = e & 127;
            float v = Wf[e];
            __nv_bfloat16 h = __float2bfloat16(v);
            WfH[n * 128 + k] = h;
            WfL[n * 128 + k] = __float2bfloat16(v - __bfloat162float(h));
        }
    }
}

// ---------------------------------------------------------------------------
// HMMA 1x1 layer, M=64 tiles, 2 CTAs/SM  (unchanged — proven)
// ---------------------------------------------------------------------------
template <int K, int N, int EPI>
__global__ __launch_bounds__(256, 2) void k_lin(
    const float* __restrict__ in,
    const __nv_bfloat16* __restrict__ BH, const __nv_bfloat16* __restrict__ BL,
    const float* __restrict__ res, const float* __restrict__ xres,
    float* __restrict__ fout, __half* __restrict__ out16)
{
    constexpr int SB   = K * 2 + 16;
    constexpr int ASZ  = 64 * SB;
    constexpr int BOFF = 2 * ASZ;
    constexpr int NTW  = N / 4;
    constexpr int NT   = NTW / 8;
    constexpr int KS   = K / 16;

    extern __shared__ char sm[];
    const uint32_t su = smem_u32(sm);
    const int tid  = threadIdx.x;
    const int lane = tid & 31;
    const int w    = tid >> 5;
    const int wm   = w & 1;
    const int wn   = w >> 1;
    const int mbase = wm * 32;
    const int p0   = blockIdx.x * 64;

    {
        int row = tid >> 2, q = tid & 3;
        const float* src = in + (size_t)(p0 + row) * K + q * (K / 4);
        char* ah = sm + row * SB + q * (K / 2);
        char* al = sm + ASZ + row * SB + q * (K / 2);
#pragma unroll
        for (int c = 0; c < K / 4; c += 8) {
            float4 f0 = *(const float4*)(src + c);
            float4 f1 = *(const float4*)(src + c + 4);
            unsigned h0, h1, h2, h3, l0, l1, l2, l3;
            split2(f0.x, f0.y, h0, l0);
            split2(f0.z, f0.w, h1, l1);
            split2(f1.x, f1.y, h2, l2);
            split2(f1.z, f1.w, h3, l3);
            *(uint4*)(ah + c * 2) = make_uint4(h0, h1, h2, h3);
            *(uint4*)(al + c * 2) = make_uint4(l0, l1, l2, l3);
        }
    }
    {
        constexpr int ITER = N * K / 1024;
        int plane = tid >> 7, t = tid & 127;
        const __nv_bfloat16* bs = plane ? BL : BH;
        char* bd = sm + BOFF + plane * (N * SB);
#pragma unroll
        for (int i = 0; i < ITER; i++) {
            int j = t + i * 128;
            int e = j * 8;
            int r = e / K, c = e % K;
            *(uint4*)(bd + r * SB + c * 2) = *(const uint4*)(bs + e);
        }
    }
    __syncthreads();

    float acc[2][NT][4];
#pragma unroll
    for (int mt = 0; mt < 2; mt++)
#pragma unroll
        for (int nt = 0; nt < NT; nt++)
#pragma unroll
            for (int e = 0; e < 4; e++) acc[mt][nt][e] = 0.f;

    const uint32_t a_ld = su + (uint32_t)(mbase + (lane & 15)) * SB
                        + (uint32_t)(lane >> 4) * 16;
    const uint32_t b_ld = su + BOFF + (uint32_t)(wn * NTW + (lane & 7)) * SB
                        + (uint32_t)((lane >> 3) & 1) * 16;

#pragma unroll
    for (int ks = 0; ks < KS; ks++) {
        uint32_t ah[2][4], al[2][4];
#pragma unroll
        for (int mt = 0; mt < 2; mt++) {
            ldsm_x4(ah[mt], a_ld + (uint32_t)mt * (16 * SB) + ks * 32);
            ldsm_x4(al[mt], a_ld + ASZ + (uint32_t)mt * (16 * SB) + ks * 32);
        }
#pragma unroll
        for (int nt = 0; nt < NT; nt++) {
            uint32_t bh[2], bl[2];
            ldsm_x2(bh, b_ld + (uint32_t)nt * (8 * SB) + ks * 32);
            ldsm_x2(bl, b_ld + (uint32_t)(N * SB) + (uint32_t)nt * (8 * SB) + ks * 32);
#pragma unroll
            for (int mt = 0; mt < 2; mt++) {
                mma_bf16(acc[mt][nt], ah[mt], bh);
                mma_bf16(acc[mt][nt], ah[mt], bl);
                mma_bf16(acc[mt][nt], al[mt], bh);
            }
        }
    }

    const int g = lane >> 2, tg = lane & 3;
#pragma unroll
    for (int mt = 0; mt < 2; mt++) {
        int r0 = p0 + mbase + mt * 16 + g;
#pragma unroll
        for (int nt = 0; nt < NT; nt++) {
            int col = wn * NTW + nt * 8 + tg * 2;
            float c0 = acc[mt][nt][0], c1 = acc[mt][nt][1];
            float c2 = acc[mt][nt][2], c3 = acc[mt][nt][3];
            if (EPI == 0) {
                __half2 o0 = __floats2half2_rn(fmaxf(c0, 0.f), fmaxf(c1, 0.f));
                __half2 o1 = __floats2half2_rn(fmaxf(c2, 0.f), fmaxf(c3, 0.f));
                *(__half2*)(out16 + (size_t)r0 * 64 + col) = o0;
                *(__half2*)(out16 + (size_t)(r0 + 8) * 64 + col) = o1;
            } else if (EPI == 1) {
                float2 ra = *(const float2*)(res + (size_t)r0 * 128 + col);
                float2 rb = *(const float2*)(res + (size_t)(r0 + 8) * 128 + col);
                float2 o0, o1;
                o0.x = fmaxf(c0 + ra.x, 0.f); o0.y = fmaxf(c1 + ra.y, 0.f);
                o1.x = fmaxf(c2 + rb.x, 0.f); o1.y = fmaxf(c3 + rb.y, 0.f);
                *(float2*)(fout + (size_t)r0 * 128 + col) = o0;
                *(float2*)(fout + (size_t)(r0 + 8) * 128 + col) = o1;
            } else {
                float2 aa = *(const float2*)(res  + (size_t)r0 * 128 + col);
                float2 xa = *(const float2*)(xres + (size_t)r0 * 128 + col);
                float2 ab = *(const float2*)(res  + (size_t)(r0 + 8) * 128 + col);
                float2 xb = *(const float2*)(xres + (size_t)(r0 + 8) * 128 + col);
                float2 o0, o1;
                o0.x = aa.x / (1.f + __expf(-c0)) + xa.x;
                o0.y = aa.y / (1.f + __expf(-c1)) + xa.y;
                o1.x = ab.x / (1.f + __expf(-c2)) + xb.x;
                o1.y = ab.y / (1.f + __expf(-c3)) + xb.y;
                *(float2*)(fout + (size_t)r0 * 128 + col) = o0;
                *(float2*)(fout + (size_t)(r0 + 8) * 128 + col) = o1;
            }
        }
    }
}

// ---------------------------------------------------------------------------
// fp16 HMMA conv v4: M=192 pts/CTA (625*192 = NPTS exactly), 8 warps
// (4 M-bands x 48 rows, 2 N-bands x 32 cols), DOUBLE-BUFFERED cp.async:
// tap k+1's loads overlap tap k's MMA via wait_group(1).
// Per stage (46080B): A @+0 (192*144=27648), Bhi @+27648, Blo @+36864.
// Stage 0 @0, stage 1 @46080, idx @92160 (27*192*4=20736) -> 112896, 2 CTAs/SM.
// ---------------------------------------------------------------------------
#define ASTRIDE 144
#define STAGE_SZ 46080
#define SB_HI 27648
#define IDX_OFF 92160
#define CONV_SMEM (IDX_OFF + 20736)

__global__ __launch_bounds__(256, 2) void k_conv_mma(
    const __half* __restrict__ T16,
    const __half* __restrict__ WtH, const __half* __restrict__ WtL,
    const int* __restrict__ nbr, float* __restrict__ out)
{
    extern __shared__ char sm[];
    const int tid  = threadIdx.x;
    const int lane = tid & 31;
    const int w    = tid >> 5;
    const int wm   = w & 3;        // M band: 48 rows each
    const int wn   = w >> 2;       // N band: 32 cols each
    const int p0   = blockIdx.x * 192;

    const uint32_t su = smem_u32(sm);
    int* idxs = (int*)(sm + IDX_OFF);

    for (int i = tid; i < 27 * 192; i += 256) {
        int p = i / 27;
        int k = i - p * 27;
        idxs[k * 192 + p] = nbr[(size_t)(p0 + p) * 27 + k];
    }

    float acc[3][4][4];
#pragma unroll
    for (int mt = 0; mt < 3; mt++)
#pragma unroll
        for (int nt = 0; nt < 4; nt++)
#pragma unroll
            for (int e = 0; e < 4; e++) acc[mt][nt][e] = 0.f;

    const uint32_t a_ld0 = su + (uint32_t)(wm * 48 + (lane & 15)) * ASTRIDE
                         + (uint32_t)(lane >> 4) * 16;
    const uint32_t b_ld0 = su + SB_HI + (uint32_t)(wn * 32 + (lane & 15)) * ASTRIDE
                         + (uint32_t)(lane >> 4) * 16;

    __syncthreads();   // idxs visible

    // per-tap load issue: A = 192 rows x 8 chunks (1536 -> 6 iters),
    //                     B = 128 rows x 8 chunks (1024 -> 4 iters)
    auto issue_tap = [&](int k, uint32_t sbase) {
#pragma unroll
        for (int i = 0; i < 6; i++) {
            int j = tid + i * 256;
            int row = j >> 3, ch = j & 7;
            int gr = idxs[k * 192 + row];
            uint32_t dst = sbase + (uint32_t)row * ASTRIDE + (uint32_t)ch * 16;
            const void* src = T16 + ((size_t)(gr < 0 ? 0 : gr) * 64 + ch * 8);
            cp_async16(dst, src, gr < 0 ? 0u : 16u);
        }
#pragma unroll
        for (int i = 0; i < 4; i++) {
            int j = tid + i * 256;
            int row = j >> 3, ch = j & 7;
            int plane = row >> 6, brow = row & 63;
            uint32_t dst = sbase + (uint32_t)(SB_HI + plane * 9216)
                         + (uint32_t)brow * ASTRIDE + (uint32_t)ch * 16;
            const __half* src = (plane ? WtL : WtH)
                              + ((size_t)k * 64 + brow) * 64 + ch * 8;
            cp_async16(dst, src, 16u);
        }
        cp_commit();
    };

    // prologue: taps 0 and 1 in flight
    issue_tap(0, su);
    issue_tap(1, su + STAGE_SZ);

    for (int k = 0; k < 27; k++) {
        const uint32_t sb = (uint32_t)(k & 1) * STAGE_SZ;
        if (k < 26) cp_wait<1>(); else cp_wait<0>();
        __syncthreads();   // stage k&1 fully loaded & all threads past prior reads

        // MMA over K=64 from stage k&1
        const uint32_t a_ld = a_ld0 + sb;
        const uint32_t b_ld = b_ld0 + sb;
#pragma unroll
        for (int ks = 0; ks < 4; ks++) {
            uint32_t a[3][4];
#pragma unroll
            for (int mt = 0; mt < 3; mt++)
                ldsm_x4(a[mt], a_ld + (uint32_t)mt * (16 * ASTRIDE) + ks * 32);
#pragma unroll
            for (int nt2 = 0; nt2 < 2; nt2++) {
                uint32_t bh[4], bl[4];
                ldsm_x4(bh, b_ld + (uint32_t)nt2 * (16 * ASTRIDE) + ks * 32);
                ldsm_x4(bl, b_ld + 9216 + (uint32_t)nt2 * (16 * ASTRIDE) + ks * 32);
#pragma unroll
                for (int mt = 0; mt < 3; mt++) {
                    mma_f16(acc[mt][nt2 * 2 + 0], a[mt], bh[0], bh[2]);
                    mma_f16(acc[mt][nt2 * 2 + 0], a[mt], bl[0], bl[2]);
                    mma_f16(acc[mt][nt2 * 2 + 1], a[mt], bh[1], bh[3]);
                    mma_f16(acc[mt][nt2 * 2 + 1], a[mt], bl[1], bl[3]);
                }
            }
        }

        // refill this stage with tap k+2 (overlaps next tap's MMA)
        if (k < 25) {
            __syncthreads();          // all MMA reads of stage k&1 done
            issue_tap(k + 2, su + sb);
        }
    }

    // epilogue: relu + fp32 store (no bounds checks: 625*192 == NPTS)
    const int g = lane >> 2, tg = lane & 3;
#pragma unroll
    for (int mt = 0; mt < 3; mt++) {
        int row0 = p0 + wm * 48 + mt * 16 + g;
#pragma unroll
        for (int nt = 0; nt < 4; nt++) {
            int col = wn * 32 + nt * 8 + tg * 2;
            float2 o0, o1;
            o0.x = fmaxf(acc[mt][nt][0], 0.f);
            o0.y = fmaxf(acc[mt][nt][1], 0.f);
            o1.x = fmaxf(acc[mt][nt][2], 0.f);
            o1.y = fmaxf(acc[mt][nt][3], 0.f);
            *(float2*)(out + (size_t)row0 * 64 + col) = o0;
            *(float2*)(out + (size_t)(row0 + 8) * 64 + col) = o1;
        }
    }
}

// ---------------------------------------------------------------------------
extern "C" void kernel_launch(void* const* d_in, const int* in_sizes, int n_in,
                              void* d_out, int out_size)
{
    const float* x   = (const float*)d_in[0];
    const float* W1s = (const float*)d_in[1];
    const float* Wks = (const float*)d_in[2];
    const float* W2s = (const float*)d_in[3];
    const float* Wf  = (const float*)d_in[4];
    const int*   nbr = (const int*)d_in[5];
    float* out = (float*)d_out;

    float *A, *B, *T2;
    __half *T16, *WtH, *WtL;
    __nv_bfloat16 *W1H, *W1L, *W2H, *W2L, *WfH, *WfL;
    cudaGetSymbolAddress((void**)&A,   g_A);
    cudaGetSymbolAddress((void**)&B,   g_B);
    cudaGetSymbolAddress((void**)&T2,  g_T2);
    cudaGetSymbolAddress((void**)&T16, g_T16);
    cudaGetSymbolAddress((void**)&WtH, g_WtH);
    cudaGetSymbolAddress((void**)&WtL, g_WtL);
    cudaGetSymbolAddress((void**)&W1H, g_W1H);
    cudaGetSymbolAddress((void**)&W1L, g_W1L);
    cudaGetSymbolAddress((void**)&W2H, g_W2H);
    cudaGetSymbolAddress((void**)&W2L, g_W2L);
    cudaGetSymbolAddress((void**)&WfH, g_WfH);
    cudaGetSymbolAddress((void**)&WfL, g_WfL);

    constexpr int SM_DOWN  = (128 * 2 + 16) * (128 + 2 * 64);   // 69632
    constexpr int SM_UP    = (64 * 2 + 16) * (128 + 2 * 128);   // 55296
    constexpr int SM_FINAL = (128 * 2 + 16) * (128 + 2 * 128);  // 104448

    cudaFuncSetAttribute(k_conv_mma, cudaFuncAttributeMaxDynamicSharedMemorySize,
                         CONV_SMEM);
    cudaFuncSetAttribute((const void*)k_lin<128, 64, 0>,
                         cudaFuncAttributeMaxDynamicSharedMemorySize, SM_DOWN);
    cudaFuncSetAttribute((const void*)k_lin<64, 128, 1>,
                         cudaFuncAttributeMaxDynamicSharedMemorySize, SM_UP);
    cudaFuncSetAttribute((const void*)k_lin<128, 128, 2>,
                         cudaFuncAttributeMaxDynamicSharedMemorySize, SM_FINAL);

    k_wsplit<<<dim3(27, 6), 256>>>(Wks, WtH, WtL);
    k_wsplit_lin<<<13, 256>>>(W1s, W2s, Wf, W1H, W1L, W2H, W2L, WfH, WfL);

    for (int i = 0; i < 6; i++) {
        const float* hin = (i == 0 || i == 3) ? x : ((i < 3) ? A : B);
        float* hout = (i < 3) ? A : B;
        k_lin<128, 64, 0><<<NBLK64, 256, SM_DOWN>>>(
            hin, W1H + (size_t)i * 8192, W1L + (size_t)i * 8192,
            nullptr, nullptr, nullptr, T16);
        k_conv_mma<<<NBLK192, 256, CONV_SMEM>>>(
            T16, WtH + (size_t)i * 27 * 4096, WtL + (size_t)i * 27 * 4096,
            nbr, T2);
        k_lin<64, 128, 1><<<NBLK64, 256, SM_UP>>>(
            T2, W2H + (size_t)i * 8192, W2L + (size_t)i * 8192,
            hin, nullptr, hout, nullptr);
    }
    k_lin<128, 128, 2><<<NBLK64, 256, SM_FINAL>>>(
        B, WfH, WfL, A, x, out, nullptr);
}

// round 9
// speedup vs baseline: 3.1831x; 1.0537x over previous
#include <cuda_runtime.h>
#include <cuda_bf16.h>
#include <cuda_fp16.h>
#include <cstdint>

#define NPTS 120000
#define NBLK64 1875
#define NBLK192 625   // 120000 / 192 exactly

// ---------------- scratch (device globals: allocation-free) ----------------
__device__ float g_A[NPTS * 128];
__device__ float g_B[NPTS * 128];
__device__ float g_T2[NPTS * 64];
__device__ __half g_T16[NPTS * 64];                 // conv input activations (fp16)
__device__ __half g_WtH[6 * 27 * 64 * 64];          // conv weights [u][k][j][c] fp16 hi
__device__ __half g_WtL[6 * 27 * 64 * 64];          // fp16 lo residual
__device__ __nv_bfloat16 g_W1H[6 * 64 * 128];       // down weights [u][n][k] bf16
__device__ __nv_bfloat16 g_W1L[6 * 64 * 128];
__device__ __half g_V1H[6 * 64 * 128];              // down weights fp16 hi/lo
__device__ __half g_V1L[6 * 64 * 128];
__device__ __nv_bfloat16 g_W2H[6 * 128 * 64];       // up weights [u][n][k]
__device__ __nv_bfloat16 g_W2L[6 * 128 * 64];
__device__ __nv_bfloat16 g_WfH[128 * 128];          // final weights [n][k]
__device__ __nv_bfloat16 g_WfL[128 * 128];

// ---------------- helpers ---------------------------------------------------
__device__ __forceinline__ uint32_t smem_u32(const void* p) {
    uint32_t a;
    asm("{ .reg .u64 t; cvta.to.shared.u64 t, %1; cvt.u32.u64 %0, t; }"
        : "=r"(a) : "l"(p));
    return a;
}
__device__ __forceinline__ void ldsm_x4(uint32_t (&r)[4], uint32_t addr) {
    asm volatile("ldmatrix.sync.aligned.m8n8.x4.shared.b16 {%0,%1,%2,%3}, [%4];"
                 : "=r"(r[0]), "=r"(r[1]), "=r"(r[2]), "=r"(r[3]) : "r"(addr));
}
__device__ __forceinline__ void ldsm_x2(uint32_t (&r)[2], uint32_t addr) {
    asm volatile("ldmatrix.sync.aligned.m8n8.x2.shared.b16 {%0,%1}, [%2];"
                 : "=r"(r[0]), "=r"(r[1]) : "r"(addr));
}
__device__ __forceinline__ void mma_bf16(float* c, const uint32_t* a,
                                         const uint32_t* b) {
    asm volatile(
        "mma.sync.aligned.m16n8k16.row.col.f32.bf16.bf16.f32 "
        "{%0,%1,%2,%3}, {%4,%5,%6,%7}, {%8,%9}, {%0,%1,%2,%3};"
        : "+f"(c[0]), "+f"(c[1]), "+f"(c[2]), "+f"(c[3])
        : "r"(a[0]), "r"(a[1]), "r"(a[2]), "r"(a[3]), "r"(b[0]), "r"(b[1]));
}
__device__ __forceinline__ void mma_f16(float* c, const uint32_t* a,
                                        uint32_t b0, uint32_t b1) {
    asm volatile(
        "mma.sync.aligned.m16n8k16.row.col.f32.f16.f16.f32 "
        "{%0,%1,%2,%3}, {%4,%5,%6,%7}, {%8,%9}, {%0,%1,%2,%3};"
        : "+f"(c[0]), "+f"(c[1]), "+f"(c[2]), "+f"(c[3])
        : "r"(a[0]), "r"(a[1]), "r"(a[2]), "r"(a[3]), "r"(b0), "r"(b1));
}
__device__ __forceinline__ void cp_async16(uint32_t dst, const void* src,
                                           uint32_t src_size) {
    asm volatile("cp.async.ca.shared.global [%0], [%1], 16, %2;"
                 :: "r"(dst), "l"(src), "r"(src_size) : "memory");
}
__device__ __forceinline__ void cp_commit() {
    asm volatile("cp.async.commit_group;" ::: "memory");
}
template <int N>
__device__ __forceinline__ void cp_wait() {
    asm volatile("cp.async.wait_group %0;" :: "n"(N) : "memory");
}
__device__ __forceinline__ unsigned pack_bf2(__nv_bfloat16 a, __nv_bfloat16 b) {
    __nv_bfloat162 t; t.x = a; t.y = b;
    return *reinterpret_cast<unsigned*>(&t);
}
__device__ __forceinline__ void split2(float x, float y, unsigned& h, unsigned& l) {
    __nv_bfloat16 hx = __float2bfloat16(x);
    __nv_bfloat16 hy = __float2bfloat16(y);
    float rx = x - __bfloat162float(hx);
    float ry = y - __bfloat162float(hy);
    h = pack_bf2(hx, hy);
    l = pack_bf2(__float2bfloat16(rx), __float2bfloat16(ry));
}

// ---------------------------------------------------------------------------
// conv weight split+transpose: Wt[u][k][j][c] = Wk[u][k][c][j] as fp16 hi/lo
// ---------------------------------------------------------------------------
__global__ void k_wsplit(const float* __restrict__ Wks,
                         __half* __restrict__ WtH,
                         __half* __restrict__ WtL) {
    int k = blockIdx.x, u = blockIdx.y;
    const float* src = Wks + ((size_t)u * 27 + k) * 4096;
    __half* dh = WtH + ((size_t)u * 27 + k) * 4096;
    __half* dl = WtL + ((size_t)u * 27 + k) * 4096;
    for (int e = threadIdx.x; e < 4096; e += blockDim.x) {
        int c = e >> 6, j = e & 63;
        float v = src[c * 64 + j];
        __half h = __float2half(v);
        float r = v - __half2float(h);
        dh[j * 64 + c] = h;
        dl[j * 64 + c] = __float2half(r);
    }
}

// ---------------------------------------------------------------------------
// linear weight split+transpose: [k][n] fp32 -> [n][k] bf16 hi/lo (+fp16 for W1)
// ---------------------------------------------------------------------------
__global__ void k_wsplit_lin(const float* __restrict__ W1s,
                             const float* __restrict__ W2s,
                             const float* __restrict__ Wf,
                             __nv_bfloat16* __restrict__ W1H, __nv_bfloat16* __restrict__ W1L,
                             __half* __restrict__ V1H, __half* __restrict__ V1L,
                             __nv_bfloat16* __restrict__ W2H, __nv_bfloat16* __restrict__ W2L,
                             __nv_bfloat16* __restrict__ WfH, __nv_bfloat16* __restrict__ WfL) {
    int b = blockIdx.x;
    if (b < 6) {
        const float* s = W1s + (size_t)b * 8192;
        __nv_bfloat16* dh = W1H + (size_t)b * 8192;
        __nv_bfloat16* dl = W1L + (size_t)b * 8192;
        __half* vh = V1H + (size_t)b * 8192;
        __half* vl = V1L + (size_t)b * 8192;
        for (int e = threadIdx.x; e < 8192; e += blockDim.x) {
            int k = e >> 6, n = e & 63;
            float v = s[e];
            __nv_bfloat16 h = __float2bfloat16(v);
            dh[n * 128 + k] = h;
            dl[n * 128 + k] = __float2bfloat16(v - __bfloat162float(h));
            __half fh = __float2half(v);
            vh[n * 128 + k] = fh;
            vl[n * 128 + k] = __float2half(v - __half2float(fh));
        }
    } else if (b < 12) {
        const float* s = W2s + (size_t)(b - 6) * 8192;
        __nv_bfloat16* dh = W2H + (size_t)(b - 6) * 8192;
        __nv_bfloat16* dl = W2L + (size_t)(b - 6) * 8192;
        for (int e = threadIdx.x; e < 8192; e += blockDim.x) {
            int k = e >> 7, n = e & 127;
            float v = s[e];
            __nv_bfloat16 h = __float2bfloat16(v);
            dh[n * 64 + k] = h;
            dl[n * 64 + k] = __float2bfloat16(v - __bfloat162float(h));
        }
    } else {
        for (int e = threadIdx.x; e < 16384; e += blockDim.x) {
            int k = e >> 7, n = e & 127;
            float v = Wf[e];
            __nv_bfloat16 h = __float2bfloat16(v);
            WfH[n * 128 + k] = h;
            WfL[n * 128 + k] = __float2bfloat16(v - __bfloat162float(h));
        }
    }
}

// ---------------------------------------------------------------------------
// HMMA 1x1 layer, M=64 tiles, 2 CTAs/SM (proven; used for down0/3, up2/5, final)
// ---------------------------------------------------------------------------
template <int K, int N, int EPI>
__global__ __launch_bounds__(256, 2) void k_lin(
    const float* __restrict__ in,
    const __nv_bfloat16* __restrict__ BH, const __nv_bfloat16* __restrict__ BL,
    const float* __restrict__ res, const float* __restrict__ xres,
    float* __restrict__ fout, __half* __restrict__ out16)
{
    constexpr int SB   = K * 2 + 16;
    constexpr int ASZ  = 64 * SB;
    constexpr int BOFF = 2 * ASZ;
    constexpr int NTW  = N / 4;
    constexpr int NT   = NTW / 8;
    constexpr int KS   = K / 16;

    extern __shared__ char sm[];
    const uint32_t su = smem_u32(sm);
    const int tid  = threadIdx.x;
    const int lane = tid & 31;
    const int w    = tid >> 5;
    const int wm   = w & 1;
    const int wn   = w >> 1;
    const int mbase = wm * 32;
    const int p0   = blockIdx.x * 64;

    {
        int row = tid >> 2, q = tid & 3;
        const float* src = in + (size_t)(p0 + row) * K + q * (K / 4);
        char* ah = sm + row * SB + q * (K / 2);
        char* al = sm + ASZ + row * SB + q * (K / 2);
#pragma unroll
        for (int c = 0; c < K / 4; c += 8) {
            float4 f0 = *(const float4*)(src + c);
            float4 f1 = *(const float4*)(src + c + 4);
            unsigned h0, h1, h2, h3, l0, l1, l2, l3;
            split2(f0.x, f0.y, h0, l0);
            split2(f0.z, f0.w, h1, l1);
            split2(f1.x, f1.y, h2, l2);
            split2(f1.z, f1.w, h3, l3);
            *(uint4*)(ah + c * 2) = make_uint4(h0, h1, h2, h3);
            *(uint4*)(al + c * 2) = make_uint4(l0, l1, l2, l3);
        }
    }
    {
        constexpr int ITER = N * K / 1024;
        int plane = tid >> 7, t = tid & 127;
        const __nv_bfloat16* bs = plane ? BL : BH;
        char* bd = sm + BOFF + plane * (N * SB);
#pragma unroll
        for (int i = 0; i < ITER; i++) {
            int j = t + i * 128;
            int e = j * 8;
            int r = e / K, c = e % K;
            *(uint4*)(bd + r * SB + c * 2) = *(const uint4*)(bs + e);
        }
    }
    __syncthreads();

    float acc[2][NT][4];
#pragma unroll
    for (int mt = 0; mt < 2; mt++)
#pragma unroll
        for (int nt = 0; nt < NT; nt++)
#pragma unroll
            for (int e = 0; e < 4; e++) acc[mt][nt][e] = 0.f;

    const uint32_t a_ld = su + (uint32_t)(mbase + (lane & 15)) * SB
                        + (uint32_t)(lane >> 4) * 16;
    const uint32_t b_ld = su + BOFF + (uint32_t)(wn * NTW + (lane & 7)) * SB
                        + (uint32_t)((lane >> 3) & 1) * 16;

#pragma unroll
    for (int ks = 0; ks < KS; ks++) {
        uint32_t ah[2][4], al[2][4];
#pragma unroll
        for (int mt = 0; mt < 2; mt++) {
            ldsm_x4(ah[mt], a_ld + (uint32_t)mt * (16 * SB) + ks * 32);
            ldsm_x4(al[mt], a_ld + ASZ + (uint32_t)mt * (16 * SB) + ks * 32);
        }
#pragma unroll
        for (int nt = 0; nt < NT; nt++) {
            uint32_t bh[2], bl[2];
            ldsm_x2(bh, b_ld + (uint32_t)nt * (8 * SB) + ks * 32);
            ldsm_x2(bl, b_ld + (uint32_t)(N * SB) + (uint32_t)nt * (8 * SB) + ks * 32);
#pragma unroll
            for (int mt = 0; mt < 2; mt++) {
                mma_bf16(acc[mt][nt], ah[mt], bh);
                mma_bf16(acc[mt][nt], ah[mt], bl);
                mma_bf16(acc[mt][nt], al[mt], bh);
            }
        }
    }

    const int g = lane >> 2, tg = lane & 3;
#pragma unroll
    for (int mt = 0; mt < 2; mt++) {
        int r0 = p0 + mbase + mt * 16 + g;
#pragma unroll
        for (int nt = 0; nt < NT; nt++) {
            int col = wn * NTW + nt * 8 + tg * 2;
            float c0 = acc[mt][nt][0], c1 = acc[mt][nt][1];
            float c2 = acc[mt][nt][2], c3 = acc[mt][nt][3];
            if (EPI == 0) {
                __half2 o0 = __floats2half2_rn(fmaxf(c0, 0.f), fmaxf(c1, 0.f));
                __half2 o1 = __floats2half2_rn(fmaxf(c2, 0.f), fmaxf(c3, 0.f));
                *(__half2*)(out16 + (size_t)r0 * 64 + col) = o0;
                *(__half2*)(out16 + (size_t)(r0 + 8) * 64 + col) = o1;
            } else if (EPI == 1) {
                float2 ra = *(const float2*)(res + (size_t)r0 * 128 + col);
                float2 rb = *(const float2*)(res + (size_t)(r0 + 8) * 128 + col);
                float2 o0, o1;
                o0.x = fmaxf(c0 + ra.x, 0.f); o0.y = fmaxf(c1 + ra.y, 0.f);
                o1.x = fmaxf(c2 + rb.x, 0.f); o1.y = fmaxf(c3 + rb.y, 0.f);
                *(float2*)(fout + (size_t)r0 * 128 + col) = o0;
                *(float2*)(fout + (size_t)(r0 + 8) * 128 + col) = o1;
            } else {
                float2 aa = *(const float2*)(res  + (size_t)r0 * 128 + col);
                float2 xa = *(const float2*)(xres + (size_t)r0 * 128 + col);
                float2 ab = *(const float2*)(res  + (size_t)(r0 + 8) * 128 + col);
                float2 xb = *(const float2*)(xres + (size_t)(r0 + 8) * 128 + col);
                float2 o0, o1;
                o0.x = aa.x / (1.f + __expf(-c0)) + xa.x;
                o0.y = aa.y / (1.f + __expf(-c1)) + xa.y;
                o1.x = ab.x / (1.f + __expf(-c2)) + xb.x;
                o1.y = ab.y / (1.f + __expf(-c3)) + xb.y;
                *(float2*)(fout + (size_t)r0 * 128 + col) = o0;
                *(float2*)(fout + (size_t)(r0 + 8) * 128 + col) = o1;
            }
        }
    }
}

// ---------------------------------------------------------------------------
// FUSED up_i + down_{i+1}:
//   h' = relu(T2 @ W2^T + res)   (bf16 3-product, fp32 acc)  -> fout (global)
//   t  = relu(h' @ W1^T)         (fp16 2-product: h' fp16 in smem, W1 fp16 hi/lo)
//        -> out16 (fp16 global, conv input)
// smem: ph1 A1 hi/lo @0 (2*9216), B1 hi/lo @18432 (2*18432)  [0,55296)
//       B2 fp16 hi/lo @55296 (2*17408)                       [55296,90112)
//       A2 fp16 @0 (17408, reuses ph1 region after barrier)
// 90112 B -> 2 CTAs/SM.
// ---------------------------------------------------------------------------
#define UD_SB1 144
#define UD_A1LO 9216
#define UD_B1 18432
#define UD_SB2 272
#define UD_B2 55296
#define UD_SMEM 90112

__global__ __launch_bounds__(256, 2) void k_updown(
    const float* __restrict__ t2,
    const __nv_bfloat16* __restrict__ W2Hp, const __nv_bfloat16* __restrict__ W2Lp,
    const float* __restrict__ res, float* __restrict__ fout,
    const __half* __restrict__ V1Hp, const __half* __restrict__ V1Lp,
    __half* __restrict__ out16)
{
    extern __shared__ char sm[];
    const uint32_t su = smem_u32(sm);
    const int tid  = threadIdx.x;
    const int lane = tid & 31;
    const int w    = tid >> 5;
    const int wm   = w & 1;
    const int wn   = w >> 1;          // 0..3
    const int mbase = wm * 32;
    const int p0   = blockIdx.x * 64;

    // ---- stage A1 (T2 fp32 -> bf16 hi/lo), K=64 ----
    {
        int row = tid >> 2, q = tid & 3;
        const float* src = t2 + (size_t)(p0 + row) * 64 + q * 16;
        char* ah = sm + row * UD_SB1 + q * 32;
        char* al = sm + UD_A1LO + row * UD_SB1 + q * 32;
#pragma unroll
        for (int c = 0; c < 16; c += 8) {
            float4 f0 = *(const float4*)(src + c);
            float4 f1 = *(const float4*)(src + c + 4);
            unsigned h0, h1, h2, h3, l0, l1, l2, l3;
            split2(f0.x, f0.y, h0, l0);
            split2(f0.z, f0.w, h1, l1);
            split2(f1.x, f1.y, h2, l2);
            split2(f1.z, f1.w, h3, l3);
            *(uint4*)(ah + c * 2) = make_uint4(h0, h1, h2, h3);
            *(uint4*)(al + c * 2) = make_uint4(l0, l1, l2, l3);
        }
    }
    // ---- stage B1 (W2 bf16 hi/lo, 128 rows x 64) ----
    {
        int plane = tid >> 7, t = tid & 127;
        const __nv_bfloat16* bs = plane ? W2Lp : W2Hp;
        char* bd = sm + UD_B1 + plane * (128 * UD_SB1);
#pragma unroll
        for (int i = 0; i < 8; i++) {
            int j = t + i * 128;
            int e = j * 8;
            int r = e >> 6, c = e & 63;
            *(uint4*)(bd + r * UD_SB1 + c * 2) = *(const uint4*)(bs + e);
        }
    }
    // ---- stage B2 (W1 fp16 hi/lo, 64 rows x 128) ----
    {
        int plane = tid >> 7, t = tid & 127;
        const __half* bs = plane ? V1Lp : V1Hp;
        char* bd = sm + UD_B2 + plane * 17408;
#pragma unroll
        for (int i = 0; i < 8; i++) {
            int j = t + i * 128;
            int e = j * 8;
            int r = e >> 7, c = e & 127;
            *(uint4*)(bd + r * UD_SB2 + c * 2) = *(const uint4*)(bs + e);
        }
    }
    __syncthreads();

    // ---- phase 1 MMA: 64x128, K=64, bf16 3-product ----
    float acc[2][4][4];
#pragma unroll
    for (int mt = 0; mt < 2; mt++)
#pragma unroll
        for (int nt = 0; nt < 4; nt++)
#pragma unroll
            for (int e = 0; e < 4; e++) acc[mt][nt][e] = 0.f;

    {
        const uint32_t a_ld = su + (uint32_t)(mbase + (lane & 15)) * UD_SB1
                            + (uint32_t)(lane >> 4) * 16;
        const uint32_t b_ld = su + UD_B1 + (uint32_t)(wn * 32 + (lane & 7)) * UD_SB1
                            + (uint32_t)((lane >> 3) & 1) * 16;
#pragma unroll
        for (int ks = 0; ks < 4; ks++) {
            uint32_t ah[2][4], al[2][4];
#pragma unroll
            for (int mt = 0; mt < 2; mt++) {
                ldsm_x4(ah[mt], a_ld + (uint32_t)mt * (16 * UD_SB1) + ks * 32);
                ldsm_x4(al[mt], a_ld + UD_A1LO + (uint32_t)mt * (16 * UD_SB1) + ks * 32);
            }
#pragma unroll
            for (int nt = 0; nt < 4; nt++) {
                uint32_t bh[2], bl[2];
                ldsm_x2(bh, b_ld + (uint32_t)nt * (8 * UD_SB1) + ks * 32);
                ldsm_x2(bl, b_ld + (uint32_t)(128 * UD_SB1)
                            + (uint32_t)nt * (8 * UD_SB1) + ks * 32);
#pragma unroll
                for (int mt = 0; mt < 2; mt++) {
                    mma_bf16(acc[mt][nt], ah[mt], bh);
                    mma_bf16(acc[mt][nt], ah[mt], bl);
                    mma_bf16(acc[mt][nt], al[mt], bh);
                }
            }
        }
    }
    __syncthreads();   // all MMA1 reads done before A2 overwrites ph1 region

    // ---- epilogue 1: h' = relu(acc+res) -> global + fp16 A2 in smem ----
    const int g = lane >> 2, tg = lane & 3;
#pragma unroll
    for (int mt = 0; mt < 2; mt++) {
        int lr0 = mbase + mt * 16 + g;          // local row 0..63
        int r0 = p0 + lr0;
#pragma unroll
        for (int nt = 0; nt < 4; nt++) {
            int col = wn * 32 + nt * 8 + tg * 2;
            float2 ra = *(const float2*)(res + (size_t)r0 * 128 + col);
            float2 rb = *(const float2*)(res + (size_t)(r0 + 8) * 128 + col);
            float2 o0, o1;
            o0.x = fmaxf(acc[mt][nt][0] + ra.x, 0.f);
            o0.y = fmaxf(acc[mt][nt][1] + ra.y, 0.f);
            o1.x = fmaxf(acc[mt][nt][2] + rb.x, 0.f);
            o1.y = fmaxf(acc[mt][nt][3] + rb.y, 0.f);
            *(float2*)(fout + (size_t)r0 * 128 + col) = o0;
            *(float2*)(fout + (size_t)(r0 + 8) * 128 + col) = o1;
            *(__half2*)(sm + lr0 * UD_SB2 + col * 2) = __floats2half2_rn(o0.x, o0.y);
            *(__half2*)(sm + (lr0 + 8) * UD_SB2 + col * 2) = __floats2half2_rn(o1.x, o1.y);
        }
    }
    __syncthreads();

    // ---- phase 2 MMA: t = relu(h' @ W1^T), 64x64, K=128, fp16 2-product ----
    float acc2[2][2][4];
#pragma unroll
    for (int mt = 0; mt < 2; mt++)
#pragma unroll
        for (int nt = 0; nt < 2; nt++)
#pragma unroll
            for (int e = 0; e < 4; e++) acc2[mt][nt][e] = 0.f;

    {
        const uint32_t a_ld = su + (uint32_t)(mbase + (lane & 15)) * UD_SB2
                            + (uint32_t)(lane >> 4) * 16;
        const uint32_t b_ld = su + UD_B2 + (uint32_t)(wn * 16 + (lane & 7)) * UD_SB2
                            + (uint32_t)((lane >> 3) & 1) * 16;
#pragma unroll
        for (int ks = 0; ks < 8; ks++) {
            uint32_t a[2][4];
#pragma unroll
            for (int mt = 0; mt < 2; mt++)
                ldsm_x4(a[mt], a_ld + (uint32_t)mt * (16 * UD_SB2) + ks * 32);
#pragma unroll
            for (int nt = 0; nt < 2; nt++) {
                uint32_t bh[2], bl[2];
                ldsm_x2(bh, b_ld + (uint32_t)nt * (8 * UD_SB2) + ks * 32);
                ldsm_x2(bl, b_ld + 17408u + (uint32_t)nt * (8 * UD_SB2) + ks * 32);
#pragma unroll
                for (int mt = 0; mt < 2; mt++) {
                    mma_f16(acc2[mt][nt], a[mt], bh[0], bh[1]);
                    mma_f16(acc2[mt][nt], a[mt], bl[0], bl[1]);
                }
            }
        }
    }

    // ---- epilogue 2: relu -> fp16 out ----
#pragma unroll
    for (int mt = 0; mt < 2; mt++) {
        int r0 = p0 + mbase + mt * 16 + g;
#pragma unroll
        for (int nt = 0; nt < 2; nt++) {
            int col = wn * 16 + nt * 8 + tg * 2;
            __half2 o0 = __floats2half2_rn(fmaxf(acc2[mt][nt][0], 0.f),
                                           fmaxf(acc2[mt][nt][1], 0.f));
            __half2 o1 = __floats2half2_rn(fmaxf(acc2[mt][nt][2], 0.f),
                                           fmaxf(acc2[mt][nt][3], 0.f));
            *(__half2*)(out16 + (size_t)r0 * 64 + col) = o0;
            *(__half2*)(out16 + (size_t)(r0 + 8) * 64 + col) = o1;
        }
    }
}

// ---------------------------------------------------------------------------
// fp16 HMMA conv v4 (unchanged from round 8 — proven)
// ---------------------------------------------------------------------------
#define ASTRIDE 144
#define STAGE_SZ 46080
#define SB_HI 27648
#define IDX_OFF 92160
#define CONV_SMEM (IDX_OFF + 20736)

__global__ __launch_bounds__(256, 2) void k_conv_mma(
    const __half* __restrict__ T16,
    const __half* __restrict__ WtH, const __half* __restrict__ WtL,
    const int* __restrict__ nbr, float* __restrict__ out)
{
    extern __shared__ char sm[];
    const int tid  = threadIdx.x;
    const int lane = tid & 31;
    const int w    = tid >> 5;
    const int wm   = w & 3;
    const int wn   = w >> 2;
    const int p0   = blockIdx.x * 192;

    const uint32_t su = smem_u32(sm);
    int* idxs = (int*)(sm + IDX_OFF);

    for (int i = tid; i < 27 * 192; i += 256) {
        int p = i / 27;
        int k = i - p * 27;
        idxs[k * 192 + p] = nbr[(size_t)(p0 + p) * 27 + k];
    }

    float acc[3][4][4];
#pragma unroll
    for (int mt = 0; mt < 3; mt++)
#pragma unroll
        for (int nt = 0; nt < 4; nt++)
#pragma unroll
            for (int e = 0; e < 4; e++) acc[mt][nt][e] = 0.f;

    const uint32_t a_ld0 = su + (uint32_t)(wm * 48 + (lane & 15)) * ASTRIDE
                         + (uint32_t)(lane >> 4) * 16;
    const uint32_t b_ld0 = su + SB_HI + (uint32_t)(wn * 32 + (lane & 15)) * ASTRIDE
                         + (uint32_t)(lane >> 4) * 16;

    __syncthreads();

    auto issue_tap = [&](int k, uint32_t sbase) {
#pragma unroll
        for (int i = 0; i < 6; i++) {
            int j = tid + i * 256;
            int row = j >> 3, ch = j & 7;
            int gr = idxs[k * 192 + row];
            uint32_t dst = sbase + (uint32_t)row * ASTRIDE + (uint32_t)ch * 16;
            const void* src = T16 + ((size_t)(gr < 0 ? 0 : gr) * 64 + ch * 8);
            cp_async16(dst, src, gr < 0 ? 0u : 16u);
        }
#pragma unroll
        for (int i = 0; i < 4; i++) {
            int j = tid + i * 256;
            int row = j >> 3, ch = j & 7;
            int plane = row >> 6, brow = row & 63;
            uint32_t dst = sbase + (uint32_t)(SB_HI + plane * 9216)
                         + (uint32_t)brow * ASTRIDE + (uint32_t)ch * 16;
            const __half* src = (plane ? WtL : WtH)
                              + ((size_t)k * 64 + brow) * 64 + ch * 8;
            cp_async16(dst, src, 16u);
        }
        cp_commit();
    };

    issue_tap(0, su);
    issue_tap(1, su + STAGE_SZ);

    for (int k = 0; k < 27; k++) {
        const uint32_t sb = (uint32_t)(k & 1) * STAGE_SZ;
        if (k < 26) cp_wait<1>(); else cp_wait<0>();
        __syncthreads();

        const uint32_t a_ld = a_ld0 + sb;
        const uint32_t b_ld = b_ld0 + sb;
#pragma unroll
        for (int ks = 0; ks < 4; ks++) {
            uint32_t a[3][4];
#pragma unroll
            for (int mt = 0; mt < 3; mt++)
                ldsm_x4(a[mt], a_ld + (uint32_t)mt * (16 * ASTRIDE) + ks * 32);
#pragma unroll
            for (int nt2 = 0; nt2 < 2; nt2++) {
                uint32_t bh[4], bl[4];
                ldsm_x4(bh, b_ld + (uint32_t)nt2 * (16 * ASTRIDE) + ks * 32);
                ldsm_x4(bl, b_ld + 9216 + (uint32_t)nt2 * (16 * ASTRIDE) + ks * 32);
#pragma unroll
                for (int mt = 0; mt < 3; mt++) {
                    mma_f16(acc[mt][nt2 * 2 + 0], a[mt], bh[0], bh[2]);
                    mma_f16(acc[mt][nt2 * 2 + 0], a[mt], bl[0], bl[2]);
                    mma_f16(acc[mt][nt2 * 2 + 1], a[mt], bh[1], bh[3]);
                    mma_f16(acc[mt][nt2 * 2 + 1], a[mt], bl[1], bl[3]);
                }
            }
        }

        if (k < 25) {
            __syncthreads();
            issue_tap(k + 2, su + sb);
        }
    }

    const int g = lane >> 2, tg = lane & 3;
#pragma unroll
    for (int mt = 0; mt < 3; mt++) {
        int row0 = p0 + wm * 48 + mt * 16 + g;
#pragma unroll
        for (int nt = 0; nt < 4; nt++) {
            int col = wn * 32 + nt * 8 + tg * 2;
            float2 o0, o1;
            o0.x = fmaxf(acc[mt][nt][0], 0.f);
            o0.y = fmaxf(acc[mt][nt][1], 0.f);
            o1.x = fmaxf(acc[mt][nt][2], 0.f);
            o1.y = fmaxf(acc[mt][nt][3], 0.f);
            *(float2*)(out + (size_t)row0 * 64 + col) = o0;
            *(float2*)(out + (size_t)(row0 + 8) * 64 + col) = o1;
        }
    }
}

// ---------------------------------------------------------------------------
extern "C" void kernel_launch(void* const* d_in, const int* in_sizes, int n_in,
                              void* d_out, int out_size)
{
    const float* x   = (const float*)d_in[0];
    const float* W1s = (const float*)d_in[1];
    const float* Wks = (const float*)d_in[2];
    const float* W2s = (const float*)d_in[3];
    const float* Wf  = (const float*)d_in[4];
    const int*   nbr = (const int*)d_in[5];
    float* out = (float*)d_out;

    float *A, *B, *T2;
    __half *T16, *WtH, *WtL, *V1H, *V1L;
    __nv_bfloat16 *W1H, *W1L, *W2H, *W2L, *WfH, *WfL;
    cudaGetSymbolAddress((void**)&A,   g_A);
    cudaGetSymbolAddress((void**)&B,   g_B);
    cudaGetSymbolAddress((void**)&T2,  g_T2);
    cudaGetSymbolAddress((void**)&T16, g_T16);
    cudaGetSymbolAddress((void**)&WtH, g_WtH);
    cudaGetSymbolAddress((void**)&WtL, g_WtL);
    cudaGetSymbolAddress((void**)&V1H, g_V1H);
    cudaGetSymbolAddress((void**)&V1L, g_V1L);
    cudaGetSymbolAddress((void**)&W1H, g_W1H);
    cudaGetSymbolAddress((void**)&W1L, g_W1L);
    cudaGetSymbolAddress((void**)&W2H, g_W2H);
    cudaGetSymbolAddress((void**)&W2L, g_W2L);
    cudaGetSymbolAddress((void**)&WfH, g_WfH);
    cudaGetSymbolAddress((void**)&WfL, g_WfL);

    constexpr int SM_DOWN  = (128 * 2 + 16) * (128 + 2 * 64);   // 69632
    constexpr int SM_UP    = (64 * 2 + 16) * (128 + 2 * 128);   // 55296
    constexpr int SM_FINAL = (128 * 2 + 16) * (128 + 2 * 128);  // 104448

    cudaFuncSetAttribute(k_conv_mma, cudaFuncAttributeMaxDynamicSharedMemorySize,
                         CONV_SMEM);
    cudaFuncSetAttribute(k_updown, cudaFuncAttributeMaxDynamicSharedMemorySize,
                         UD_SMEM);
    cudaFuncSetAttribute((const void*)k_lin<128, 64, 0>,
                         cudaFuncAttributeMaxDynamicSharedMemorySize, SM_DOWN);
    cudaFuncSetAttribute((const void*)k_lin<64, 128, 1>,
                         cudaFuncAttributeMaxDynamicSharedMemorySize, SM_UP);
    cudaFuncSetAttribute((const void*)k_lin<128, 128, 2>,
                         cudaFuncAttributeMaxDynamicSharedMemorySize, SM_FINAL);

    k_wsplit<<<dim3(27, 6), 256>>>(Wks, WtH, WtL);
    k_wsplit_lin<<<13, 256>>>(W1s, W2s, Wf, W1H, W1L, V1H, V1L,
                              W2H, W2L, WfH, WfL);

    // branch a: units 0..2
    k_lin<128, 64, 0><<<NBLK64, 256, SM_DOWN>>>(
        x, W1H, W1L, nullptr, nullptr, nullptr, T16);
    for (int i = 0; i < 2; i++) {
        const float* hin = (i == 0) ? x : A;
        k_conv_mma<<<NBLK192, 256, CONV_SMEM>>>(
            T16, WtH + (size_t)i * 27 * 4096, WtL + (size_t)i * 27 * 4096,
            nbr, T2);
        k_updown<<<NBLK64, 256, UD_SMEM>>>(
            T2, W2H + (size_t)i * 8192, W2L + (size_t)i * 8192,
            hin, A, V1H + (size_t)(i + 1) * 8192, V1L + (size_t)(i + 1) * 8192,
            T16);
    }
    k_conv_mma<<<NBLK192, 256, CONV_SMEM>>>(
        T16, WtH + (size_t)2 * 27 * 4096, WtL + (size_t)2 * 27 * 4096, nbr, T2);
    k_lin<64, 128, 1><<<NBLK64, 256, SM_UP>>>(
        T2, W2H + (size_t)2 * 8192, W2L + (size_t)2 * 8192,
        A, nullptr, A, nullptr);

    // branch b: units 3..5
    k_lin<128, 64, 0><<<NBLK64, 256, SM_DOWN>>>(
        x, W1H + (size_t)3 * 8192, W1L + (size_t)3 * 8192,
        nullptr, nullptr, nullptr, T16);
    for (int i = 3; i < 5; i++) {
        const float* hin = (i == 3) ? x : B;
        k_conv_mma<<<NBLK192, 256, CONV_SMEM>>>(
            T16, WtH + (size_t)i * 27 * 4096, WtL + (size_t)i * 27 * 4096,
            nbr, T2);
        k_updown<<<NBLK64, 256, UD_SMEM>>>(
            T2, W2H + (size_t)i * 8192, W2L + (size_t)i * 8192,
            hin, B, V1H + (size_t)(i + 1) * 8192, V1L + (size_t)(i + 1) * 8192,
            T16);
    }
    k_conv_mma<<<NBLK192, 256, CONV_SMEM>>>(
        T16, WtH + (size_t)5 * 27 * 4096, WtL + (size_t)5 * 27 * 4096, nbr, T2);
    k_lin<64, 128, 1><<<NBLK64, 256, SM_UP>>>(
        T2, W2H + (size_t)5 * 8192, W2L + (size_t)5 * 8192,
        B, nullptr, B, nullptr);

    k_lin<128, 128, 2><<<NBLK64, 256, SM_FINAL>>>(
        B, WfH, WfL, A, x, out, nullptr);
}

// round 10
// speedup vs baseline: 4.1916x; 1.3168x over previous
#include <cuda_runtime.h>
#include <cuda_bf16.h>
#include <cuda_fp16.h>
#include <cstdint>

#define NPTS 120000
#define NBLK64 1875
#define NBLK192 625   // 120000 / 192 exactly

// ---------------- scratch (device globals: allocation-free) ----------------
__device__ float g_A[NPTS * 128];
__device__ float g_B[NPTS * 128];
__device__ float g_T2[NPTS * 64];
__device__ __half g_T16[NPTS * 64];                 // conv input activations (fp16)
__device__ __half g_WtH[6 * 27 * 64 * 64];          // conv weights [u][k][j][c] fp16
__device__ __nv_bfloat16 g_W1H[6 * 64 * 128];       // down weights [u][n][k] bf16
__device__ __nv_bfloat16 g_W1L[6 * 64 * 128];
__device__ __half g_V1H[6 * 64 * 128];              // down weights fp16 hi/lo
__device__ __half g_V1L[6 * 64 * 128];
__device__ __nv_bfloat16 g_W2H[6 * 128 * 64];       // up weights [u][n][k]
__device__ __nv_bfloat16 g_W2L[6 * 128 * 64];
__device__ __nv_bfloat16 g_WfH[128 * 128];          // final weights [n][k]
__device__ __nv_bfloat16 g_WfL[128 * 128];

// ---------------- helpers ---------------------------------------------------
__device__ __forceinline__ uint32_t smem_u32(const void* p) {
    uint32_t a;
    asm("{ .reg .u64 t; cvta.to.shared.u64 t, %1; cvt.u32.u64 %0, t; }"
        : "=r"(a) : "l"(p));
    return a;
}
__device__ __forceinline__ void ldsm_x4(uint32_t (&r)[4], uint32_t addr) {
    asm volatile("ldmatrix.sync.aligned.m8n8.x4.shared.b16 {%0,%1,%2,%3}, [%4];"
                 : "=r"(r[0]), "=r"(r[1]), "=r"(r[2]), "=r"(r[3]) : "r"(addr));
}
__device__ __forceinline__ void ldsm_x2(uint32_t (&r)[2], uint32_t addr) {
    asm volatile("ldmatrix.sync.aligned.m8n8.x2.shared.b16 {%0,%1}, [%2];"
                 : "=r"(r[0]), "=r"(r[1]) : "r"(addr));
}
__device__ __forceinline__ void mma_bf16(float* c, const uint32_t* a,
                                         const uint32_t* b) {
    asm volatile(
        "mma.sync.aligned.m16n8k16.row.col.f32.bf16.bf16.f32 "
        "{%0,%1,%2,%3}, {%4,%5,%6,%7}, {%8,%9}, {%0,%1,%2,%3};"
        : "+f"(c[0]), "+f"(c[1]), "+f"(c[2]), "+f"(c[3])
        : "r"(a[0]), "r"(a[1]), "r"(a[2]), "r"(a[3]), "r"(b[0]), "r"(b[1]));
}
__device__ __forceinline__ void mma_f16(float* c, const uint32_t* a,
                                        uint32_t b0, uint32_t b1) {
    asm volatile(
        "mma.sync.aligned.m16n8k16.row.col.f32.f16.f16.f32 "
        "{%0,%1,%2,%3}, {%4,%5,%6,%7}, {%8,%9}, {%0,%1,%2,%3};"
        : "+f"(c[0]), "+f"(c[1]), "+f"(c[2]), "+f"(c[3])
        : "r"(a[0]), "r"(a[1]), "r"(a[2]), "r"(a[3]), "r"(b0), "r"(b1));
}
__device__ __forceinline__ void cp_async16(uint32_t dst, const void* src,
                                           uint32_t src_size) {
    asm volatile("cp.async.ca.shared.global [%0], [%1], 16, %2;"
                 :: "r"(dst), "l"(src), "r"(src_size) : "memory");
}
__device__ __forceinline__ void cp_commit() {
    asm volatile("cp.async.commit_group;" ::: "memory");
}
template <int N>
__device__ __forceinline__ void cp_wait() {
    asm volatile("cp.async.wait_group %0;" :: "n"(N) : "memory");
}
__device__ __forceinline__ unsigned pack_bf2(__nv_bfloat16 a, __nv_bfloat16 b) {
    __nv_bfloat162 t; t.x = a; t.y = b;
    return *reinterpret_cast<unsigned*>(&t);
}
__device__ __forceinline__ void split2(float x, float y, unsigned& h, unsigned& l) {
    __nv_bfloat16 hx = __float2bfloat16(x);
    __nv_bfloat16 hy = __float2bfloat16(y);
    float rx = x - __bfloat162float(hx);
    float ry = y - __bfloat162float(hy);
    h = pack_bf2(hx, hy);
    l = pack_bf2(__float2bfloat16(rx), __float2bfloat16(ry));
}

// ---------------------------------------------------------------------------
// conv weight split+transpose: Wt[u][k][j][c] = Wk[u][k][c][j] as single fp16
// ---------------------------------------------------------------------------
__global__ void k_wsplit(const float* __restrict__ Wks,
                         __half* __restrict__ WtH) {
    int k = blockIdx.x, u = blockIdx.y;
    const float* src = Wks + ((size_t)u * 27 + k) * 4096;
    __half* dh = WtH + ((size_t)u * 27 + k) * 4096;
    for (int e = threadIdx.x; e < 4096; e += blockDim.x) {
        int c = e >> 6, j = e & 63;
        dh[j * 64 + c] = __float2half(src[c * 64 + j]);
    }
}

// ---------------------------------------------------------------------------
// linear weight split+transpose: [k][n] fp32 -> [n][k] bf16 hi/lo (+fp16 for W1)
// ---------------------------------------------------------------------------
__global__ void k_wsplit_lin(const float* __restrict__ W1s,
                             const float* __restrict__ W2s,
                             const float* __restrict__ Wf,
                             __nv_bfloat16* __restrict__ W1H, __nv_bfloat16* __restrict__ W1L,
                             __half* __restrict__ V1H, __half* __restrict__ V1L,
                             __nv_bfloat16* __restrict__ W2H, __nv_bfloat16* __restrict__ W2L,
                             __nv_bfloat16* __restrict__ WfH, __nv_bfloat16* __restrict__ WfL) {
    int b = blockIdx.x;
    if (b < 6) {
        const float* s = W1s + (size_t)b * 8192;
        __nv_bfloat16* dh = W1H + (size_t)b * 8192;
        __nv_bfloat16* dl = W1L + (size_t)b * 8192;
        __half* vh = V1H + (size_t)b * 8192;
        __half* vl = V1L + (size_t)b * 8192;
        for (int e = threadIdx.x; e < 8192; e += blockDim.x) {
            int k = e >> 6, n = e & 63;
            float v = s[e];
            __nv_bfloat16 h = __float2bfloat16(v);
            dh[n * 128 + k] = h;
            dl[n * 128 + k] = __float2bfloat16(v - __bfloat162float(h));
            __half fh = __float2half(v);
            vh[n * 128 + k] = fh;
            vl[n * 128 + k] = __float2half(v - __half2float(fh));
        }
    } else if (b < 12) {
        const float* s = W2s + (size_t)(b - 6) * 8192;
        __nv_bfloat16* dh = W2H + (size_t)(b - 6) * 8192;
        __nv_bfloat16* dl = W2L + (size_t)(b - 6) * 8192;
        for (int e = threadIdx.x; e < 8192; e += blockDim.x) {
            int k = e >> 7, n = e & 127;
            float v = s[e];
            __nv_bfloat16 h = __float2bfloat16(v);
            dh[n * 64 + k] = h;
            dl[n * 64 + k] = __float2bfloat16(v - __bfloat162float(h));
        }
    } else {
        for (int e = threadIdx.x; e < 16384; e += blockDim.x) {
            int k = e >> 7, n = e & 127;
            float v = Wf[e];
            __nv_bfloat16 h = __float2bfloat16(v);
            WfH[n * 128 + k] = h;
            WfL[n * 128 + k] = __float2bfloat16(v - __bfloat162float(h));
        }
    }
}

// ---------------------------------------------------------------------------
// HMMA 1x1 layer, M=64 tiles, 2 CTAs/SM (proven; used for down0/3, up2/5, final)
// ---------------------------------------------------------------------------
template <int K, int N, int EPI>
__global__ __launch_bounds__(256, 2) void k_lin(
    const float* __restrict__ in,
    const __nv_bfloat16* __restrict__ BH, const __nv_bfloat16* __restrict__ BL,
    const float* __restrict__ res, const float* __restrict__ xres,
    float* __restrict__ fout, __half* __restrict__ out16)
{
    constexpr int SB   = K * 2 + 16;
    constexpr int ASZ  = 64 * SB;
    constexpr int BOFF = 2 * ASZ;
    constexpr int NTW  = N / 4;
    constexpr int NT   = NTW / 8;
    constexpr int KS   = K / 16;

    extern __shared__ char sm[];
    const uint32_t su = smem_u32(sm);
    const int tid  = threadIdx.x;
    const int lane = tid & 31;
    const int w    = tid >> 5;
    const int wm   = w & 1;
    const int wn   = w >> 1;
    const int mbase = wm * 32;
    const int p0   = blockIdx.x * 64;

    {
        int row = tid >> 2, q = tid & 3;
        const float* src = in + (size_t)(p0 + row) * K + q * (K / 4);
        char* ah = sm + row * SB + q * (K / 2);
        char* al = sm + ASZ + row * SB + q * (K / 2);
#pragma unroll
        for (int c = 0; c < K / 4; c += 8) {
            float4 f0 = *(const float4*)(src + c);
            float4 f1 = *(const float4*)(src + c + 4);
            unsigned h0, h1, h2, h3, l0, l1, l2, l3;
            split2(f0.x, f0.y, h0, l0);
            split2(f0.z, f0.w, h1, l1);
            split2(f1.x, f1.y, h2, l2);
            split2(f1.z, f1.w, h3, l3);
            *(uint4*)(ah + c * 2) = make_uint4(h0, h1, h2, h3);
            *(uint4*)(al + c * 2) = make_uint4(l0, l1, l2, l3);
        }
    }
    {
        constexpr int ITER = N * K / 1024;
        int plane = tid >> 7, t = tid & 127;
        const __nv_bfloat16* bs = plane ? BL : BH;
        char* bd = sm + BOFF + plane * (N * SB);
#pragma unroll
        for (int i = 0; i < ITER; i++) {
            int j = t + i * 128;
            int e = j * 8;
            int r = e / K, c = e % K;
            *(uint4*)(bd + r * SB + c * 2) = *(const uint4*)(bs + e);
        }
    }
    __syncthreads();

    float acc[2][NT][4];
#pragma unroll
    for (int mt = 0; mt < 2; mt++)
#pragma unroll
        for (int nt = 0; nt < NT; nt++)
#pragma unroll
            for (int e = 0; e < 4; e++) acc[mt][nt][e] = 0.f;

    const uint32_t a_ld = su + (uint32_t)(mbase + (lane & 15)) * SB
                        + (uint32_t)(lane >> 4) * 16;
    const uint32_t b_ld = su + BOFF + (uint32_t)(wn * NTW + (lane & 7)) * SB
                        + (uint32_t)((lane >> 3) & 1) * 16;

#pragma unroll
    for (int ks = 0; ks < KS; ks++) {
        uint32_t ah[2][4], al[2][4];
#pragma unroll
        for (int mt = 0; mt < 2; mt++) {
            ldsm_x4(ah[mt], a_ld + (uint32_t)mt * (16 * SB) + ks * 32);
            ldsm_x4(al[mt], a_ld + ASZ + (uint32_t)mt * (16 * SB) + ks * 32);
        }
#pragma unroll
        for (int nt = 0; nt < NT; nt++) {
            uint32_t bh[2], bl[2];
            ldsm_x2(bh, b_ld + (uint32_t)nt * (8 * SB) + ks * 32);
            ldsm_x2(bl, b_ld + (uint32_t)(N * SB) + (uint32_t)nt * (8 * SB) + ks * 32);
#pragma unroll
            for (int mt = 0; mt < 2; mt++) {
                mma_bf16(acc[mt][nt], ah[mt], bh);
                mma_bf16(acc[mt][nt], ah[mt], bl);
                mma_bf16(acc[mt][nt], al[mt], bh);
            }
        }
    }

    const int g = lane >> 2, tg = lane & 3;
#pragma unroll
    for (int mt = 0; mt < 2; mt++) {
        int r0 = p0 + mbase + mt * 16 + g;
#pragma unroll
        for (int nt = 0; nt < NT; nt++) {
            int col = wn * NTW + nt * 8 + tg * 2;
            float c0 = acc[mt][nt][0], c1 = acc[mt][nt][1];
            float c2 = acc[mt][nt][2], c3 = acc[mt][nt][3];
            if (EPI == 0) {
                __half2 o0 = __floats2half2_rn(fmaxf(c0, 0.f), fmaxf(c1, 0.f));
                __half2 o1 = __floats2half2_rn(fmaxf(c2, 0.f), fmaxf(c3, 0.f));
                *(__half2*)(out16 + (size_t)r0 * 64 + col) = o0;
                *(__half2*)(out16 + (size_t)(r0 + 8) * 64 + col) = o1;
            } else if (EPI == 1) {
                float2 ra = *(const float2*)(res + (size_t)r0 * 128 + col);
                float2 rb = *(const float2*)(res + (size_t)(r0 + 8) * 128 + col);
                float2 o0, o1;
                o0.x = fmaxf(c0 + ra.x, 0.f); o0.y = fmaxf(c1 + ra.y, 0.f);
                o1.x = fmaxf(c2 + rb.x, 0.f); o1.y = fmaxf(c3 + rb.y, 0.f);
                *(float2*)(fout + (size_t)r0 * 128 + col) = o0;
                *(float2*)(fout + (size_t)(r0 + 8) * 128 + col) = o1;
            } else {
                float2 aa = *(const float2*)(res  + (size_t)r0 * 128 + col);
                float2 xa = *(const float2*)(xres + (size_t)r0 * 128 + col);
                float2 ab = *(const float2*)(res  + (size_t)(r0 + 8) * 128 + col);
                float2 xb = *(const float2*)(xres + (size_t)(r0 + 8) * 128 + col);
                float2 o0, o1;
                o0.x = aa.x / (1.f + __expf(-c0)) + xa.x;
                o0.y = aa.y / (1.f + __expf(-c1)) + xa.y;
                o1.x = ab.x / (1.f + __expf(-c2)) + xb.x;
                o1.y = ab.y / (1.f + __expf(-c3)) + xb.y;
                *(float2*)(fout + (size_t)r0 * 128 + col) = o0;
                *(float2*)(fout + (size_t)(r0 + 8) * 128 + col) = o1;
            }
        }
    }
}

// ---------------------------------------------------------------------------
// FUSED up_i + down_{i+1} (unchanged from round 9 — proven)
// ---------------------------------------------------------------------------
#define UD_SB1 144
#define UD_A1LO 9216
#define UD_B1 18432
#define UD_SB2 272
#define UD_B2 55296
#define UD_SMEM 90112

__global__ __launch_bounds__(256, 2) void k_updown(
    const float* __restrict__ t2,
    const __nv_bfloat16* __restrict__ W2Hp, const __nv_bfloat16* __restrict__ W2Lp,
    const float* __restrict__ res, float* __restrict__ fout,
    const __half* __restrict__ V1Hp, const __half* __restrict__ V1Lp,
    __half* __restrict__ out16)
{
    extern __shared__ char sm[];
    const uint32_t su = smem_u32(sm);
    const int tid  = threadIdx.x;
    const int lane = tid & 31;
    const int w    = tid >> 5;
    const int wm   = w & 1;
    const int wn   = w >> 1;
    const int mbase = wm * 32;
    const int p0   = blockIdx.x * 64;

    {
        int row = tid >> 2, q = tid & 3;
        const float* src = t2 + (size_t)(p0 + row) * 64 + q * 16;
        char* ah = sm + row * UD_SB1 + q * 32;
        char* al = sm + UD_A1LO + row * UD_SB1 + q * 32;
#pragma unroll
        for (int c = 0; c < 16; c += 8) {
            float4 f0 = *(const float4*)(src + c);
            float4 f1 = *(const float4*)(src + c + 4);
            unsigned h0, h1, h2, h3, l0, l1, l2, l3;
            split2(f0.x, f0.y, h0, l0);
            split2(f0.z, f0.w, h1, l1);
            split2(f1.x, f1.y, h2, l2);
            split2(f1.z, f1.w, h3, l3);
            *(uint4*)(ah + c * 2) = make_uint4(h0, h1, h2, h3);
            *(uint4*)(al + c * 2) = make_uint4(l0, l1, l2, l3);
        }
    }
    {
        int plane = tid >> 7, t = tid & 127;
        const __nv_bfloat16* bs = plane ? W2Lp : W2Hp;
        char* bd = sm + UD_B1 + plane * (128 * UD_SB1);
#pragma unroll
        for (int i = 0; i < 8; i++) {
            int j = t + i * 128;
            int e = j * 8;
            int r = e >> 6, c = e & 63;
            *(uint4*)(bd + r * UD_SB1 + c * 2) = *(const uint4*)(bs + e);
        }
    }
    {
        int plane = tid >> 7, t = tid & 127;
        const __half* bs = plane ? V1Lp : V1Hp;
        char* bd = sm + UD_B2 + plane * 17408;
#pragma unroll
        for (int i = 0; i < 8; i++) {
            int j = t + i * 128;
            int e = j * 8;
            int r = e >> 7, c = e & 127;
            *(uint4*)(bd + r * UD_SB2 + c * 2) = *(const uint4*)(bs + e);
        }
    }
    __syncthreads();

    float acc[2][4][4];
#pragma unroll
    for (int mt = 0; mt < 2; mt++)
#pragma unroll
        for (int nt = 0; nt < 4; nt++)
#pragma unroll
            for (int e = 0; e < 4; e++) acc[mt][nt][e] = 0.f;

    {
        const uint32_t a_ld = su + (uint32_t)(mbase + (lane & 15)) * UD_SB1
                            + (uint32_t)(lane >> 4) * 16;
        const uint32_t b_ld = su + UD_B1 + (uint32_t)(wn * 32 + (lane & 7)) * UD_SB1
                            + (uint32_t)((lane >> 3) & 1) * 16;
#pragma unroll
        for (int ks = 0; ks < 4; ks++) {
            uint32_t ah[2][4], al[2][4];
#pragma unroll
            for (int mt = 0; mt < 2; mt++) {
                ldsm_x4(ah[mt], a_ld + (uint32_t)mt * (16 * UD_SB1) + ks * 32);
                ldsm_x4(al[mt], a_ld + UD_A1LO + (uint32_t)mt * (16 * UD_SB1) + ks * 32);
            }
#pragma unroll
            for (int nt = 0; nt < 4; nt++) {
                uint32_t bh[2], bl[2];
                ldsm_x2(bh, b_ld + (uint32_t)nt * (8 * UD_SB1) + ks * 32);
                ldsm_x2(bl, b_ld + (uint32_t)(128 * UD_SB1)
                            + (uint32_t)nt * (8 * UD_SB1) + ks * 32);
#pragma unroll
                for (int mt = 0; mt < 2; mt++) {
                    mma_bf16(acc[mt][nt], ah[mt], bh);
                    mma_bf16(acc[mt][nt], ah[mt], bl);
                    mma_bf16(acc[mt][nt], al[mt], bh);
                }
            }
        }
    }
    __syncthreads();

    const int g = lane >> 2, tg = lane & 3;
#pragma unroll
    for (int mt = 0; mt < 2; mt++) {
        int lr0 = mbase + mt * 16 + g;
        int r0 = p0 + lr0;
#pragma unroll
        for (int nt = 0; nt < 4; nt++) {
            int col = wn * 32 + nt * 8 + tg * 2;
            float2 ra = *(const float2*)(res + (size_t)r0 * 128 + col);
            float2 rb = *(const float2*)(res + (size_t)(r0 + 8) * 128 + col);
            float2 o0, o1;
            o0.x = fmaxf(acc[mt][nt][0] + ra.x, 0.f);
            o0.y = fmaxf(acc[mt][nt][1] + ra.y, 0.f);
            o1.x = fmaxf(acc[mt][nt][2] + rb.x, 0.f);
            o1.y = fmaxf(acc[mt][nt][3] + rb.y, 0.f);
            *(float2*)(fout + (size_t)r0 * 128 + col) = o0;
            *(float2*)(fout + (size_t)(r0 + 8) * 128 + col) = o1;
            *(__half2*)(sm + lr0 * UD_SB2 + col * 2) = __floats2half2_rn(o0.x, o0.y);
            *(__half2*)(sm + (lr0 + 8) * UD_SB2 + col * 2) = __floats2half2_rn(o1.x, o1.y);
        }
    }
    __syncthreads();

    float acc2[2][2][4];
#pragma unroll
    for (int mt = 0; mt < 2; mt++)
#pragma unroll
        for (int nt = 0; nt < 2; nt++)
#pragma unroll
            for (int e = 0; e < 4; e++) acc2[mt][nt][e] = 0.f;

    {
        const uint32_t a_ld = su + (uint32_t)(mbase + (lane & 15)) * UD_SB2
                            + (uint32_t)(lane >> 4) * 16;
        const uint32_t b_ld = su + UD_B2 + (uint32_t)(wn * 16 + (lane & 7)) * UD_SB2
                            + (uint32_t)((lane >> 3) & 1) * 16;
#pragma unroll
        for (int ks = 0; ks < 8; ks++) {
            uint32_t a[2][4];
#pragma unroll
            for (int mt = 0; mt < 2; mt++)
                ldsm_x4(a[mt], a_ld + (uint32_t)mt * (16 * UD_SB2) + ks * 32);
#pragma unroll
            for (int nt = 0; nt < 2; nt++) {
                uint32_t bh[2], bl[2];
                ldsm_x2(bh, b_ld + (uint32_t)nt * (8 * UD_SB2) + ks * 32);
                ldsm_x2(bl, b_ld + 17408u + (uint32_t)nt * (8 * UD_SB2) + ks * 32);
#pragma unroll
                for (int mt = 0; mt < 2; mt++) {
                    mma_f16(acc2[mt][nt], a[mt], bh[0], bh[1]);
                    mma_f16(acc2[mt][nt], a[mt], bl[0], bl[1]);
                }
            }
        }
    }

#pragma unroll
    for (int mt = 0; mt < 2; mt++) {
        int r0 = p0 + mbase + mt * 16 + g;
#pragma unroll
        for (int nt = 0; nt < 2; nt++) {
            int col = wn * 16 + nt * 8 + tg * 2;
            __half2 o0 = __floats2half2_rn(fmaxf(acc2[mt][nt][0], 0.f),
                                           fmaxf(acc2[mt][nt][1], 0.f));
            __half2 o1 = __floats2half2_rn(fmaxf(acc2[mt][nt][2], 0.f),
                                           fmaxf(acc2[mt][nt][3], 0.f));
            *(__half2*)(out16 + (size_t)r0 * 64 + col) = o0;
            *(__half2*)(out16 + (size_t)(r0 + 8) * 64 + col) = o1;
        }
    }
}

// ---------------------------------------------------------------------------
// fp16 HMMA conv v5: PURE fp16 (single product), M=192 pts/CTA, 8 warps
// (4 M-bands x 48 rows, 2 N-bands x 32 cols), double-buffered cp.async.
// Per stage (36864B): A @+0 (192*144=27648), B @+27648 (64*144=9216).
// Stage 0 @0, stage 1 @36864, idx @73728 (20736) -> 94464 total, 2 CTAs/SM.
// ---------------------------------------------------------------------------
#define ASTRIDE 144
#define STAGE_SZ 36864
#define SB_B 27648
#define IDX_OFF 73728
#define CONV_SMEM (IDX_OFF + 20736)

__global__ __launch_bounds__(256, 2) void k_conv_mma(
    const __half* __restrict__ T16,
    const __half* __restrict__ WtH,
    const int* __restrict__ nbr, float* __restrict__ out)
{
    extern __shared__ char sm[];
    const int tid  = threadIdx.x;
    const int lane = tid & 31;
    const int w    = tid >> 5;
    const int wm   = w & 3;
    const int wn   = w >> 2;
    const int p0   = blockIdx.x * 192;

    const uint32_t su = smem_u32(sm);
    int* idxs = (int*)(sm + IDX_OFF);

    for (int i = tid; i < 27 * 192; i += 256) {
        int p = i / 27;
        int k = i - p * 27;
        idxs[k * 192 + p] = nbr[(size_t)(p0 + p) * 27 + k];
    }

    float acc[3][4][4];
#pragma unroll
    for (int mt = 0; mt < 3; mt++)
#pragma unroll
        for (int nt = 0; nt < 4; nt++)
#pragma unroll
            for (int e = 0; e < 4; e++) acc[mt][nt][e] = 0.f;

    const uint32_t a_ld0 = su + (uint32_t)(wm * 48 + (lane & 15)) * ASTRIDE
                         + (uint32_t)(lane >> 4) * 16;
    const uint32_t b_ld0 = su + SB_B + (uint32_t)(wn * 32 + (lane & 15)) * ASTRIDE
                         + (uint32_t)(lane >> 4) * 16;

    __syncthreads();   // idxs visible

    // per-tap loads: A = 192 rows x 8 chunks (1536 -> 6 iters),
    //                B = 64 rows x 8 chunks (512 -> 2 iters)
    auto issue_tap = [&](int k, uint32_t sbase) {
#pragma unroll
        for (int i = 0; i < 6; i++) {
            int j = tid + i * 256;
            int row = j >> 3, ch = j & 7;
            int gr = idxs[k * 192 + row];
            uint32_t dst = sbase + (uint32_t)row * ASTRIDE + (uint32_t)ch * 16;
            const void* src = T16 + ((size_t)(gr < 0 ? 0 : gr) * 64 + ch * 8);
            cp_async16(dst, src, gr < 0 ? 0u : 16u);
        }
#pragma unroll
        for (int i = 0; i < 2; i++) {
            int j = tid + i * 256;
            int row = j >> 3, ch = j & 7;     // row 0-63
            uint32_t dst = sbase + (uint32_t)SB_B
                         + (uint32_t)row * ASTRIDE + (uint32_t)ch * 16;
            const __half* src = WtH + ((size_t)k * 64 + row) * 64 + ch * 8;
            cp_async16(dst, src, 16u);
        }
        cp_commit();
    };

    issue_tap(0, su);
    issue_tap(1, su + STAGE_SZ);

    for (int k = 0; k < 27; k++) {
        const uint32_t sb = (uint32_t)(k & 1) * STAGE_SZ;
        if (k < 26) cp_wait<1>(); else cp_wait<0>();
        __syncthreads();

        const uint32_t a_ld = a_ld0 + sb;
        const uint32_t b_ld = b_ld0 + sb;
#pragma unroll
        for (int ks = 0; ks < 4; ks++) {
            uint32_t a[3][4];
#pragma unroll
            for (int mt = 0; mt < 3; mt++)
                ldsm_x4(a[mt], a_ld + (uint32_t)mt * (16 * ASTRIDE) + ks * 32);
#pragma unroll
            for (int nt2 = 0; nt2 < 2; nt2++) {
                uint32_t bh[4];
                ldsm_x4(bh, b_ld + (uint32_t)nt2 * (16 * ASTRIDE) + ks * 32);
#pragma unroll
                for (int mt = 0; mt < 3; mt++) {
                    mma_f16(acc[mt][nt2 * 2 + 0], a[mt], bh[0], bh[2]);
                    mma_f16(acc[mt][nt2 * 2 + 1], a[mt], bh[1], bh[3]);
                }
            }
        }

        if (k < 25) {
            __syncthreads();
            issue_tap(k + 2, su + sb);
        }
    }

    const int g = lane >> 2, tg = lane & 3;
#pragma unroll
    for (int mt = 0; mt < 3; mt++) {
        int row0 = p0 + wm * 48 + mt * 16 + g;
#pragma unroll
        for (int nt = 0; nt < 4; nt++) {
            int col = wn * 32 + nt * 8 + tg * 2;
            float2 o0, o1;
            o0.x = fmaxf(acc[mt][nt][0], 0.f);
            o0.y = fmaxf(acc[mt][nt][1], 0.f);
            o1.x = fmaxf(acc[mt][nt][2], 0.f);
            o1.y = fmaxf(acc[mt][nt][3], 0.f);
            *(float2*)(out + (size_t)row0 * 64 + col) = o0;
            *(float2*)(out + (size_t)(row0 + 8) * 64 + col) = o1;
        }
    }
}

// ---------------------------------------------------------------------------
extern "C" void kernel_launch(void* const* d_in, const int* in_sizes, int n_in,
                              void* d_out, int out_size)
{
    const float* x   = (const float*)d_in[0];
    const float* W1s = (const float*)d_in[1];
    const float* Wks = (const float*)d_in[2];
    const float* W2s = (const float*)d_in[3];
    const float* Wf  = (const float*)d_in[4];
    const int*   nbr = (const int*)d_in[5];
    float* out = (float*)d_out;

    float *A, *B, *T2;
    __half *T16, *WtH, *V1H, *V1L;
    __nv_bfloat16 *W1H, *W1L, *W2H, *W2L, *WfH, *WfL;
    cudaGetSymbolAddress((void**)&A,   g_A);
    cudaGetSymbolAddress((void**)&B,   g_B);
    cudaGetSymbolAddress((void**)&T2,  g_T2);
    cudaGetSymbolAddress((void**)&T16, g_T16);
    cudaGetSymbolAddress((void**)&WtH, g_WtH);
    cudaGetSymbolAddress((void**)&V1H, g_V1H);
    cudaGetSymbolAddress((void**)&V1L, g_V1L);
    cudaGetSymbolAddress((void**)&W1H, g_W1H);
    cudaGetSymbolAddress((void**)&W1L, g_W1L);
    cudaGetSymbolAddress((void**)&W2H, g_W2H);
    cudaGetSymbolAddress((void**)&W2L, g_W2L);
    cudaGetSymbolAddress((void**)&WfH, g_WfH);
    cudaGetSymbolAddress((void**)&WfL, g_WfL);

    constexpr int SM_DOWN  = (128 * 2 + 16) * (128 + 2 * 64);   // 69632
    constexpr int SM_UP    = (64 * 2 + 16) * (128 + 2 * 128);   // 55296
    constexpr int SM_FINAL = (128 * 2 + 16) * (128 + 2 * 128);  // 104448

    cudaFuncSetAttribute(k_conv_mma, cudaFuncAttributeMaxDynamicSharedMemorySize,
                         CONV_SMEM);
    cudaFuncSetAttribute(k_updown, cudaFuncAttributeMaxDynamicSharedMemorySize,
                         UD_SMEM);
    cudaFuncSetAttribute((const void*)k_lin<128, 64, 0>,
                         cudaFuncAttributeMaxDynamicSharedMemorySize, SM_DOWN);
    cudaFuncSetAttribute((const void*)k_lin<64, 128, 1>,
                         cudaFuncAttributeMaxDynamicSharedMemorySize, SM_UP);
    cudaFuncSetAttribute((const void*)k_lin<128, 128, 2>,
                         cudaFuncAttributeMaxDynamicSharedMemorySize, SM_FINAL);

    k_wsplit<<<dim3(27, 6), 256>>>(Wks, WtH);
    k_wsplit_lin<<<13, 256>>>(W1s, W2s, Wf, W1H, W1L, V1H, V1L,
                              W2H, W2L, WfH, WfL);

    // branch a: units 0..2
    k_lin<128, 64, 0><<<NBLK64, 256, SM_DOWN>>>(
        x, W1H, W1L, nullptr, nullptr, nullptr, T16);
    for (int i = 0; i < 2; i++) {
        const float* hin = (i == 0) ? x : A;
        k_conv_mma<<<NBLK192, 256, CONV_SMEM>>>(
            T16, WtH + (size_t)i * 27 * 4096, nbr, T2);
        k_updown<<<NBLK64, 256, UD_SMEM>>>(
            T2, W2H + (size_t)i * 8192, W2L + (size_t)i * 8192,
            hin, A, V1H + (size_t)(i + 1) * 8192, V1L + (size_t)(i + 1) * 8192,
            T16);
    }
    k_conv_mma<<<NBLK192, 256, CONV_SMEM>>>(
        T16, WtH + (size_t)2 * 27 * 4096, nbr, T2);
    k_lin<64, 128, 1><<<NBLK64, 256, SM_UP>>>(
        T2, W2H + (size_t)2 * 8192, W2L + (size_t)2 * 8192,
        A, nullptr, A, nullptr);

    // branch b: units 3..5
    k_lin<128, 64, 0><<<NBLK64, 256, SM_DOWN>>>(
        x, W1H + (size_t)3 * 8192, W1L + (size_t)3 * 8192,
        nullptr, nullptr, nullptr, T16);
    for (int i = 3; i < 5; i++) {
        const float* hin = (i == 3) ? x : B;
        k_conv_mma<<<NBLK192, 256, CONV_SMEM>>>(
            T16, WtH + (size_t)i * 27 * 4096, nbr, T2);
        k_updown<<<NBLK64, 256, UD_SMEM>>>(
            T2, W2H + (size_t)i * 8192, W2L + (size_t)i * 8192,
            hin, B, V1H + (size_t)(i + 1) * 8192, V1L + (size_t)(i + 1) * 8192,
            T16);
    }
    k_conv_mma<<<NBLK192, 256, CONV_SMEM>>>(
        T16, WtH + (size_t)5 * 27 * 4096, nbr, T2);
    k_lin<64, 128, 1><<<NBLK64, 256, SM_UP>>>(
        T2, W2H + (size_t)5 * 8192, W2L + (size_t)5 * 8192,
        B, nullptr, B, nullptr);

    k_lin<128, 128, 2><<<NBLK64, 256, SM_FINAL>>>(
        B, WfH, WfL, A, x, out, nullptr);
}

// round 11
// speedup vs baseline: 4.4118x; 1.0525x over previous
#include <cuda_runtime.h>
#include <cuda_bf16.h>
#include <cuda_fp16.h>
#include <cstdint>

#define NPTS 120000
#define NBLK64 1875
#define NBLK192 625   // 120000 / 192 exactly

// ---------------- scratch (device globals: allocation-free) ----------------
__device__ float g_A[NPTS * 128];
__device__ float g_B[NPTS * 128];
__device__ __half g_T2h[NPTS * 64];                 // conv output (fp16)
__device__ __half g_T16[NPTS * 64];                 // conv input activations (fp16)
__device__ __half g_WtH[6 * 27 * 64 * 64];          // conv weights [u][k][j][c] fp16
__device__ __half g_V1H[6 * 64 * 128];              // down weights [u][n][k] fp16 hi/lo
__device__ __half g_V1L[6 * 64 * 128];
__device__ __half g_V2H[6 * 128 * 64];              // up weights [u][n][k] fp16 hi/lo
__device__ __half g_V2L[6 * 128 * 64];
__device__ __half g_VfH[128 * 128];                 // final weights [n][k] fp16 hi/lo
__device__ __half g_VfL[128 * 128];

// ---------------- helpers ---------------------------------------------------
__device__ __forceinline__ uint32_t smem_u32(const void* p) {
    uint32_t a;
    asm("{ .reg .u64 t; cvta.to.shared.u64 t, %1; cvt.u32.u64 %0, t; }"
        : "=r"(a) : "l"(p));
    return a;
}
__device__ __forceinline__ void ldsm_x4(uint32_t (&r)[4], uint32_t addr) {
    asm volatile("ldmatrix.sync.aligned.m8n8.x4.shared.b16 {%0,%1,%2,%3}, [%4];"
                 : "=r"(r[0]), "=r"(r[1]), "=r"(r[2]), "=r"(r[3]) : "r"(addr));
}
__device__ __forceinline__ void ldsm_x2(uint32_t (&r)[2], uint32_t addr) {
    asm volatile("ldmatrix.sync.aligned.m8n8.x2.shared.b16 {%0,%1}, [%2];"
                 : "=r"(r[0]), "=r"(r[1]) : "r"(addr));
}
__device__ __forceinline__ void mma_f16(float* c, const uint32_t* a,
                                        uint32_t b0, uint32_t b1) {
    asm volatile(
        "mma.sync.aligned.m16n8k16.row.col.f32.f16.f16.f32 "
        "{%0,%1,%2,%3}, {%4,%5,%6,%7}, {%8,%9}, {%0,%1,%2,%3};"
        : "+f"(c[0]), "+f"(c[1]), "+f"(c[2]), "+f"(c[3])
        : "r"(a[0]), "r"(a[1]), "r"(a[2]), "r"(a[3]), "r"(b0), "r"(b1));
}
__device__ __forceinline__ void cp_async16(uint32_t dst, const void* src,
                                           uint32_t src_size) {
    asm volatile("cp.async.ca.shared.global [%0], [%1], 16, %2;"
                 :: "r"(dst), "l"(src), "r"(src_size) : "memory");
}
__device__ __forceinline__ void cp_commit() {
    asm volatile("cp.async.commit_group;" ::: "memory");
}
template <int N>
__device__ __forceinline__ void cp_wait() {
    asm volatile("cp.async.wait_group %0;" :: "n"(N) : "memory");
}
__device__ __forceinline__ unsigned h2u(__half2 h) {
    return *reinterpret_cast<unsigned*>(&h);
}

// ---------------------------------------------------------------------------
// conv weight transpose: Wt[u][k][j][c] = Wk[u][k][c][j] as single fp16
// ---------------------------------------------------------------------------
__global__ void k_wsplit(const float* __restrict__ Wks,
                         __half* __restrict__ WtH) {
    int k = blockIdx.x, u = blockIdx.y;
    const float* src = Wks + ((size_t)u * 27 + k) * 4096;
    __half* dh = WtH + ((size_t)u * 27 + k) * 4096;
    for (int e = threadIdx.x; e < 4096; e += blockDim.x) {
        int c = e >> 6, j = e & 63;
        dh[j * 64 + c] = __float2half(src[c * 64 + j]);
    }
}

// ---------------------------------------------------------------------------
// linear weight split+transpose: [k][n] fp32 -> [n][k] fp16 hi/lo
// blocks 0-5: W1 units; 6-11: W2 units; 12: Wf
// ---------------------------------------------------------------------------
__global__ void k_wsplit_lin(const float* __restrict__ W1s,
                             const float* __restrict__ W2s,
                             const float* __restrict__ Wf,
                             __half* __restrict__ V1H, __half* __restrict__ V1L,
                             __half* __restrict__ V2H, __half* __restrict__ V2L,
                             __half* __restrict__ VfH, __half* __restrict__ VfL) {
    int b = blockIdx.x;
    if (b < 6) {
        const float* s = W1s + (size_t)b * 8192;
        __half* vh = V1H + (size_t)b * 8192;
        __half* vl = V1L + (size_t)b * 8192;
        for (int e = threadIdx.x; e < 8192; e += blockDim.x) {
            int k = e >> 6, n = e & 63;
            float v = s[e];
            __half fh = __float2half(v);
            vh[n * 128 + k] = fh;
            vl[n * 128 + k] = __float2half(v - __half2float(fh));
        }
    } else if (b < 12) {
        const float* s = W2s + (size_t)(b - 6) * 8192;
        __half* vh = V2H + (size_t)(b - 6) * 8192;
        __half* vl = V2L + (size_t)(b - 6) * 8192;
        for (int e = threadIdx.x; e < 8192; e += blockDim.x) {
            int k = e >> 7, n = e & 127;
            float v = s[e];
            __half fh = __float2half(v);
            vh[n * 64 + k] = fh;
            vl[n * 64 + k] = __float2half(v - __half2float(fh));
        }
    } else {
        for (int e = threadIdx.x; e < 16384; e += blockDim.x) {
            int k = e >> 7, n = e & 127;
            float v = Wf[e];
            __half fh = __float2half(v);
            VfH[n * 128 + k] = fh;
            VfL[n * 128 + k] = __float2half(v - __half2float(fh));
        }
    }
}

// ---------------------------------------------------------------------------
// HMMA 1x1 layer, M=64 tiles, fp16 2-product (A single fp16, W fp16 hi/lo).
// EPI 0: in fp32 -> relu -> fp16 plane (out16, stride 64)          [down]
// EPI 1: in16 fp16 -> relu(acc + res) -> fp32 (stride 128)          [up]
// EPI 2: in fp32 -> res * sigmoid(acc) + xres -> fp32 (stride 128)  [final]
// smem: A @0 (64*SB), B hi @64*SB, B lo @64*SB + N*SB.
// ---------------------------------------------------------------------------
template <int K, int N, int EPI>
__global__ __launch_bounds__(256, 2) void k_lin(
    const float* __restrict__ in, const __half* __restrict__ in16,
    const __half* __restrict__ BH, const __half* __restrict__ BL,
    const float* __restrict__ res, const float* __restrict__ xres,
    float* __restrict__ fout, __half* __restrict__ out16)
{
    constexpr int SB   = K * 2 + 16;
    constexpr int BOFF = 64 * SB;
    constexpr int NTW  = N / 4;
    constexpr int NT   = NTW / 8;
    constexpr int KS   = K / 16;

    extern __shared__ char sm[];
    const uint32_t su = smem_u32(sm);
    const int tid  = threadIdx.x;
    const int lane = tid & 31;
    const int w    = tid >> 5;
    const int wm   = w & 1;
    const int wn   = w >> 1;
    const int mbase = wm * 32;
    const int p0   = blockIdx.x * 64;

    // ---- stage A ----
    if (EPI == 1) {
        // fp16 input: 64 rows x K halves, straight 16B copies
        constexpr int CH = 64 * K / 8;
#pragma unroll
        for (int i = 0; i < CH / 256; i++) {
            int j = tid + i * 256;
            int row = j / (K / 8), ch = j % (K / 8);
            *(uint4*)(sm + row * SB + ch * 16) =
                *(const uint4*)(in16 + (size_t)(p0 + row) * K + ch * 8);
        }
    } else {
        int row = tid >> 2, q = tid & 3;
        const float* src = in + (size_t)(p0 + row) * K + q * (K / 4);
        char* ad = sm + row * SB + q * (K / 2);
#pragma unroll
        for (int c = 0; c < K / 4; c += 8) {
            float4 f0 = *(const float4*)(src + c);
            float4 f1 = *(const float4*)(src + c + 4);
            *(uint4*)(ad + c * 2) = make_uint4(
                h2u(__floats2half2_rn(f0.x, f0.y)),
                h2u(__floats2half2_rn(f0.z, f0.w)),
                h2u(__floats2half2_rn(f1.x, f1.y)),
                h2u(__floats2half2_rn(f1.z, f1.w)));
        }
    }
    // ---- stage B (fp16 hi/lo) ----
    {
        constexpr int ITER = N * K / 1024;
        int plane = tid >> 7, t = tid & 127;
        const __half* bs = plane ? BL : BH;
        char* bd = sm + BOFF + plane * (N * SB);
#pragma unroll
        for (int i = 0; i < ITER; i++) {
            int j = t + i * 128;
            int e = j * 8;
            int r = e / K, c = e % K;
            *(uint4*)(bd + r * SB + c * 2) = *(const uint4*)(bs + e);
        }
    }
    __syncthreads();

    float acc[2][NT][4];
#pragma unroll
    for (int mt = 0; mt < 2; mt++)
#pragma unroll
        for (int nt = 0; nt < NT; nt++)
#pragma unroll
            for (int e = 0; e < 4; e++) acc[mt][nt][e] = 0.f;

    const uint32_t a_ld = su + (uint32_t)(mbase + (lane & 15)) * SB
                        + (uint32_t)(lane >> 4) * 16;
    const uint32_t b_ld = su + BOFF + (uint32_t)(wn * NTW + (lane & 7)) * SB
                        + (uint32_t)((lane >> 3) & 1) * 16;

#pragma unroll
    for (int ks = 0; ks < KS; ks++) {
        uint32_t a[2][4];
#pragma unroll
        for (int mt = 0; mt < 2; mt++)
            ldsm_x4(a[mt], a_ld + (uint32_t)mt * (16 * SB) + ks * 32);
#pragma unroll
        for (int nt = 0; nt < NT; nt++) {
            uint32_t bh[2], bl[2];
            ldsm_x2(bh, b_ld + (uint32_t)nt * (8 * SB) + ks * 32);
            ldsm_x2(bl, b_ld + (uint32_t)(N * SB) + (uint32_t)nt * (8 * SB) + ks * 32);
#pragma unroll
            for (int mt = 0; mt < 2; mt++) {
                mma_f16(acc[mt][nt], a[mt], bh[0], bh[1]);
                mma_f16(acc[mt][nt], a[mt], bl[0], bl[1]);
            }
        }
    }

    const int g = lane >> 2, tg = lane & 3;
#pragma unroll
    for (int mt = 0; mt < 2; mt++) {
        int r0 = p0 + mbase + mt * 16 + g;
#pragma unroll
        for (int nt = 0; nt < NT; nt++) {
            int col = wn * NTW + nt * 8 + tg * 2;
            float c0 = acc[mt][nt][0], c1 = acc[mt][nt][1];
            float c2 = acc[mt][nt][2], c3 = acc[mt][nt][3];
            if (EPI == 0) {
                __half2 o0 = __floats2half2_rn(fmaxf(c0, 0.f), fmaxf(c1, 0.f));
                __half2 o1 = __floats2half2_rn(fmaxf(c2, 0.f), fmaxf(c3, 0.f));
                *(__half2*)(out16 + (size_t)r0 * 64 + col) = o0;
                *(__half2*)(out16 + (size_t)(r0 + 8) * 64 + col) = o1;
            } else if (EPI == 1) {
                float2 ra = *(const float2*)(res + (size_t)r0 * 128 + col);
                float2 rb = *(const float2*)(res + (size_t)(r0 + 8) * 128 + col);
                float2 o0, o1;
                o0.x = fmaxf(c0 + ra.x, 0.f); o0.y = fmaxf(c1 + ra.y, 0.f);
                o1.x = fmaxf(c2 + rb.x, 0.f); o1.y = fmaxf(c3 + rb.y, 0.f);
                *(float2*)(fout + (size_t)r0 * 128 + col) = o0;
                *(float2*)(fout + (size_t)(r0 + 8) * 128 + col) = o1;
            } else {
                float2 aa = *(const float2*)(res  + (size_t)r0 * 128 + col);
                float2 xa = *(const float2*)(xres + (size_t)r0 * 128 + col);
                float2 ab = *(const float2*)(res  + (size_t)(r0 + 8) * 128 + col);
                float2 xb = *(const float2*)(xres + (size_t)(r0 + 8) * 128 + col);
                float2 o0, o1;
                o0.x = aa.x / (1.f + __expf(-c0)) + xa.x;
                o0.y = aa.y / (1.f + __expf(-c1)) + xa.y;
                o1.x = ab.x / (1.f + __expf(-c2)) + xb.x;
                o1.y = ab.y / (1.f + __expf(-c3)) + xb.y;
                *(float2*)(fout + (size_t)r0 * 128 + col) = o0;
                *(float2*)(fout + (size_t)(r0 + 8) * 128 + col) = o1;
            }
        }
    }
}

// ---------------------------------------------------------------------------
// FUSED up_i + down_{i+1}, all fp16 2-product:
//   h' = relu(T2h @ W2^T + res) -> fout fp32; t = relu(h' @ W1^T) -> out16
// smem: phase1 A (fp16, 64x144=9216) @0 (inside A2 region)
//       B1 (W2 hi/lo) @17408, planes of 128*144=18432   [17408,54272)
//       B2 (W1 hi/lo) @54272, planes of 64*272=17408    [54272,89088)
//       phase2 A (fp16, 64x272) @0
// ---------------------------------------------------------------------------
#define UD_SB1 144
#define UD_B1 17408
#define UD_SB2 272
#define UD_B2 54272
#define UD_SMEM 89088

__global__ __launch_bounds__(256, 2) void k_updown(
    const __half* __restrict__ t2h,
    const __half* __restrict__ W2Hp, const __half* __restrict__ W2Lp,
    const float* __restrict__ res, float* __restrict__ fout,
    const __half* __restrict__ V1Hp, const __half* __restrict__ V1Lp,
    __half* __restrict__ out16)
{
    extern __shared__ char sm[];
    const uint32_t su = smem_u32(sm);
    const int tid  = threadIdx.x;
    const int lane = tid & 31;
    const int w    = tid >> 5;
    const int wm   = w & 1;
    const int wn   = w >> 1;
    const int mbase = wm * 32;
    const int p0   = blockIdx.x * 64;

    // ---- stage phase1 A (T2h fp16, 64 rows x 64 halves) ----
#pragma unroll
    for (int i = 0; i < 2; i++) {
        int j = tid + i * 256;
        int row = j >> 3, ch = j & 7;
        *(uint4*)(sm + row * UD_SB1 + ch * 16) =
            *(const uint4*)(t2h + (size_t)(p0 + row) * 64 + ch * 8);
    }
    // ---- stage B1 (W2 fp16 hi/lo, 128 rows x 64) ----
    {
        int plane = tid >> 7, t = tid & 127;
        const __half* bs = plane ? W2Lp : W2Hp;
        char* bd = sm + UD_B1 + plane * 18432;
#pragma unroll
        for (int i = 0; i < 8; i++) {
            int j = t + i * 128;
            int e = j * 8;
            int r = e >> 6, c = e & 63;
            *(uint4*)(bd + r * UD_SB1 + c * 2) = *(const uint4*)(bs + e);
        }
    }
    // ---- stage B2 (W1 fp16 hi/lo, 64 rows x 128) ----
    {
        int plane = tid >> 7, t = tid & 127;
        const __half* bs = plane ? V1Lp : V1Hp;
        char* bd = sm + UD_B2 + plane * 17408;
#pragma unroll
        for (int i = 0; i < 8; i++) {
            int j = t + i * 128;
            int e = j * 8;
            int r = e >> 7, c = e & 127;
            *(uint4*)(bd + r * UD_SB2 + c * 2) = *(const uint4*)(bs + e);
        }
    }
    __syncthreads();

    // ---- phase 1 MMA: 64x128, K=64, fp16 2-product ----
    float acc[2][4][4];
#pragma unroll
    for (int mt = 0; mt < 2; mt++)
#pragma unroll
        for (int nt = 0; nt < 4; nt++)
#pragma unroll
            for (int e = 0; e < 4; e++) acc[mt][nt][e] = 0.f;

    {
        const uint32_t a_ld = su + (uint32_t)(mbase + (lane & 15)) * UD_SB1
                            + (uint32_t)(lane >> 4) * 16;
        const uint32_t b_ld = su + UD_B1 + (uint32_t)(wn * 32 + (lane & 7)) * UD_SB1
                            + (uint32_t)((lane >> 3) & 1) * 16;
#pragma unroll
        for (int ks = 0; ks < 4; ks++) {
            uint32_t a[2][4];
#pragma unroll
            for (int mt = 0; mt < 2; mt++)
                ldsm_x4(a[mt], a_ld + (uint32_t)mt * (16 * UD_SB1) + ks * 32);
#pragma unroll
            for (int nt = 0; nt < 4; nt++) {
                uint32_t bh[2], bl[2];
                ldsm_x2(bh, b_ld + (uint32_t)nt * (8 * UD_SB1) + ks * 32);
                ldsm_x2(bl, b_ld + 18432u + (uint32_t)nt * (8 * UD_SB1) + ks * 32);
#pragma unroll
                for (int mt = 0; mt < 2; mt++) {
                    mma_f16(acc[mt][nt], a[mt], bh[0], bh[1]);
                    mma_f16(acc[mt][nt], a[mt], bl[0], bl[1]);
                }
            }
        }
    }
    __syncthreads();   // phase1 A reads done before A2 overwrites [0,17408)

    // ---- epilogue 1: h' = relu(acc+res) -> fp32 global + fp16 A2 smem ----
    const int g = lane >> 2, tg = lane & 3;
#pragma unroll
    for (int mt = 0; mt < 2; mt++) {
        int lr0 = mbase + mt * 16 + g;
        int r0 = p0 + lr0;
#pragma unroll
        for (int nt = 0; nt < 4; nt++) {
            int col = wn * 32 + nt * 8 + tg * 2;
            float2 ra = *(const float2*)(res + (size_t)r0 * 128 + col);
            float2 rb = *(const float2*)(res + (size_t)(r0 + 8) * 128 + col);
            float2 o0, o1;
            o0.x = fmaxf(acc[mt][nt][0] + ra.x, 0.f);
            o0.y = fmaxf(acc[mt][nt][1] + ra.y, 0.f);
            o1.x = fmaxf(acc[mt][nt][2] + rb.x, 0.f);
            o1.y = fmaxf(acc[mt][nt][3] + rb.y, 0.f);
            *(float2*)(fout + (size_t)r0 * 128 + col) = o0;
            *(float2*)(fout + (size_t)(r0 + 8) * 128 + col) = o1;
            *(__half2*)(sm + lr0 * UD_SB2 + col * 2) = __floats2half2_rn(o0.x, o0.y);
            *(__half2*)(sm + (lr0 + 8) * UD_SB2 + col * 2) = __floats2half2_rn(o1.x, o1.y);
        }
    }
    __syncthreads();

    // ---- phase 2 MMA: t = relu(h' @ W1^T), 64x64, K=128, fp16 2-product ----
    float acc2[2][2][4];
#pragma unroll
    for (int mt = 0; mt < 2; mt++)
#pragma unroll
        for (int nt = 0; nt < 2; nt++)
#pragma unroll
            for (int e = 0; e < 4; e++) acc2[mt][nt][e] = 0.f;

    {
        const uint32_t a_ld = su + (uint32_t)(mbase + (lane & 15)) * UD_SB2
                            + (uint32_t)(lane >> 4) * 16;
        const uint32_t b_ld = su + UD_B2 + (uint32_t)(wn * 16 + (lane & 7)) * UD_SB2
                            + (uint32_t)((lane >> 3) & 1) * 16;
#pragma unroll
        for (int ks = 0; ks < 8; ks++) {
            uint32_t a[2][4];
#pragma unroll
            for (int mt = 0; mt < 2; mt++)
                ldsm_x4(a[mt], a_ld + (uint32_t)mt * (16 * UD_SB2) + ks * 32);
#pragma unroll
            for (int nt = 0; nt < 2; nt++) {
                uint32_t bh[2], bl[2];
                ldsm_x2(bh, b_ld + (uint32_t)nt * (8 * UD_SB2) + ks * 32);
                ldsm_x2(bl, b_ld + 17408u + (uint32_t)nt * (8 * UD_SB2) + ks * 32);
#pragma unroll
                for (int mt = 0; mt < 2; mt++) {
                    mma_f16(acc2[mt][nt], a[mt], bh[0], bh[1]);
                    mma_f16(acc2[mt][nt], a[mt], bl[0], bl[1]);
                }
            }
        }
    }

#pragma unroll
    for (int mt = 0; mt < 2; mt++) {
        int r0 = p0 + mbase + mt * 16 + g;
#pragma unroll
        for (int nt = 0; nt < 2; nt++) {
            int col = wn * 16 + nt * 8 + tg * 2;
            __half2 o0 = __floats2half2_rn(fmaxf(acc2[mt][nt][0], 0.f),
                                           fmaxf(acc2[mt][nt][1], 0.f));
            __half2 o1 = __floats2half2_rn(fmaxf(acc2[mt][nt][2], 0.f),
                                           fmaxf(acc2[mt][nt][3], 0.f));
            *(__half2*)(out16 + (size_t)r0 * 64 + col) = o0;
            *(__half2*)(out16 + (size_t)(r0 + 8) * 64 + col) = o1;
        }
    }
}

// ---------------------------------------------------------------------------
// fp16 HMMA conv v5 (round-10 proven) — now writes T2 as fp16.
// ---------------------------------------------------------------------------
#define ASTRIDE 144
#define STAGE_SZ 36864
#define SB_B 27648
#define IDX_OFF 73728
#define CONV_SMEM (IDX_OFF + 20736)

__global__ __launch_bounds__(256, 2) void k_conv_mma(
    const __half* __restrict__ T16,
    const __half* __restrict__ WtH,
    const int* __restrict__ nbr, __half* __restrict__ outh)
{
    extern __shared__ char sm[];
    const int tid  = threadIdx.x;
    const int lane = tid & 31;
    const int w    = tid >> 5;
    const int wm   = w & 3;
    const int wn   = w >> 2;
    const int p0   = blockIdx.x * 192;

    const uint32_t su = smem_u32(sm);
    int* idxs = (int*)(sm + IDX_OFF);

    for (int i = tid; i < 27 * 192; i += 256) {
        int p = i / 27;
        int k = i - p * 27;
        idxs[k * 192 + p] = nbr[(size_t)(p0 + p) * 27 + k];
    }

    float acc[3][4][4];
#pragma unroll
    for (int mt = 0; mt < 3; mt++)
#pragma unroll
        for (int nt = 0; nt < 4; nt++)
#pragma unroll
            for (int e = 0; e < 4; e++) acc[mt][nt][e] = 0.f;

    const uint32_t a_ld0 = su + (uint32_t)(wm * 48 + (lane & 15)) * ASTRIDE
                         + (uint32_t)(lane >> 4) * 16;
    const uint32_t b_ld0 = su + SB_B + (uint32_t)(wn * 32 + (lane & 15)) * ASTRIDE
                         + (uint32_t)(lane >> 4) * 16;

    __syncthreads();

    auto issue_tap = [&](int k, uint32_t sbase) {
#pragma unroll
        for (int i = 0; i < 6; i++) {
            int j = tid + i * 256;
            int row = j >> 3, ch = j & 7;
            int gr = idxs[k * 192 + row];
            uint32_t dst = sbase + (uint32_t)row * ASTRIDE + (uint32_t)ch * 16;
            const void* src = T16 + ((size_t)(gr < 0 ? 0 : gr) * 64 + ch * 8);
            cp_async16(dst, src, gr < 0 ? 0u : 16u);
        }
#pragma unroll
        for (int i = 0; i < 2; i++) {
            int j = tid + i * 256;
            int row = j >> 3, ch = j & 7;
            uint32_t dst = sbase + (uint32_t)SB_B
                         + (uint32_t)row * ASTRIDE + (uint32_t)ch * 16;
            const __half* src = WtH + ((size_t)k * 64 + row) * 64 + ch * 8;
            cp_async16(dst, src, 16u);
        }
        cp_commit();
    };

    issue_tap(0, su);
    issue_tap(1, su + STAGE_SZ);

    for (int k = 0; k < 27; k++) {
        const uint32_t sb = (uint32_t)(k & 1) * STAGE_SZ;
        if (k < 26) cp_wait<1>(); else cp_wait<0>();
        __syncthreads();

        const uint32_t a_ld = a_ld0 + sb;
        const uint32_t b_ld = b_ld0 + sb;
#pragma unroll
        for (int ks = 0; ks < 4; ks++) {
            uint32_t a[3][4];
#pragma unroll
            for (int mt = 0; mt < 3; mt++)
                ldsm_x4(a[mt], a_ld + (uint32_t)mt * (16 * ASTRIDE) + ks * 32);
#pragma unroll
            for (int nt2 = 0; nt2 < 2; nt2++) {
                uint32_t bh[4];
                ldsm_x4(bh, b_ld + (uint32_t)nt2 * (16 * ASTRIDE) + ks * 32);
#pragma unroll
                for (int mt = 0; mt < 3; mt++) {
                    mma_f16(acc[mt][nt2 * 2 + 0], a[mt], bh[0], bh[2]);
                    mma_f16(acc[mt][nt2 * 2 + 1], a[mt], bh[1], bh[3]);
                }
            }
        }

        if (k < 25) {
            __syncthreads();
            issue_tap(k + 2, su + sb);
        }
    }

    const int g = lane >> 2, tg = lane & 3;
#pragma unroll
    for (int mt = 0; mt < 3; mt++) {
        int row0 = p0 + wm * 48 + mt * 16 + g;
#pragma unroll
        for (int nt = 0; nt < 4; nt++) {
            int col = wn * 32 + nt * 8 + tg * 2;
            __half2 o0 = __floats2half2_rn(fmaxf(acc[mt][nt][0], 0.f),
                                           fmaxf(acc[mt][nt][1], 0.f));
            __half2 o1 = __floats2half2_rn(fmaxf(acc[mt][nt][2], 0.f),
                                           fmaxf(acc[mt][nt][3], 0.f));
            *(__half2*)(outh + (size_t)row0 * 64 + col) = o0;
            *(__half2*)(outh + (size_t)(row0 + 8) * 64 + col) = o1;
        }
    }
}

// ---------------------------------------------------------------------------
extern "C" void kernel_launch(void* const* d_in, const int* in_sizes, int n_in,
                              void* d_out, int out_size)
{
    const float* x   = (const float*)d_in[0];
    const float* W1s = (const float*)d_in[1];
    const float* Wks = (const float*)d_in[2];
    const float* W2s = (const float*)d_in[3];
    const float* Wf  = (const float*)d_in[4];
    const int*   nbr = (const int*)d_in[5];
    float* out = (float*)d_out;

    float *A, *B;
    __half *T2h, *T16, *WtH, *V1H, *V1L, *V2H, *V2L, *VfH, *VfL;
    cudaGetSymbolAddress((void**)&A,   g_A);
    cudaGetSymbolAddress((void**)&B,   g_B);
    cudaGetSymbolAddress((void**)&T2h, g_T2h);
    cudaGetSymbolAddress((void**)&T16, g_T16);
    cudaGetSymbolAddress((void**)&WtH, g_WtH);
    cudaGetSymbolAddress((void**)&V1H, g_V1H);
    cudaGetSymbolAddress((void**)&V1L, g_V1L);
    cudaGetSymbolAddress((void**)&V2H, g_V2H);
    cudaGetSymbolAddress((void**)&V2L, g_V2L);
    cudaGetSymbolAddress((void**)&VfH, g_VfH);
    cudaGetSymbolAddress((void**)&VfL, g_VfL);

    constexpr int SM_DOWN  = 64 * 272 + 2 * 64 * 272;    // 52224
    constexpr int SM_UP    = 64 * 144 + 2 * 128 * 144;   // 46080
    constexpr int SM_FINAL = 64 * 272 + 2 * 128 * 272;   // 87040

    cudaFuncSetAttribute(k_conv_mma, cudaFuncAttributeMaxDynamicSharedMemorySize,
                         CONV_SMEM);
    cudaFuncSetAttribute(k_updown, cudaFuncAttributeMaxDynamicSharedMemorySize,
                         UD_SMEM);
    cudaFuncSetAttribute((const void*)k_lin<128, 64, 0>,
                         cudaFuncAttributeMaxDynamicSharedMemorySize, SM_DOWN);
    cudaFuncSetAttribute((const void*)k_lin<64, 128, 1>,
                         cudaFuncAttributeMaxDynamicSharedMemorySize, SM_UP);
    cudaFuncSetAttribute((const void*)k_lin<128, 128, 2>,
                         cudaFuncAttributeMaxDynamicSharedMemorySize, SM_FINAL);

    k_wsplit<<<dim3(27, 6), 256>>>(Wks, WtH);
    k_wsplit_lin<<<13, 256>>>(W1s, W2s, Wf, V1H, V1L, V2H, V2L, VfH, VfL);

    // branch a: units 0..2
    k_lin<128, 64, 0><<<NBLK64, 256, SM_DOWN>>>(
        x, nullptr, V1H, V1L, nullptr, nullptr, nullptr, T16);
    for (int i = 0; i < 2; i++) {
        const float* hin = (i == 0) ? x : A;
        k_conv_mma<<<NBLK192, 256, CONV_SMEM>>>(
            T16, WtH + (size_t)i * 27 * 4096, nbr, T2h);
        k_updown<<<NBLK64, 256, UD_SMEM>>>(
            T2h, V2H + (size_t)i * 8192, V2L + (size_t)i * 8192,
            hin, A, V1H + (size_t)(i + 1) * 8192, V1L + (size_t)(i + 1) * 8192,
            T16);
    }
    k_conv_mma<<<NBLK192, 256, CONV_SMEM>>>(
        T16, WtH + (size_t)2 * 27 * 4096, nbr, T2h);
    k_lin<64, 128, 1><<<NBLK64, 256, SM_UP>>>(
        nullptr, T2h, V2H + (size_t)2 * 8192, V2L + (size_t)2 * 8192,
        A, nullptr, A, nullptr);

    // branch b: units 3..5
    k_lin<128, 64, 0><<<NBLK64, 256, SM_DOWN>>>(
        x, nullptr, V1H + (size_t)3 * 8192, V1L + (size_t)3 * 8192,
        nullptr, nullptr, nullptr, T16);
    for (int i = 3; i < 5; i++) {
        const float* hin = (i == 3) ? x : B;
        k_conv_mma<<<NBLK192, 256, CONV_SMEM>>>(
            T16, WtH + (size_t)i * 27 * 4096, nbr, T2h);
        k_updown<<<NBLK64, 256, UD_SMEM>>>(
            T2h, V2H + (size_t)i * 8192, V2L + (size_t)i * 8192,
            hin, B, V1H + (size_t)(i + 1) * 8192, V1L + (size_t)(i + 1) * 8192,
            T16);
    }
    k_conv_mma<<<NBLK192, 256, CONV_SMEM>>>(
        T16, WtH + (size_t)5 * 27 * 4096, nbr, T2h);
    k_lin<64, 128, 1><<<NBLK64, 256, SM_UP>>>(
        nullptr, T2h, V2H + (size_t)5 * 8192, V2L + (size_t)5 * 8192,
        B, nullptr, B, nullptr);

    k_lin<128, 128, 2><<<NBLK64, 256, SM_FINAL>>>(
        B, nullptr, VfH, VfL, A, x, out, nullptr);
}

// round 12
// speedup vs baseline: 4.5962x; 1.0418x over previous
#include <cuda_runtime.h>
#include <cuda_bf16.h>
#include <cuda_fp16.h>
#include <cstdint>

#define NPTS 120000
#define NBLK64 1875
#define NBLK192 625   // 120000 / 192 exactly

// ---------------- scratch (device globals: allocation-free) ----------------
__device__ float g_A[NPTS * 128];
__device__ float g_B[NPTS * 128];
__device__ __half g_T2a[NPTS * 64];                 // conv output (fp16), branch a
__device__ __half g_T2b[NPTS * 64];                 // branch b
__device__ __half g_T16a[NPTS * 64];                // conv input (fp16), branch a
__device__ __half g_T16b[NPTS * 64];                // branch b
__device__ __half g_WtH[6 * 27 * 64 * 64];          // conv weights [u][k][j][c] fp16
__device__ __half g_V1H[6 * 64 * 128];              // down weights [u][n][k] fp16 hi/lo
__device__ __half g_V1L[6 * 64 * 128];
__device__ __half g_V2H[6 * 128 * 64];              // up weights [u][n][k] fp16 hi/lo
__device__ __half g_V2L[6 * 128 * 64];
__device__ __half g_VfH[128 * 128];                 // final weights [n][k] fp16 hi/lo
__device__ __half g_VfL[128 * 128];

// ---------------- helpers ---------------------------------------------------
__device__ __forceinline__ uint32_t smem_u32(const void* p) {
    uint32_t a;
    asm("{ .reg .u64 t; cvta.to.shared.u64 t, %1; cvt.u32.u64 %0, t; }"
        : "=r"(a) : "l"(p));
    return a;
}
__device__ __forceinline__ void ldsm_x4(uint32_t (&r)[4], uint32_t addr) {
    asm volatile("ldmatrix.sync.aligned.m8n8.x4.shared.b16 {%0,%1,%2,%3}, [%4];"
                 : "=r"(r[0]), "=r"(r[1]), "=r"(r[2]), "=r"(r[3]) : "r"(addr));
}
__device__ __forceinline__ void ldsm_x2(uint32_t (&r)[2], uint32_t addr) {
    asm volatile("ldmatrix.sync.aligned.m8n8.x2.shared.b16 {%0,%1}, [%2];"
                 : "=r"(r[0]), "=r"(r[1]) : "r"(addr));
}
__device__ __forceinline__ void mma_f16(float* c, const uint32_t* a,
                                        uint32_t b0, uint32_t b1) {
    asm volatile(
        "mma.sync.aligned.m16n8k16.row.col.f32.f16.f16.f32 "
        "{%0,%1,%2,%3}, {%4,%5,%6,%7}, {%8,%9}, {%0,%1,%2,%3};"
        : "+f"(c[0]), "+f"(c[1]), "+f"(c[2]), "+f"(c[3])
        : "r"(a[0]), "r"(a[1]), "r"(a[2]), "r"(a[3]), "r"(b0), "r"(b1));
}
__device__ __forceinline__ void cp_async16(uint32_t dst, const void* src,
                                           uint32_t src_size) {
    asm volatile("cp.async.ca.shared.global [%0], [%1], 16, %2;"
                 :: "r"(dst), "l"(src), "r"(src_size) : "memory");
}
__device__ __forceinline__ void cp_commit() {
    asm volatile("cp.async.commit_group;" ::: "memory");
}
template <int N>
__device__ __forceinline__ void cp_wait() {
    asm volatile("cp.async.wait_group %0;" :: "n"(N) : "memory");
}
__device__ __forceinline__ unsigned h2u(__half2 h) {
    return *reinterpret_cast<unsigned*>(&h);
}

// ---------------------------------------------------------------------------
// conv weight transpose: Wt[u][k][j][c] = Wk[u][k][c][j] as single fp16
// ---------------------------------------------------------------------------
__global__ void k_wsplit(const float* __restrict__ Wks,
                         __half* __restrict__ WtH) {
    int k = blockIdx.x, u = blockIdx.y;
    const float* src = Wks + ((size_t)u * 27 + k) * 4096;
    __half* dh = WtH + ((size_t)u * 27 + k) * 4096;
    for (int e = threadIdx.x; e < 4096; e += blockDim.x) {
        int c = e >> 6, j = e & 63;
        dh[j * 64 + c] = __float2half(src[c * 64 + j]);
    }
}

// ---------------------------------------------------------------------------
// linear weight split+transpose: [k][n] fp32 -> [n][k] fp16 hi/lo
// ---------------------------------------------------------------------------
__global__ void k_wsplit_lin(const float* __restrict__ W1s,
                             const float* __restrict__ W2s,
                             const float* __restrict__ Wf,
                             __half* __restrict__ V1H, __half* __restrict__ V1L,
                             __half* __restrict__ V2H, __half* __restrict__ V2L,
                             __half* __restrict__ VfH, __half* __restrict__ VfL) {
    int b = blockIdx.x;
    if (b < 6) {
        const float* s = W1s + (size_t)b * 8192;
        __half* vh = V1H + (size_t)b * 8192;
        __half* vl = V1L + (size_t)b * 8192;
        for (int e = threadIdx.x; e < 8192; e += blockDim.x) {
            int k = e >> 6, n = e & 63;
            float v = s[e];
            __half fh = __float2half(v);
            vh[n * 128 + k] = fh;
            vl[n * 128 + k] = __float2half(v - __half2float(fh));
        }
    } else if (b < 12) {
        const float* s = W2s + (size_t)(b - 6) * 8192;
        __half* vh = V2H + (size_t)(b - 6) * 8192;
        __half* vl = V2L + (size_t)(b - 6) * 8192;
        for (int e = threadIdx.x; e < 8192; e += blockDim.x) {
            int k = e >> 7, n = e & 127;
            float v = s[e];
            __half fh = __float2half(v);
            vh[n * 64 + k] = fh;
            vl[n * 64 + k] = __float2half(v - __half2float(fh));
        }
    } else {
        for (int e = threadIdx.x; e < 16384; e += blockDim.x) {
            int k = e >> 7, n = e & 127;
            float v = Wf[e];
            __half fh = __float2half(v);
            VfH[n * 128 + k] = fh;
            VfL[n * 128 + k] = __float2half(v - __half2float(fh));
        }
    }
}

// ---------------------------------------------------------------------------
// HMMA 1x1 layer, M=64 tiles, fp16 2-product, DUAL-BRANCH (grid may be 2x):
// blocks [0, NBLK64) use set a; [NBLK64, 2*NBLK64) use set b.
// EPI 0: in fp32 -> relu -> fp16 (out16)          [down]
// EPI 1: in16 fp16 -> relu(acc+res) -> fp32       [up]
// EPI 2: in fp32 -> res*sigmoid(acc)+xres -> fp32 [final; launch grid NBLK64]
// ---------------------------------------------------------------------------
template <int K, int N, int EPI>
__global__ __launch_bounds__(256, 2) void k_lin(
    const float* in_a, const __half* in16_a,
    const __half* BHa, const __half* BLa,
    const float* res_a, const float* xres_a,
    float* fout_a, __half* out16_a,
    const float* in_b, const __half* in16_b,
    const __half* BHb, const __half* BLb,
    const float* res_b, const float* xres_b,
    float* fout_b, __half* out16_b)
{
    constexpr int SB   = K * 2 + 16;
    constexpr int BOFF = 64 * SB;
    constexpr int NTW  = N / 4;
    constexpr int NT   = NTW / 8;
    constexpr int KS   = K / 16;

    extern __shared__ char sm[];
    const uint32_t su = smem_u32(sm);
    const int tid  = threadIdx.x;
    const int lane = tid & 31;
    const int w    = tid >> 5;
    const int wm   = w & 1;
    const int wn   = w >> 1;
    const int mbase = wm * 32;

    const int bid = blockIdx.x;
    const bool sel = bid >= NBLK64;
    const int p0 = (sel ? bid - NBLK64 : bid) * 64;
    const float*  in    = sel ? in_b    : in_a;
    const __half* in16  = sel ? in16_b  : in16_a;
    const __half* BH    = sel ? BHb     : BHa;
    const __half* BL    = sel ? BLb     : BLa;
    const float*  res   = sel ? res_b   : res_a;
    const float*  xres  = sel ? xres_b  : xres_a;
    float*        fout  = sel ? fout_b  : fout_a;
    __half*       out16 = sel ? out16_b : out16_a;

    // ---- stage A ----
    if (EPI == 1) {
        constexpr int CH = 64 * K / 8;
#pragma unroll
        for (int i = 0; i < CH / 256; i++) {
            int j = tid + i * 256;
            int row = j / (K / 8), ch = j % (K / 8);
            *(uint4*)(sm + row * SB + ch * 16) =
                *(const uint4*)(in16 + (size_t)(p0 + row) * K + ch * 8);
        }
    } else {
        int row = tid >> 2, q = tid & 3;
        const float* src = in + (size_t)(p0 + row) * K + q * (K / 4);
        char* ad = sm + row * SB + q * (K / 2);
#pragma unroll
        for (int c = 0; c < K / 4; c += 8) {
            float4 f0 = *(const float4*)(src + c);
            float4 f1 = *(const float4*)(src + c + 4);
            *(uint4*)(ad + c * 2) = make_uint4(
                h2u(__floats2half2_rn(f0.x, f0.y)),
                h2u(__floats2half2_rn(f0.z, f0.w)),
                h2u(__floats2half2_rn(f1.x, f1.y)),
                h2u(__floats2half2_rn(f1.z, f1.w)));
        }
    }
    // ---- stage B (fp16 hi/lo) ----
    {
        constexpr int ITER = N * K / 1024;
        int plane = tid >> 7, t = tid & 127;
        const __half* bs = plane ? BL : BH;
        char* bd = sm + BOFF + plane * (N * SB);
#pragma unroll
        for (int i = 0; i < ITER; i++) {
            int j = t + i * 128;
            int e = j * 8;
            int r = e / K, c = e % K;
            *(uint4*)(bd + r * SB + c * 2) = *(const uint4*)(bs + e);
        }
    }
    __syncthreads();

    float acc[2][NT][4];
#pragma unroll
    for (int mt = 0; mt < 2; mt++)
#pragma unroll
        for (int nt = 0; nt < NT; nt++)
#pragma unroll
            for (int e = 0; e < 4; e++) acc[mt][nt][e] = 0.f;

    const uint32_t a_ld = su + (uint32_t)(mbase + (lane & 15)) * SB
                        + (uint32_t)(lane >> 4) * 16;
    const uint32_t b_ld = su + BOFF + (uint32_t)(wn * NTW + (lane & 7)) * SB
                        + (uint32_t)((lane >> 3) & 1) * 16;

#pragma unroll
    for (int ks = 0; ks < KS; ks++) {
        uint32_t a[2][4];
#pragma unroll
        for (int mt = 0; mt < 2; mt++)
            ldsm_x4(a[mt], a_ld + (uint32_t)mt * (16 * SB) + ks * 32);
#pragma unroll
        for (int nt = 0; nt < NT; nt++) {
            uint32_t bh[2], bl[2];
            ldsm_x2(bh, b_ld + (uint32_t)nt * (8 * SB) + ks * 32);
            ldsm_x2(bl, b_ld + (uint32_t)(N * SB) + (uint32_t)nt * (8 * SB) + ks * 32);
#pragma unroll
            for (int mt = 0; mt < 2; mt++) {
                mma_f16(acc[mt][nt], a[mt], bh[0], bh[1]);
                mma_f16(acc[mt][nt], a[mt], bl[0], bl[1]);
            }
        }
    }

    const int g = lane >> 2, tg = lane & 3;
#pragma unroll
    for (int mt = 0; mt < 2; mt++) {
        int r0 = p0 + mbase + mt * 16 + g;
#pragma unroll
        for (int nt = 0; nt < NT; nt++) {
            int col = wn * NTW + nt * 8 + tg * 2;
            float c0 = acc[mt][nt][0], c1 = acc[mt][nt][1];
            float c2 = acc[mt][nt][2], c3 = acc[mt][nt][3];
            if (EPI == 0) {
                __half2 o0 = __floats2half2_rn(fmaxf(c0, 0.f), fmaxf(c1, 0.f));
                __half2 o1 = __floats2half2_rn(fmaxf(c2, 0.f), fmaxf(c3, 0.f));
                *(__half2*)(out16 + (size_t)r0 * 64 + col) = o0;
                *(__half2*)(out16 + (size_t)(r0 + 8) * 64 + col) = o1;
            } else if (EPI == 1) {
                float2 ra = *(const float2*)(res + (size_t)r0 * 128 + col);
                float2 rb = *(const float2*)(res + (size_t)(r0 + 8) * 128 + col);
                float2 o0, o1;
                o0.x = fmaxf(c0 + ra.x, 0.f); o0.y = fmaxf(c1 + ra.y, 0.f);
                o1.x = fmaxf(c2 + rb.x, 0.f); o1.y = fmaxf(c3 + rb.y, 0.f);
                *(float2*)(fout + (size_t)r0 * 128 + col) = o0;
                *(float2*)(fout + (size_t)(r0 + 8) * 128 + col) = o1;
            } else {
                float2 aa = *(const float2*)(res  + (size_t)r0 * 128 + col);
                float2 xa = *(const float2*)(xres + (size_t)r0 * 128 + col);
                float2 ab = *(const float2*)(res  + (size_t)(r0 + 8) * 128 + col);
                float2 xb = *(const float2*)(xres + (size_t)(r0 + 8) * 128 + col);
                float2 o0, o1;
                o0.x = aa.x / (1.f + __expf(-c0)) + xa.x;
                o0.y = aa.y / (1.f + __expf(-c1)) + xa.y;
                o1.x = ab.x / (1.f + __expf(-c2)) + xb.x;
                o1.y = ab.y / (1.f + __expf(-c3)) + xb.y;
                *(float2*)(fout + (size_t)r0 * 128 + col) = o0;
                *(float2*)(fout + (size_t)(r0 + 8) * 128 + col) = o1;
            }
        }
    }
}

// ---------------------------------------------------------------------------
// FUSED up_i + down_{i+1}, fp16 2-product, DUAL-BRANCH (grid 2*NBLK64)
// ---------------------------------------------------------------------------
#define UD_SB1 144
#define UD_B1 17408
#define UD_SB2 272
#define UD_B2 54272
#define UD_SMEM 89088

__global__ __launch_bounds__(256, 2) void k_updown(
    const __half* t2_a, const __half* W2Ha, const __half* W2La,
    const float* res_a, float* fout_a,
    const __half* V1Ha, const __half* V1La, __half* out16_a,
    const __half* t2_b, const __half* W2Hb, const __half* W2Lb,
    const float* res_b, float* fout_b,
    const __half* V1Hb, const __half* V1Lb, __half* out16_b)
{
    extern __shared__ char sm[];
    const uint32_t su = smem_u32(sm);
    const int tid  = threadIdx.x;
    const int lane = tid & 31;
    const int w    = tid >> 5;
    const int wm   = w & 1;
    const int wn   = w >> 1;
    const int mbase = wm * 32;

    const int bid = blockIdx.x;
    const bool sel = bid >= NBLK64;
    const int p0 = (sel ? bid - NBLK64 : bid) * 64;
    const __half* t2h   = sel ? t2_b    : t2_a;
    const __half* W2Hp  = sel ? W2Hb    : W2Ha;
    const __half* W2Lp  = sel ? W2Lb    : W2La;
    const float*  res   = sel ? res_b   : res_a;
    float*        fout  = sel ? fout_b  : fout_a;
    const __half* V1Hp  = sel ? V1Hb    : V1Ha;
    const __half* V1Lp  = sel ? V1Lb    : V1La;
    __half*       out16 = sel ? out16_b : out16_a;

    // ---- stage phase1 A (t2h fp16, 64 rows x 64) ----
#pragma unroll
    for (int i = 0; i < 2; i++) {
        int j = tid + i * 256;
        int row = j >> 3, ch = j & 7;
        *(uint4*)(sm + row * UD_SB1 + ch * 16) =
            *(const uint4*)(t2h + (size_t)(p0 + row) * 64 + ch * 8);
    }
    // ---- stage B1 (W2 fp16 hi/lo, 128 rows x 64) ----
    {
        int plane = tid >> 7, t = tid & 127;
        const __half* bs = plane ? W2Lp : W2Hp;
        char* bd = sm + UD_B1 + plane * 18432;
#pragma unroll
        for (int i = 0; i < 8; i++) {
            int j = t + i * 128;
            int e = j * 8;
            int r = e >> 6, c = e & 63;
            *(uint4*)(bd + r * UD_SB1 + c * 2) = *(const uint4*)(bs + e);
        }
    }
    // ---- stage B2 (W1 fp16 hi/lo, 64 rows x 128) ----
    {
        int plane = tid >> 7, t = tid & 127;
        const __half* bs = plane ? V1Lp : V1Hp;
        char* bd = sm + UD_B2 + plane * 17408;
#pragma unroll
        for (int i = 0; i < 8; i++) {
            int j = t + i * 128;
            int e = j * 8;
            int r = e >> 7, c = e & 127;
            *(uint4*)(bd + r * UD_SB2 + c * 2) = *(const uint4*)(bs + e);
        }
    }
    __syncthreads();

    // ---- phase 1 MMA: 64x128, K=64 ----
    float acc[2][4][4];
#pragma unroll
    for (int mt = 0; mt < 2; mt++)
#pragma unroll
        for (int nt = 0; nt < 4; nt++)
#pragma unroll
            for (int e = 0; e < 4; e++) acc[mt][nt][e] = 0.f;

    {
        const uint32_t a_ld = su + (uint32_t)(mbase + (lane & 15)) * UD_SB1
                            + (uint32_t)(lane >> 4) * 16;
        const uint32_t b_ld = su + UD_B1 + (uint32_t)(wn * 32 + (lane & 7)) * UD_SB1
                            + (uint32_t)((lane >> 3) & 1) * 16;
#pragma unroll
        for (int ks = 0; ks < 4; ks++) {
            uint32_t a[2][4];
#pragma unroll
            for (int mt = 0; mt < 2; mt++)
                ldsm_x4(a[mt], a_ld + (uint32_t)mt * (16 * UD_SB1) + ks * 32);
#pragma unroll
            for (int nt = 0; nt < 4; nt++) {
                uint32_t bh[2], bl[2];
                ldsm_x2(bh, b_ld + (uint32_t)nt * (8 * UD_SB1) + ks * 32);
                ldsm_x2(bl, b_ld + 18432u + (uint32_t)nt * (8 * UD_SB1) + ks * 32);
#pragma unroll
                for (int mt = 0; mt < 2; mt++) {
                    mma_f16(acc[mt][nt], a[mt], bh[0], bh[1]);
                    mma_f16(acc[mt][nt], a[mt], bl[0], bl[1]);
                }
            }
        }
    }
    __syncthreads();

    // ---- epilogue 1 ----
    const int g = lane >> 2, tg = lane & 3;
#pragma unroll
    for (int mt = 0; mt < 2; mt++) {
        int lr0 = mbase + mt * 16 + g;
        int r0 = p0 + lr0;
#pragma unroll
        for (int nt = 0; nt < 4; nt++) {
            int col = wn * 32 + nt * 8 + tg * 2;
            float2 ra = *(const float2*)(res + (size_t)r0 * 128 + col);
            float2 rb = *(const float2*)(res + (size_t)(r0 + 8) * 128 + col);
            float2 o0, o1;
            o0.x = fmaxf(acc[mt][nt][0] + ra.x, 0.f);
            o0.y = fmaxf(acc[mt][nt][1] + ra.y, 0.f);
            o1.x = fmaxf(acc[mt][nt][2] + rb.x, 0.f);
            o1.y = fmaxf(acc[mt][nt][3] + rb.y, 0.f);
            *(float2*)(fout + (size_t)r0 * 128 + col) = o0;
            *(float2*)(fout + (size_t)(r0 + 8) * 128 + col) = o1;
            *(__half2*)(sm + lr0 * UD_SB2 + col * 2) = __floats2half2_rn(o0.x, o0.y);
            *(__half2*)(sm + (lr0 + 8) * UD_SB2 + col * 2) = __floats2half2_rn(o1.x, o1.y);
        }
    }
    __syncthreads();

    // ---- phase 2 MMA: 64x64, K=128 ----
    float acc2[2][2][4];
#pragma unroll
    for (int mt = 0; mt < 2; mt++)
#pragma unroll
        for (int nt = 0; nt < 2; nt++)
#pragma unroll
            for (int e = 0; e < 4; e++) acc2[mt][nt][e] = 0.f;

    {
        const uint32_t a_ld = su + (uint32_t)(mbase + (lane & 15)) * UD_SB2
                            + (uint32_t)(lane >> 4) * 16;
        const uint32_t b_ld = su + UD_B2 + (uint32_t)(wn * 16 + (lane & 7)) * UD_SB2
                            + (uint32_t)((lane >> 3) & 1) * 16;
#pragma unroll
        for (int ks = 0; ks < 8; ks++) {
            uint32_t a[2][4];
#pragma unroll
            for (int mt = 0; mt < 2; mt++)
                ldsm_x4(a[mt], a_ld + (uint32_t)mt * (16 * UD_SB2) + ks * 32);
#pragma unroll
            for (int nt = 0; nt < 2; nt++) {
                uint32_t bh[2], bl[2];
                ldsm_x2(bh, b_ld + (uint32_t)nt * (8 * UD_SB2) + ks * 32);
                ldsm_x2(bl, b_ld + 17408u + (uint32_t)nt * (8 * UD_SB2) + ks * 32);
#pragma unroll
                for (int mt = 0; mt < 2; mt++) {
                    mma_f16(acc2[mt][nt], a[mt], bh[0], bh[1]);
                    mma_f16(acc2[mt][nt], a[mt], bl[0], bl[1]);
                }
            }
        }
    }

#pragma unroll
    for (int mt = 0; mt < 2; mt++) {
        int r0 = p0 + mbase + mt * 16 + g;
#pragma unroll
        for (int nt = 0; nt < 2; nt++) {
            int col = wn * 16 + nt * 8 + tg * 2;
            __half2 o0 = __floats2half2_rn(fmaxf(acc2[mt][nt][0], 0.f),
                                           fmaxf(acc2[mt][nt][1], 0.f));
            __half2 o1 = __floats2half2_rn(fmaxf(acc2[mt][nt][2], 0.f),
                                           fmaxf(acc2[mt][nt][3], 0.f));
            *(__half2*)(out16 + (size_t)r0 * 64 + col) = o0;
            *(__half2*)(out16 + (size_t)(r0 + 8) * 64 + col) = o1;
        }
    }
}

// ---------------------------------------------------------------------------
// fp16 HMMA conv, DUAL-BRANCH (grid 2*NBLK192):
// blocks [0, NBLK192) use set a; [NBLK192, 2*NBLK192) use set b.
// ---------------------------------------------------------------------------
#define ASTRIDE 144
#define STAGE_SZ 36864
#define SB_B 27648
#define IDX_OFF 73728
#define CONV_SMEM (IDX_OFF + 20736)

__global__ __launch_bounds__(256, 2) void k_conv_mma(
    const __half* T16a, const __half* Wta, __half* outa,
    const __half* T16b, const __half* Wtb, __half* outb,
    const int* __restrict__ nbr)
{
    extern __shared__ char sm[];
    const int tid  = threadIdx.x;
    const int lane = tid & 31;
    const int w    = tid >> 5;
    const int wm   = w & 3;
    const int wn   = w >> 2;

    const int bid = blockIdx.x;
    const bool selb = bid >= NBLK192;
    const int p0 = (selb ? bid - NBLK192 : bid) * 192;
    const __half* T16  = selb ? T16b : T16a;
    const __half* WtH  = selb ? Wtb  : Wta;
    __half*       outh = selb ? outb : outa;

    const uint32_t su = smem_u32(sm);
    int* idxs = (int*)(sm + IDX_OFF);

    for (int i = tid; i < 27 * 192; i += 256) {
        int p = i / 27;
        int k = i - p * 27;
        idxs[k * 192 + p] = nbr[(size_t)(p0 + p) * 27 + k];
    }

    float acc[3][4][4];
#pragma unroll
    for (int mt = 0; mt < 3; mt++)
#pragma unroll
        for (int nt = 0; nt < 4; nt++)
#pragma unroll
            for (int e = 0; e < 4; e++) acc[mt][nt][e] = 0.f;

    const uint32_t a_ld0 = su + (uint32_t)(wm * 48 + (lane & 15)) * ASTRIDE
                         + (uint32_t)(lane >> 4) * 16;
    const uint32_t b_ld0 = su + SB_B + (uint32_t)(wn * 32 + (lane & 15)) * ASTRIDE
                         + (uint32_t)(lane >> 4) * 16;

    __syncthreads();

    auto issue_tap = [&](int k, uint32_t sbase) {
#pragma unroll
        for (int i = 0; i < 6; i++) {
            int j = tid + i * 256;
            int row = j >> 3, ch = j & 7;
            int gr = idxs[k * 192 + row];
            uint32_t dst = sbase + (uint32_t)row * ASTRIDE + (uint32_t)ch * 16;
            const void* src = T16 + ((size_t)(gr < 0 ? 0 : gr) * 64 + ch * 8);
            cp_async16(dst, src, gr < 0 ? 0u : 16u);
        }
#pragma unroll
        for (int i = 0; i < 2; i++) {
            int j = tid + i * 256;
            int row = j >> 3, ch = j & 7;
            uint32_t dst = sbase + (uint32_t)SB_B
                         + (uint32_t)row * ASTRIDE + (uint32_t)ch * 16;
            const __half* src = WtH + ((size_t)k * 64 + row) * 64 + ch * 8;
            cp_async16(dst, src, 16u);
        }
        cp_commit();
    };

    issue_tap(0, su);
    issue_tap(1, su + STAGE_SZ);

    for (int k = 0; k < 27; k++) {
        const uint32_t sb = (uint32_t)(k & 1) * STAGE_SZ;
        if (k < 26) cp_wait<1>(); else cp_wait<0>();
        __syncthreads();

        const uint32_t a_ld = a_ld0 + sb;
        const uint32_t b_ld = b_ld0 + sb;
#pragma unroll
        for (int ks = 0; ks < 4; ks++) {
            uint32_t a[3][4];
#pragma unroll
            for (int mt = 0; mt < 3; mt++)
                ldsm_x4(a[mt], a_ld + (uint32_t)mt * (16 * ASTRIDE) + ks * 32);
#pragma unroll
            for (int nt2 = 0; nt2 < 2; nt2++) {
                uint32_t bh[4];
                ldsm_x4(bh, b_ld + (uint32_t)nt2 * (16 * ASTRIDE) + ks * 32);
#pragma unroll
                for (int mt = 0; mt < 3; mt++) {
                    mma_f16(acc[mt][nt2 * 2 + 0], a[mt], bh[0], bh[2]);
                    mma_f16(acc[mt][nt2 * 2 + 1], a[mt], bh[1], bh[3]);
                }
            }
        }

        if (k < 25) {
            __syncthreads();
            issue_tap(k + 2, su + sb);
        }
    }

    const int g = lane >> 2, tg = lane & 3;
#pragma unroll
    for (int mt = 0; mt < 3; mt++) {
        int row0 = p0 + wm * 48 + mt * 16 + g;
#pragma unroll
        for (int nt = 0; nt < 4; nt++) {
            int col = wn * 32 + nt * 8 + tg * 2;
            __half2 o0 = __floats2half2_rn(fmaxf(acc[mt][nt][0], 0.f),
                                           fmaxf(acc[mt][nt][1], 0.f));
            __half2 o1 = __floats2half2_rn(fmaxf(acc[mt][nt][2], 0.f),
                                           fmaxf(acc[mt][nt][3], 0.f));
            *(__half2*)(outh + (size_t)row0 * 64 + col) = o0;
            *(__half2*)(outh + (size_t)(row0 + 8) * 64 + col) = o1;
        }
    }
}

// ---------------------------------------------------------------------------
extern "C" void kernel_launch(void* const* d_in, const int* in_sizes, int n_in,
                              void* d_out, int out_size)
{
    const float* x   = (const float*)d_in[0];
    const float* W1s = (const float*)d_in[1];
    const float* Wks = (const float*)d_in[2];
    const float* W2s = (const float*)d_in[3];
    const float* Wf  = (const float*)d_in[4];
    const int*   nbr = (const int*)d_in[5];
    float* out = (float*)d_out;

    float *A, *B;
    __half *T2a, *T2b, *T16a, *T16b, *WtH, *V1H, *V1L, *V2H, *V2L, *VfH, *VfL;
    cudaGetSymbolAddress((void**)&A,    g_A);
    cudaGetSymbolAddress((void**)&B,    g_B);
    cudaGetSymbolAddress((void**)&T2a,  g_T2a);
    cudaGetSymbolAddress((void**)&T2b,  g_T2b);
    cudaGetSymbolAddress((void**)&T16a, g_T16a);
    cudaGetSymbolAddress((void**)&T16b, g_T16b);
    cudaGetSymbolAddress((void**)&WtH,  g_WtH);
    cudaGetSymbolAddress((void**)&V1H,  g_V1H);
    cudaGetSymbolAddress((void**)&V1L,  g_V1L);
    cudaGetSymbolAddress((void**)&V2H,  g_V2H);
    cudaGetSymbolAddress((void**)&V2L,  g_V2L);
    cudaGetSymbolAddress((void**)&VfH,  g_VfH);
    cudaGetSymbolAddress((void**)&VfL,  g_VfL);

    constexpr int SM_DOWN  = 64 * 272 + 2 * 64 * 272;    // 52224
    constexpr int SM_UP    = 64 * 144 + 2 * 128 * 144;   // 46080
    constexpr int SM_FINAL = 64 * 272 + 2 * 128 * 272;   // 87040

    cudaFuncSetAttribute(k_conv_mma, cudaFuncAttributeMaxDynamicSharedMemorySize,
                         CONV_SMEM);
    cudaFuncSetAttribute(k_updown, cudaFuncAttributeMaxDynamicSharedMemorySize,
                         UD_SMEM);
    cudaFuncSetAttribute((const void*)k_lin<128, 64, 0>,
                         cudaFuncAttributeMaxDynamicSharedMemorySize, SM_DOWN);
    cudaFuncSetAttribute((const void*)k_lin<64, 128, 1>,
                         cudaFuncAttributeMaxDynamicSharedMemorySize, SM_UP);
    cudaFuncSetAttribute((const void*)k_lin<128, 128, 2>,
                         cudaFuncAttributeMaxDynamicSharedMemorySize, SM_FINAL);

    k_wsplit<<<dim3(27, 6), 256>>>(Wks, WtH);
    k_wsplit_lin<<<13, 256>>>(W1s, W2s, Wf, V1H, V1L, V2H, V2L, VfH, VfL);

    // merged down: unit0 -> T16a, unit3 -> T16b
    k_lin<128, 64, 0><<<2 * NBLK64, 256, SM_DOWN>>>(
        x, nullptr, V1H, V1L, nullptr, nullptr, nullptr, T16a,
        x, nullptr, V1H + (size_t)3 * 8192, V1L + (size_t)3 * 8192,
        nullptr, nullptr, nullptr, T16b);

    // two merged conv+updown steps
    for (int s = 0; s < 2; s++) {
        const float* hinA = (s == 0) ? x : A;
        const float* hinB = (s == 0) ? x : B;
        k_conv_mma<<<2 * NBLK192, 256, CONV_SMEM>>>(
            T16a, WtH + (size_t)s * 27 * 4096, T2a,
            T16b, WtH + (size_t)(s + 3) * 27 * 4096, T2b, nbr);
        k_updown<<<2 * NBLK64, 256, UD_SMEM>>>(
            T2a, V2H + (size_t)s * 8192, V2L + (size_t)s * 8192,
            hinA, A, V1H + (size_t)(s + 1) * 8192, V1L + (size_t)(s + 1) * 8192,
            T16a,
            T2b, V2H + (size_t)(s + 3) * 8192, V2L + (size_t)(s + 3) * 8192,
            hinB, B, V1H + (size_t)(s + 4) * 8192, V1L + (size_t)(s + 4) * 8192,
            T16b);
    }

    // last merged conv (units 2 and 5)
    k_conv_mma<<<2 * NBLK192, 256, CONV_SMEM>>>(
        T16a, WtH + (size_t)2 * 27 * 4096, T2a,
        T16b, WtH + (size_t)5 * 27 * 4096, T2b, nbr);

    // merged up: unit2 -> A, unit5 -> B
    k_lin<64, 128, 1><<<2 * NBLK64, 256, SM_UP>>>(
        nullptr, T2a, V2H + (size_t)2 * 8192, V2L + (size_t)2 * 8192,
        A, nullptr, A, nullptr,
        nullptr, T2b, V2H + (size_t)5 * 8192, V2L + (size_t)5 * 8192,
        B, nullptr, B, nullptr);

    // final (single branch)
    k_lin<128, 128, 2><<<NBLK64, 256, SM_FINAL>>>(
        B, nullptr, VfH, VfL, A, x, out, nullptr,
        B, nullptr, VfH, VfL, A, x, out, nullptr);
}

// round 13
// speedup vs baseline: 4.8039x; 1.0452x over previous
#include <cuda_runtime.h>
#include <cuda_bf16.h>
#include <cuda_fp16.h>
#include <cstdint>

#define NPTS 120000
#define NBLK96 1250   // 120000 / 96 exactly
#define NBLK192 625   // 120000 / 192 exactly

// ---------------- scratch (device globals: allocation-free) ----------------
__device__ float g_A[NPTS * 128];
__device__ float g_B[NPTS * 128];
__device__ __half g_T2a[NPTS * 64];                 // conv output (fp16), branch a
__device__ __half g_T2b[NPTS * 64];                 // branch b
__device__ __half g_T16a[NPTS * 64];                // conv input (fp16), branch a
__device__ __half g_T16b[NPTS * 64];                // branch b
__device__ __half g_WtH[6 * 27 * 64 * 64];          // conv weights [u][k][j][c] fp16
__device__ __half g_V1H[6 * 64 * 128];              // down weights [u][n][k] fp16 hi/lo
__device__ __half g_V1L[6 * 64 * 128];
__device__ __half g_V2H[6 * 128 * 64];              // up weights [u][n][k] fp16 hi/lo
__device__ __half g_V2L[6 * 128 * 64];
__device__ __half g_VfH[128 * 128];                 // final weights [n][k] fp16 hi/lo
__device__ __half g_VfL[128 * 128];

// ---------------- helpers ---------------------------------------------------
__device__ __forceinline__ uint32_t smem_u32(const void* p) {
    uint32_t a;
    asm("{ .reg .u64 t; cvta.to.shared.u64 t, %1; cvt.u32.u64 %0, t; }"
        : "=r"(a) : "l"(p));
    return a;
}
__device__ __forceinline__ void ldsm_x4(uint32_t (&r)[4], uint32_t addr) {
    asm volatile("ldmatrix.sync.aligned.m8n8.x4.shared.b16 {%0,%1,%2,%3}, [%4];"
                 : "=r"(r[0]), "=r"(r[1]), "=r"(r[2]), "=r"(r[3]) : "r"(addr));
}
__device__ __forceinline__ void ldsm_x2(uint32_t (&r)[2], uint32_t addr) {
    asm volatile("ldmatrix.sync.aligned.m8n8.x2.shared.b16 {%0,%1}, [%2];"
                 : "=r"(r[0]), "=r"(r[1]) : "r"(addr));
}
__device__ __forceinline__ void mma_f16(float* c, const uint32_t* a,
                                        uint32_t b0, uint32_t b1) {
    asm volatile(
        "mma.sync.aligned.m16n8k16.row.col.f32.f16.f16.f32 "
        "{%0,%1,%2,%3}, {%4,%5,%6,%7}, {%8,%9}, {%0,%1,%2,%3};"
        : "+f"(c[0]), "+f"(c[1]), "+f"(c[2]), "+f"(c[3])
        : "r"(a[0]), "r"(a[1]), "r"(a[2]), "r"(a[3]), "r"(b0), "r"(b1));
}
__device__ __forceinline__ void cp_async16(uint32_t dst, const void* src,
                                           uint32_t src_size) {
    asm volatile("cp.async.ca.shared.global [%0], [%1], 16, %2;"
                 :: "r"(dst), "l"(src), "r"(src_size) : "memory");
}
__device__ __forceinline__ void cp_commit() {
    asm volatile("cp.async.commit_group;" ::: "memory");
}
template <int N>
__device__ __forceinline__ void cp_wait() {
    asm volatile("cp.async.wait_group %0;" :: "n"(N) : "memory");
}
__device__ __forceinline__ unsigned h2u(__half2 h) {
    return *reinterpret_cast<unsigned*>(&h);
}

// ---------------------------------------------------------------------------
// conv weight transpose: Wt[u][k][j][c] = Wk[u][k][c][j] as single fp16
// ---------------------------------------------------------------------------
__global__ void k_wsplit(const float* __restrict__ Wks,
                         __half* __restrict__ WtH) {
    int k = blockIdx.x, u = blockIdx.y;
    const float* src = Wks + ((size_t)u * 27 + k) * 4096;
    __half* dh = WtH + ((size_t)u * 27 + k) * 4096;
    for (int e = threadIdx.x; e < 4096; e += blockDim.x) {
        int c = e >> 6, j = e & 63;
        dh[j * 64 + c] = __float2half(src[c * 64 + j]);
    }
}

// ---------------------------------------------------------------------------
// linear weight split+transpose: [k][n] fp32 -> [n][k] fp16 hi/lo
// ---------------------------------------------------------------------------
__global__ void k_wsplit_lin(const float* __restrict__ W1s,
                             const float* __restrict__ W2s,
                             const float* __restrict__ Wf,
                             __half* __restrict__ V1H, __half* __restrict__ V1L,
                             __half* __restrict__ V2H, __half* __restrict__ V2L,
                             __half* __restrict__ VfH, __half* __restrict__ VfL) {
    int b = blockIdx.x;
    if (b < 6) {
        const float* s = W1s + (size_t)b * 8192;
        __half* vh = V1H + (size_t)b * 8192;
        __half* vl = V1L + (size_t)b * 8192;
        for (int e = threadIdx.x; e < 8192; e += blockDim.x) {
            int k = e >> 6, n = e & 63;
            float v = s[e];
            __half fh = __float2half(v);
            vh[n * 128 + k] = fh;
            vl[n * 128 + k] = __float2half(v - __half2float(fh));
        }
    } else if (b < 12) {
        const float* s = W2s + (size_t)(b - 6) * 8192;
        __half* vh = V2H + (size_t)(b - 6) * 8192;
        __half* vl = V2L + (size_t)(b - 6) * 8192;
        for (int e = threadIdx.x; e < 8192; e += blockDim.x) {
            int k = e >> 7, n = e & 127;
            float v = s[e];
            __half fh = __float2half(v);
            vh[n * 64 + k] = fh;
            vl[n * 64 + k] = __float2half(v - __half2float(fh));
        }
    } else {
        for (int e = threadIdx.x; e < 16384; e += blockDim.x) {
            int k = e >> 7, n = e & 127;
            float v = Wf[e];
            __half fh = __float2half(v);
            VfH[n * 128 + k] = fh;
            VfL[n * 128 + k] = __float2half(v - __half2float(fh));
        }
    }
}

// ---------------------------------------------------------------------------
// HMMA 1x1 layer, M=96 tiles, fp16 2-product, DUAL-BRANCH:
// blocks [0, NBLK96) use set a; [NBLK96, 2*NBLK96) use set b.
// Warps: 2 M-bands (48 rows = 3 m16 tiles) x 4 N-bands.
// EPI 0: in fp32 -> relu -> fp16 (out16)          [down]
// EPI 1: in16 fp16 -> relu(acc+res) -> fp32       [up]
// EPI 2: in fp32 -> res*sigmoid(acc)+xres -> fp32 [final; grid NBLK96]
// ---------------------------------------------------------------------------
template <int K, int N, int EPI>
__global__ __launch_bounds__(256, 2) void k_lin(
    const float* in_a, const __half* in16_a,
    const __half* BHa, const __half* BLa,
    const float* res_a, const float* xres_a,
    float* fout_a, __half* out16_a,
    const float* in_b, const __half* in16_b,
    const __half* BHb, const __half* BLb,
    const float* res_b, const float* xres_b,
    float* fout_b, __half* out16_b)
{
    constexpr int SB   = K * 2 + 16;
    constexpr int BOFF = 96 * SB;
    constexpr int NTW  = N / 4;
    constexpr int NT   = NTW / 8;
    constexpr int KS   = K / 16;

    extern __shared__ char sm[];
    const uint32_t su = smem_u32(sm);
    const int tid  = threadIdx.x;
    const int lane = tid & 31;
    const int w    = tid >> 5;
    const int wm   = w & 1;
    const int wn   = w >> 1;
    const int mbase = wm * 48;

    const int bid = blockIdx.x;
    const bool sel = bid >= NBLK96;
    const int p0 = (sel ? bid - NBLK96 : bid) * 96;
    const float*  in    = sel ? in_b    : in_a;
    const __half* in16  = sel ? in16_b  : in16_a;
    const __half* BH    = sel ? BHb     : BHa;
    const __half* BL    = sel ? BLb     : BLa;
    const float*  res   = sel ? res_b   : res_a;
    const float*  xres  = sel ? xres_b  : xres_a;
    float*        fout  = sel ? fout_b  : fout_a;
    __half*       out16 = sel ? out16_b : out16_a;

    // ---- stage A ----
    if (EPI == 1) {
        // fp16 input: 96 rows x K halves, 16B chunks
        constexpr int CH = 96 * K / 8;
#pragma unroll
        for (int i = 0; i < CH / 256; i++) {
            int j = tid + i * 256;
            int row = j / (K / 8), ch = j % (K / 8);
            *(uint4*)(sm + row * SB + ch * 16) =
                *(const uint4*)(in16 + (size_t)(p0 + row) * K + ch * 8);
        }
    } else {
        // fp32 input: 96*K floats, 8-float units -> 16B fp16
        constexpr int UNITS = 96 * K / 8;
#pragma unroll
        for (int i = 0; i < UNITS / 256; i++) {
            int j = tid + i * 256;
            int row = j / (K / 8), q = j % (K / 8);
            const float* src = in + (size_t)(p0 + row) * K + q * 8;
            float4 f0 = *(const float4*)(src);
            float4 f1 = *(const float4*)(src + 4);
            *(uint4*)(sm + row * SB + q * 16) = make_uint4(
                h2u(__floats2half2_rn(f0.x, f0.y)),
                h2u(__floats2half2_rn(f0.z, f0.w)),
                h2u(__floats2half2_rn(f1.x, f1.y)),
                h2u(__floats2half2_rn(f1.z, f1.w)));
        }
    }
    // ---- stage B (fp16 hi/lo) ----
    {
        constexpr int ITER = N * K / 1024;
        int plane = tid >> 7, t = tid & 127;
        const __half* bs = plane ? BL : BH;
        char* bd = sm + BOFF + plane * (N * SB);
#pragma unroll
        for (int i = 0; i < ITER; i++) {
            int j = t + i * 128;
            int e = j * 8;
            int r = e / K, c = e % K;
            *(uint4*)(bd + r * SB + c * 2) = *(const uint4*)(bs + e);
        }
    }
    __syncthreads();

    float acc[3][NT][4];
#pragma unroll
    for (int mt = 0; mt < 3; mt++)
#pragma unroll
        for (int nt = 0; nt < NT; nt++)
#pragma unroll
            for (int e = 0; e < 4; e++) acc[mt][nt][e] = 0.f;

    const uint32_t a_ld = su + (uint32_t)(mbase + (lane & 15)) * SB
                        + (uint32_t)(lane >> 4) * 16;
    const uint32_t b_ld = su + BOFF + (uint32_t)(wn * NTW + (lane & 7)) * SB
                        + (uint32_t)((lane >> 3) & 1) * 16;

#pragma unroll
    for (int ks = 0; ks < KS; ks++) {
        uint32_t a[3][4];
#pragma unroll
        for (int mt = 0; mt < 3; mt++)
            ldsm_x4(a[mt], a_ld + (uint32_t)mt * (16 * SB) + ks * 32);
#pragma unroll
        for (int nt = 0; nt < NT; nt++) {
            uint32_t bh[2], bl[2];
            ldsm_x2(bh, b_ld + (uint32_t)nt * (8 * SB) + ks * 32);
            ldsm_x2(bl, b_ld + (uint32_t)(N * SB) + (uint32_t)nt * (8 * SB) + ks * 32);
#pragma unroll
            for (int mt = 0; mt < 3; mt++) {
                mma_f16(acc[mt][nt], a[mt], bh[0], bh[1]);
                mma_f16(acc[mt][nt], a[mt], bl[0], bl[1]);
            }
        }
    }

    const int g = lane >> 2, tg = lane & 3;
#pragma unroll
    for (int mt = 0; mt < 3; mt++) {
        int r0 = p0 + mbase + mt * 16 + g;
#pragma unroll
        for (int nt = 0; nt < NT; nt++) {
            int col = wn * NTW + nt * 8 + tg * 2;
            float c0 = acc[mt][nt][0], c1 = acc[mt][nt][1];
            float c2 = acc[mt][nt][2], c3 = acc[mt][nt][3];
            if (EPI == 0) {
                __half2 o0 = __floats2half2_rn(fmaxf(c0, 0.f), fmaxf(c1, 0.f));
                __half2 o1 = __floats2half2_rn(fmaxf(c2, 0.f), fmaxf(c3, 0.f));
                *(__half2*)(out16 + (size_t)r0 * 64 + col) = o0;
                *(__half2*)(out16 + (size_t)(r0 + 8) * 64 + col) = o1;
            } else if (EPI == 1) {
                float2 ra = *(const float2*)(res + (size_t)r0 * 128 + col);
                float2 rb = *(const float2*)(res + (size_t)(r0 + 8) * 128 + col);
                float2 o0, o1;
                o0.x = fmaxf(c0 + ra.x, 0.f); o0.y = fmaxf(c1 + ra.y, 0.f);
                o1.x = fmaxf(c2 + rb.x, 0.f); o1.y = fmaxf(c3 + rb.y, 0.f);
                *(float2*)(fout + (size_t)r0 * 128 + col) = o0;
                *(float2*)(fout + (size_t)(r0 + 8) * 128 + col) = o1;
            } else {
                float2 aa = *(const float2*)(res  + (size_t)r0 * 128 + col);
                float2 xa = *(const float2*)(xres + (size_t)r0 * 128 + col);
                float2 ab = *(const float2*)(res  + (size_t)(r0 + 8) * 128 + col);
                float2 xb = *(const float2*)(xres + (size_t)(r0 + 8) * 128 + col);
                float2 o0, o1;
                o0.x = aa.x / (1.f + __expf(-c0)) + xa.x;
                o0.y = aa.y / (1.f + __expf(-c1)) + xa.y;
                o1.x = ab.x / (1.f + __expf(-c2)) + xb.x;
                o1.y = ab.y / (1.f + __expf(-c3)) + xb.y;
                *(float2*)(fout + (size_t)r0 * 128 + col) = o0;
                *(float2*)(fout + (size_t)(r0 + 8) * 128 + col) = o1;
            }
        }
    }
}

// ---------------------------------------------------------------------------
// FUSED up_i + down_{i+1}, M=96, fp16 2-product, DUAL-BRANCH (grid 2*NBLK96)
// smem: phase1 A (fp16, 96x144=13824) @0; phase2 A (96x272=26112) @0 (reuse)
//       B1 (W2 hi/lo) @26112, planes of 128*144=18432   [26112,62976)
//       B2 (W1 hi/lo) @62976, planes of 64*272=17408    [62976,97792)
// ---------------------------------------------------------------------------
#define UD_SB1 144
#define UD_B1 26112
#define UD_SB2 272
#define UD_B2 62976
#define UD_SMEM 97792

__global__ __launch_bounds__(256, 2) void k_updown(
    const __half* t2_a, const __half* W2Ha, const __half* W2La,
    const float* res_a, float* fout_a,
    const __half* V1Ha, const __half* V1La, __half* out16_a,
    const __half* t2_b, const __half* W2Hb, const __half* W2Lb,
    const float* res_b, float* fout_b,
    const __half* V1Hb, const __half* V1Lb, __half* out16_b)
{
    extern __shared__ char sm[];
    const uint32_t su = smem_u32(sm);
    const int tid  = threadIdx.x;
    const int lane = tid & 31;
    const int w    = tid >> 5;
    const int wm   = w & 1;
    const int wn   = w >> 1;
    const int mbase = wm * 48;

    const int bid = blockIdx.x;
    const bool sel = bid >= NBLK96;
    const int p0 = (sel ? bid - NBLK96 : bid) * 96;
    const __half* t2h   = sel ? t2_b    : t2_a;
    const __half* W2Hp  = sel ? W2Hb    : W2Ha;
    const __half* W2Lp  = sel ? W2Lb    : W2La;
    const float*  res   = sel ? res_b   : res_a;
    float*        fout  = sel ? fout_b  : fout_a;
    const __half* V1Hp  = sel ? V1Hb    : V1Ha;
    const __half* V1Lp  = sel ? V1Lb    : V1La;
    __half*       out16 = sel ? out16_b : out16_a;

    // ---- stage phase1 A (t2h fp16, 96 rows x 64) ----
#pragma unroll
    for (int i = 0; i < 3; i++) {
        int j = tid + i * 256;
        int row = j >> 3, ch = j & 7;
        *(uint4*)(sm + row * UD_SB1 + ch * 16) =
            *(const uint4*)(t2h + (size_t)(p0 + row) * 64 + ch * 8);
    }
    // ---- stage B1 (W2 fp16 hi/lo, 128 rows x 64) ----
    {
        int plane = tid >> 7, t = tid & 127;
        const __half* bs = plane ? W2Lp : W2Hp;
        char* bd = sm + UD_B1 + plane * 18432;
#pragma unroll
        for (int i = 0; i < 8; i++) {
            int j = t + i * 128;
            int e = j * 8;
            int r = e >> 6, c = e & 63;
            *(uint4*)(bd + r * UD_SB1 + c * 2) = *(const uint4*)(bs + e);
        }
    }
    // ---- stage B2 (W1 fp16 hi/lo, 64 rows x 128) ----
    {
        int plane = tid >> 7, t = tid & 127;
        const __half* bs = plane ? V1Lp : V1Hp;
        char* bd = sm + UD_B2 + plane * 17408;
#pragma unroll
        for (int i = 0; i < 8; i++) {
            int j = t + i * 128;
            int e = j * 8;
            int r = e >> 7, c = e & 127;
            *(uint4*)(bd + r * UD_SB2 + c * 2) = *(const uint4*)(bs + e);
        }
    }
    __syncthreads();

    // ---- phase 1 MMA: 96x128, K=64 ----
    float acc[3][4][4];
#pragma unroll
    for (int mt = 0; mt < 3; mt++)
#pragma unroll
        for (int nt = 0; nt < 4; nt++)
#pragma unroll
            for (int e = 0; e < 4; e++) acc[mt][nt][e] = 0.f;

    {
        const uint32_t a_ld = su + (uint32_t)(mbase + (lane & 15)) * UD_SB1
                            + (uint32_t)(lane >> 4) * 16;
        const uint32_t b_ld = su + UD_B1 + (uint32_t)(wn * 32 + (lane & 7)) * UD_SB1
                            + (uint32_t)((lane >> 3) & 1) * 16;
#pragma unroll
        for (int ks = 0; ks < 4; ks++) {
            uint32_t a[3][4];
#pragma unroll
            for (int mt = 0; mt < 3; mt++)
                ldsm_x4(a[mt], a_ld + (uint32_t)mt * (16 * UD_SB1) + ks * 32);
#pragma unroll
            for (int nt = 0; nt < 4; nt++) {
                uint32_t bh[2], bl[2];
                ldsm_x2(bh, b_ld + (uint32_t)nt * (8 * UD_SB1) + ks * 32);
                ldsm_x2(bl, b_ld + 18432u + (uint32_t)nt * (8 * UD_SB1) + ks * 32);
#pragma unroll
                for (int mt = 0; mt < 3; mt++) {
                    mma_f16(acc[mt][nt], a[mt], bh[0], bh[1]);
                    mma_f16(acc[mt][nt], a[mt], bl[0], bl[1]);
                }
            }
        }
    }
    __syncthreads();   // phase1 A reads done before phase2 A overwrites [0,26112)

    // ---- epilogue 1: h' = relu(acc+res) -> fp32 global + fp16 A2 smem ----
    const int g = lane >> 2, tg = lane & 3;
#pragma unroll
    for (int mt = 0; mt < 3; mt++) {
        int lr0 = mbase + mt * 16 + g;
        int r0 = p0 + lr0;
#pragma unroll
        for (int nt = 0; nt < 4; nt++) {
            int col = wn * 32 + nt * 8 + tg * 2;
            float2 ra = *(const float2*)(res + (size_t)r0 * 128 + col);
            float2 rb = *(const float2*)(res + (size_t)(r0 + 8) * 128 + col);
            float2 o0, o1;
            o0.x = fmaxf(acc[mt][nt][0] + ra.x, 0.f);
            o0.y = fmaxf(acc[mt][nt][1] + ra.y, 0.f);
            o1.x = fmaxf(acc[mt][nt][2] + rb.x, 0.f);
            o1.y = fmaxf(acc[mt][nt][3] + rb.y, 0.f);
            *(float2*)(fout + (size_t)r0 * 128 + col) = o0;
            *(float2*)(fout + (size_t)(r0 + 8) * 128 + col) = o1;
            *(__half2*)(sm + lr0 * UD_SB2 + col * 2) = __floats2half2_rn(o0.x, o0.y);
            *(__half2*)(sm + (lr0 + 8) * UD_SB2 + col * 2) = __floats2half2_rn(o1.x, o1.y);
        }
    }
    __syncthreads();

    // ---- phase 2 MMA: t = relu(h' @ W1^T), 96x64, K=128 ----
    float acc2[3][2][4];
#pragma unroll
    for (int mt = 0; mt < 3; mt++)
#pragma unroll
        for (int nt = 0; nt < 2; nt++)
#pragma unroll
            for (int e = 0; e < 4; e++) acc2[mt][nt][e] = 0.f;

    {
        const uint32_t a_ld = su + (uint32_t)(mbase + (lane & 15)) * UD_SB2
                            + (uint32_t)(lane >> 4) * 16;
        const uint32_t b_ld = su + UD_B2 + (uint32_t)(wn * 16 + (lane & 7)) * UD_SB2
                            + (uint32_t)((lane >> 3) & 1) * 16;
#pragma unroll
        for (int ks = 0; ks < 8; ks++) {
            uint32_t a[3][4];
#pragma unroll
            for (int mt = 0; mt < 3; mt++)
                ldsm_x4(a[mt], a_ld + (uint32_t)mt * (16 * UD_SB2) + ks * 32);
#pragma unroll
            for (int nt = 0; nt < 2; nt++) {
                uint32_t bh[2], bl[2];
                ldsm_x2(bh, b_ld + (uint32_t)nt * (8 * UD_SB2) + ks * 32);
                ldsm_x2(bl, b_ld + 17408u + (uint32_t)nt * (8 * UD_SB2) + ks * 32);
#pragma unroll
                for (int mt = 0; mt < 3; mt++) {
                    mma_f16(acc2[mt][nt], a[mt], bh[0], bh[1]);
                    mma_f16(acc2[mt][nt], a[mt], bl[0], bl[1]);
                }
            }
        }
    }

#pragma unroll
    for (int mt = 0; mt < 3; mt++) {
        int r0 = p0 + mbase + mt * 16 + g;
#pragma unroll
        for (int nt = 0; nt < 2; nt++) {
            int col = wn * 16 + nt * 8 + tg * 2;
            __half2 o0 = __floats2half2_rn(fmaxf(acc2[mt][nt][0], 0.f),
                                           fmaxf(acc2[mt][nt][1], 0.f));
            __half2 o1 = __floats2half2_rn(fmaxf(acc2[mt][nt][2], 0.f),
                                           fmaxf(acc2[mt][nt][3], 0.f));
            *(__half2*)(out16 + (size_t)r0 * 64 + col) = o0;
            *(__half2*)(out16 + (size_t)(r0 + 8) * 64 + col) = o1;
        }
    }
}

// ---------------------------------------------------------------------------
// fp16 HMMA conv, DUAL-BRANCH (grid 2*NBLK192) — unchanged from round 12
// ---------------------------------------------------------------------------
#define ASTRIDE 144
#define STAGE_SZ 36864
#define SB_B 27648
#define IDX_OFF 73728
#define CONV_SMEM (IDX_OFF + 20736)

__global__ __launch_bounds__(256, 2) void k_conv_mma(
    const __half* T16a, const __half* Wta, __half* outa,
    const __half* T16b, const __half* Wtb, __half* outb,
    const int* __restrict__ nbr)
{
    extern __shared__ char sm[];
    const int tid  = threadIdx.x;
    const int lane = tid & 31;
    const int w    = tid >> 5;
    const int wm   = w & 3;
    const int wn   = w >> 2;

    const int bid = blockIdx.x;
    const bool selb = bid >= NBLK192;
    const int p0 = (selb ? bid - NBLK192 : bid) * 192;
    const __half* T16  = selb ? T16b : T16a;
    const __half* WtH  = selb ? Wtb  : Wta;
    __half*       outh = selb ? outb : outa;

    const uint32_t su = smem_u32(sm);
    int* idxs = (int*)(sm + IDX_OFF);

    for (int i = tid; i < 27 * 192; i += 256) {
        int p = i / 27;
        int k = i - p * 27;
        idxs[k * 192 + p] = nbr[(size_t)(p0 + p) * 27 + k];
    }

    float acc[3][4][4];
#pragma unroll
    for (int mt = 0; mt < 3; mt++)
#pragma unroll
        for (int nt = 0; nt < 4; nt++)
#pragma unroll
            for (int e = 0; e < 4; e++) acc[mt][nt][e] = 0.f;

    const uint32_t a_ld0 = su + (uint32_t)(wm * 48 + (lane & 15)) * ASTRIDE
                         + (uint32_t)(lane >> 4) * 16;
    const uint32_t b_ld0 = su + SB_B + (uint32_t)(wn * 32 + (lane & 15)) * ASTRIDE
                         + (uint32_t)(lane >> 4) * 16;

    __syncthreads();

    auto issue_tap = [&](int k, uint32_t sbase) {
#pragma unroll
        for (int i = 0; i < 6; i++) {
            int j = tid + i * 256;
            int row = j >> 3, ch = j & 7;
            int gr = idxs[k * 192 + row];
            uint32_t dst = sbase + (uint32_t)row * ASTRIDE + (uint32_t)ch * 16;
            const void* src = T16 + ((size_t)(gr < 0 ? 0 : gr) * 64 + ch * 8);
            cp_async16(dst, src, gr < 0 ? 0u : 16u);
        }
#pragma unroll
        for (int i = 0; i < 2; i++) {
            int j = tid + i * 256;
            int row = j >> 3, ch = j & 7;
            uint32_t dst = sbase + (uint32_t)SB_B
                         + (uint32_t)row * ASTRIDE + (uint32_t)ch * 16;
            const __half* src = WtH + ((size_t)k * 64 + row) * 64 + ch * 8;
            cp_async16(dst, src, 16u);
        }
        cp_commit();
    };

    issue_tap(0, su);
    issue_tap(1, su + STAGE_SZ);

    for (int k = 0; k < 27; k++) {
        const uint32_t sb = (uint32_t)(k & 1) * STAGE_SZ;
        if (k < 26) cp_wait<1>(); else cp_wait<0>();
        __syncthreads();

        const uint32_t a_ld = a_ld0 + sb;
        const uint32_t b_ld = b_ld0 + sb;
#pragma unroll
        for (int ks = 0; ks < 4; ks++) {
            uint32_t a[3][4];
#pragma unroll
            for (int mt = 0; mt < 3; mt++)
                ldsm_x4(a[mt], a_ld + (uint32_t)mt * (16 * ASTRIDE) + ks * 32);
#pragma unroll
            for (int nt2 = 0; nt2 < 2; nt2++) {
                uint32_t bh[4];
                ldsm_x4(bh, b_ld + (uint32_t)nt2 * (16 * ASTRIDE) + ks * 32);
#pragma unroll
                for (int mt = 0; mt < 3; mt++) {
                    mma_f16(acc[mt][nt2 * 2 + 0], a[mt], bh[0], bh[2]);
                    mma_f16(acc[mt][nt2 * 2 + 1], a[mt], bh[1], bh[3]);
                }
            }
        }

        if (k < 25) {
            __syncthreads();
            issue_tap(k + 2, su + sb);
        }
    }

    const int g = lane >> 2, tg = lane & 3;
#pragma unroll
    for (int mt = 0; mt < 3; mt++) {
        int row0 = p0 + wm * 48 + mt * 16 + g;
#pragma unroll
        for (int nt = 0; nt < 4; nt++) {
            int col = wn * 32 + nt * 8 + tg * 2;
            __half2 o0 = __floats2half2_rn(fmaxf(acc[mt][nt][0], 0.f),
                                           fmaxf(acc[mt][nt][1], 0.f));
            __half2 o1 = __floats2half2_rn(fmaxf(acc[mt][nt][2], 0.f),
                                           fmaxf(acc[mt][nt][3], 0.f));
            *(__half2*)(outh + (size_t)row0 * 64 + col) = o0;
            *(__half2*)(outh + (size_t)(row0 + 8) * 64 + col) = o1;
        }
    }
}

// ---------------------------------------------------------------------------
extern "C" void kernel_launch(void* const* d_in, const int* in_sizes, int n_in,
                              void* d_out, int out_size)
{
    const float* x   = (const float*)d_in[0];
    const float* W1s = (const float*)d_in[1];
    const float* Wks = (const float*)d_in[2];
    const float* W2s = (const float*)d_in[3];
    const float* Wf  = (const float*)d_in[4];
    const int*   nbr = (const int*)d_in[5];
    float* out = (float*)d_out;

    float *A, *B;
    __half *T2a, *T2b, *T16a, *T16b, *WtH, *V1H, *V1L, *V2H, *V2L, *VfH, *VfL;
    cudaGetSymbolAddress((void**)&A,    g_A);
    cudaGetSymbolAddress((void**)&B,    g_B);
    cudaGetSymbolAddress((void**)&T2a,  g_T2a);
    cudaGetSymbolAddress((void**)&T2b,  g_T2b);
    cudaGetSymbolAddress((void**)&T16a, g_T16a);
    cudaGetSymbolAddress((void**)&T16b, g_T16b);
    cudaGetSymbolAddress((void**)&WtH,  g_WtH);
    cudaGetSymbolAddress((void**)&V1H,  g_V1H);
    cudaGetSymbolAddress((void**)&V1L,  g_V1L);
    cudaGetSymbolAddress((void**)&V2H,  g_V2H);
    cudaGetSymbolAddress((void**)&V2L,  g_V2L);
    cudaGetSymbolAddress((void**)&VfH,  g_VfH);
    cudaGetSymbolAddress((void**)&VfL,  g_VfL);

    constexpr int SM_DOWN  = 96 * 272 + 2 * 64 * 272;    // 60928
    constexpr int SM_UP    = 96 * 144 + 2 * 128 * 144;   // 50688
    constexpr int SM_FINAL = 96 * 272 + 2 * 128 * 272;   // 95744

    cudaFuncSetAttribute(k_conv_mma, cudaFuncAttributeMaxDynamicSharedMemorySize,
                         CONV_SMEM);
    cudaFuncSetAttribute(k_updown, cudaFuncAttributeMaxDynamicSharedMemorySize,
                         UD_SMEM);
    cudaFuncSetAttribute((const void*)k_lin<128, 64, 0>,
                         cudaFuncAttributeMaxDynamicSharedMemorySize, SM_DOWN);
    cudaFuncSetAttribute((const void*)k_lin<64, 128, 1>,
                         cudaFuncAttributeMaxDynamicSharedMemorySize, SM_UP);
    cudaFuncSetAttribute((const void*)k_lin<128, 128, 2>,
                         cudaFuncAttributeMaxDynamicSharedMemorySize, SM_FINAL);

    k_wsplit<<<dim3(27, 6), 256>>>(Wks, WtH);
    k_wsplit_lin<<<13, 256>>>(W1s, W2s, Wf, V1H, V1L, V2H, V2L, VfH, VfL);

    // merged down: unit0 -> T16a, unit3 -> T16b
    k_lin<128, 64, 0><<<2 * NBLK96, 256, SM_DOWN>>>(
        x, nullptr, V1H, V1L, nullptr, nullptr, nullptr, T16a,
        x, nullptr, V1H + (size_t)3 * 8192, V1L + (size_t)3 * 8192,
        nullptr, nullptr, nullptr, T16b);

    // two merged conv+updown steps
    for (int s = 0; s < 2; s++) {
        const float* hinA = (s == 0) ? x : A;
        const float* hinB = (s == 0) ? x : B;
        k_conv_mma<<<2 * NBLK192, 256, CONV_SMEM>>>(
            T16a, WtH + (size_t)s * 27 * 4096, T2a,
            T16b, WtH + (size_t)(s + 3) * 27 * 4096, T2b, nbr);
        k_updown<<<2 * NBLK96, 256, UD_SMEM>>>(
            T2a, V2H + (size_t)s * 8192, V2L + (size_t)s * 8192,
            hinA, A, V1H + (size_t)(s + 1) * 8192, V1L + (size_t)(s + 1) * 8192,
            T16a,
            T2b, V2H + (size_t)(s + 3) * 8192, V2L + (size_t)(s + 3) * 8192,
            hinB, B, V1H + (size_t)(s + 4) * 8192, V1L + (size_t)(s + 4) * 8192,
            T16b);
    }

    // last merged conv (units 2 and 5)
    k_conv_mma<<<2 * NBLK192, 256, CONV_SMEM>>>(
        T16a, WtH + (size_t)2 * 27 * 4096, T2a,
        T16b, WtH + (size_t)5 * 27 * 4096, T2b, nbr);

    // merged up: unit2 -> A, unit5 -> B
    k_lin<64, 128, 1><<<2 * NBLK96, 256, SM_UP>>>(
        nullptr, T2a, V2H + (size_t)2 * 8192, V2L + (size_t)2 * 8192,
        A, nullptr, A, nullptr,
        nullptr, T2b, V2H + (size_t)5 * 8192, V2L + (size_t)5 * 8192,
        B, nullptr, B, nullptr);

    // final (single branch)
    k_lin<128, 128, 2><<<NBLK96, 256, SM_FINAL>>>(
        B, nullptr, VfH, VfL, A, x, out, nullptr,
        B, nullptr, VfH, VfL, A, x, out, nullptr);
}